// round 10
// baseline (speedup 1.0000x reference)
#include <cuda_runtime.h>
#include <cuda_bf16.h>
#include <cstdint>

#define BATCH 16384
#define DIM   1024
#define NLAY  6
#define NMC   64
#define HW    16

#define BM 128
#define BN 128
#define BK 32
#define AST 40     // A smem row stride (bf16 elems)
#define WST 136    // W smem row stride (bf16 elems)
#define NST 3      // cp.async ring stages
#define NTCH (DIM / BK)   // 32 K-chunks

#define STG_ELEMS_A (BM * AST)            // per buffer per h/l
#define STG_ELEMS_W (BK * WST)
#define SMEM_BYTES ((2 * NST * STG_ELEMS_A + 2 * NST * STG_ELEMS_W) * 2)  // 113664
// fused-mc epilogue smem layout (fp32 view of same buffer):
#define TSTR 132
#define SWL_OFF (128 * TSTR)
#define SBL_OFF (SWL_OFF + 4 * 256)

// ---------------- static device scratch ----------------
#define SQ ((size_t)1048576)
#define OFF_WEI ((size_t)0)
#define OFF_LAT ((size_t)(6 * 2048 * 1024))
#define OFF_V   (OFF_LAT + 6 * SQ)
#define OFF_O   (OFF_V + 6 * SQ)
#define OFF_FB  (OFF_O + 6 * SQ)
#define OFF_VO  (OFF_FB + 5 * SQ)
#define OFF_W3  (OFF_VO + 6 * SQ)
#define WT_TOT  (OFF_W3 + 6 * SQ)

__device__ __nv_bfloat16 g_w_h[WT_TOT];
__device__ __nv_bfloat16 g_w_l[WT_TOT];
__device__ float g_bei[NLAY * 2 * DIM];   // interleaved [mc][exc16|inh16]
__device__ float g_bvo[NLAY * DIM];
__device__ float g_b3[NLAY * DIM];
__device__ float g_wvo_f[6 * SQ];         // fp32 Wvo (for exact b3)

__device__ __nv_bfloat16 g_actA_h[(size_t)BATCH * DIM];
__device__ __nv_bfloat16 g_actA_l[(size_t)BATCH * DIM];
__device__ __nv_bfloat16 g_actB_h[(size_t)BATCH * DIM];
__device__ __nv_bfloat16 g_actB_l[(size_t)BATCH * DIM];
__device__ __nv_bfloat16 g_mc_h[(size_t)BATCH * DIM];
__device__ __nv_bfloat16 g_mc_l[(size_t)BATCH * DIM];

// ---------------- helpers ----------------
__device__ __forceinline__ uint32_t cvt_bf16x2(float lo_elem, float hi_elem) {
    uint32_t r;
    asm("cvt.rn.bf16x2.f32 %0, %1, %2;" : "=r"(r) : "f"(hi_elem), "f"(lo_elem));
    return r;
}
__device__ __forceinline__ void split2(float a, float b, uint32_t& h, uint32_t& l) {
    h = cvt_bf16x2(a, b);
    float ha = __uint_as_float(h << 16);
    float hb = __uint_as_float(h & 0xffff0000u);
    l = cvt_bf16x2(a - ha, b - hb);
}
__device__ __forceinline__ void cp16(uint32_t dst, const void* src) {
    asm volatile("cp.async.cg.shared.global [%0], [%1], 16;" :: "r"(dst), "l"(src));
}
__device__ __forceinline__ void ldsm4(uint32_t addr, uint32_t& r0, uint32_t& r1,
                                      uint32_t& r2, uint32_t& r3) {
    asm volatile("ldmatrix.sync.aligned.m8n8.x4.shared.b16 {%0,%1,%2,%3}, [%4];"
                 : "=r"(r0), "=r"(r1), "=r"(r2), "=r"(r3) : "r"(addr));
}
__device__ __forceinline__ void ldsm4t(uint32_t addr, uint32_t& r0, uint32_t& r1,
                                       uint32_t& r2, uint32_t& r3) {
    asm volatile("ldmatrix.sync.aligned.m8n8.x4.trans.shared.b16 {%0,%1,%2,%3}, [%4];"
                 : "=r"(r0), "=r"(r1), "=r"(r2), "=r"(r3) : "r"(addr));
}
__device__ __forceinline__ void mma16816(float* c, const uint32_t* a, const uint32_t* b) {
    asm volatile(
        "mma.sync.aligned.m16n8k16.row.col.f32.bf16.bf16.f32 "
        "{%0,%1,%2,%3}, {%4,%5,%6,%7}, {%8,%9}, {%0,%1,%2,%3};"
        : "+f"(c[0]), "+f"(c[1]), "+f"(c[2]), "+f"(c[3])
        : "r"(a[0]), "r"(a[1]), "r"(a[2]), "r"(a[3]), "r"(b[0]), "r"(b[1]));
}

// ---------------- pack kernels ----------------
__global__ void pack_wei(const float* __restrict__ We, const float* __restrict__ Wi) {
    size_t i = (size_t)blockIdx.x * blockDim.x + threadIdx.x;
    const size_t total = (size_t)NLAY * DIM * 2 * DIM;
    if (i >= total) return;
    int l = (int)(i / ((size_t)DIM * 2 * DIM));
    size_t r = i % ((size_t)DIM * 2 * DIM);
    int k = (int)(r / (2 * DIM));
    int n = (int)(r % (2 * DIM));
    int mc = n >> 5, rr = n & 31;
    const float* src;
    int h;
    if (rr < 16) { src = We; h = rr; } else { src = Wi; h = rr - 16; }
    float v = src[(((size_t)l * NMC + mc) * DIM + k) * HW + h];
    __nv_bfloat16 hb = __float2bfloat16(v);
    g_w_h[OFF_WEI + i] = hb;
    g_w_l[OFF_WEI + i] = __float2bfloat16(v - __bfloat162float(hb));
}

__global__ void pack_split(const float* __restrict__ src, __nv_bfloat16* __restrict__ dh,
                           __nv_bfloat16* __restrict__ dl, size_t total) {
    size_t i = ((size_t)blockIdx.x * blockDim.x + threadIdx.x) * 4;
    if (i >= total) return;
    float4 v = *(const float4*)(src + i);
    uint32_t h0, l0, h1, l1;
    split2(v.x, v.y, h0, l0);
    split2(v.z, v.w, h1, l1);
    *(uint2*)(dh + i) = make_uint2(h0, h1);
    *(uint2*)(dl + i) = make_uint2(l0, l1);
}

__global__ void pack_bias_kernel(const float* __restrict__ be, const float* __restrict__ bi) {
    int i = blockIdx.x * blockDim.x + threadIdx.x;
    if (i >= NLAY * 2 * DIM) return;
    int l = i / (2 * DIM);
    int n = i % (2 * DIM);
    int mc = n >> 5, rr = n & 31;
    g_bei[i] = (rr < 16) ? be[l * DIM + mc * HW + rr] : bi[l * DIM + mc * HW + (rr - 16)];
}

__global__ void bvo_kernel(const float* __restrict__ bv, const float* __restrict__ Wo,
                           const float* __restrict__ bo) {
    int l = blockIdx.y;
    int n = blockIdx.x * 256 + threadIdx.x;
    const float* w = Wo + (size_t)l * SQ + n;
    const float* b = bv + l * DIM;
    float s = bo[l * DIM + n];
    for (int k = 0; k < DIM; k++) s += b[k] * w[(size_t)k * DIM];
    g_bvo[l * DIM + n] = s;
}

__global__ void b3_kernel(const float* __restrict__ blat) {
    int l = blockIdx.y;
    int n = blockIdx.x * 256 + threadIdx.x;
    const float* w = g_wvo_f + (size_t)l * SQ + n;
    const float* b = blat + l * DIM;
    float s = g_bvo[l * DIM + n];
    for (int k = 0; k < DIM; k++) s += b[k] * w[(size_t)k * DIM];
    g_b3[l * DIM + n] = s;
}

// ---------------- bf16x3 HMMA GEMM, 3-stage cp.async ring, 2 CTAs/SM ----------------
// EPI 0: bias + hi/lo split out
// EPI 1: fused minicolumn epilogue (wide GEMM): relu, block-diag lat, mc out
// EPI 2: bias + fp32 out + split      EPI 3: bias + fp32 out += + split
// BATCH6: 6 contiguous matrices; l = by>>3 selects W
template <int EPI, bool BATCH6>
__global__ __launch_bounds__(256, 2)
void bgemm(const __nv_bfloat16* __restrict__ Ah, const __nv_bfloat16* __restrict__ Al,
           const __nv_bfloat16* __restrict__ Wh, const __nv_bfloat16* __restrict__ Wl,
           const float* __restrict__ bias,
           __nv_bfloat16* __restrict__ oHi, __nv_bfloat16* __restrict__ oLo,
           float* __restrict__ oF, int N,
           const float* __restrict__ mcW, const float* __restrict__ mcB) {
    extern __shared__ __nv_bfloat16 smem[];
    __nv_bfloat16* sAh = smem;                          // [NST][BM][AST]
    __nv_bfloat16* sAl = sAh + NST * STG_ELEMS_A;
    __nv_bfloat16* sWh = sAl + NST * STG_ELEMS_A;       // [NST][BK][WST]
    __nv_bfloat16* sWl = sWh + NST * STG_ELEMS_W;
    const uint32_t sAh_u = (uint32_t)__cvta_generic_to_shared(sAh);
    const uint32_t sAl_u = (uint32_t)__cvta_generic_to_shared(sAl);
    const uint32_t sWh_u = (uint32_t)__cvta_generic_to_shared(sWh);
    const uint32_t sWl_u = (uint32_t)__cvta_generic_to_shared(sWl);

    const int tid = threadIdx.x;
    const int lane = tid & 31, wid = tid >> 5;
    const int wm = wid >> 2, wn = wid & 3;
    const int bx = blockIdx.x, by = blockIdx.y;

    if (BATCH6) {
        size_t ws = (size_t)(by >> 3) * SQ;
        Wh += ws; Wl += ws;
    }

    const char* pAh = (const char*)Ah + (size_t)by * BM * (DIM * 2);
    const char* pAl = (const char*)Al + (size_t)by * BM * (DIM * 2);
    const char* pWh = (const char*)Wh + (size_t)bx * BN * 2;
    const char* pWl = (const char*)Wl + (size_t)bx * BN * 2;
    const size_t wrow_b = (size_t)N * 2;

    uint32_t sAb[2], sWb[2];
    size_t gA[2], gW[2];
#pragma unroll
    for (int i = 0; i < 2; i++) {
        int idx = i * 256 + tid;
        int ar = idx >> 2, ac = idx & 3;
        gA[i] = (size_t)ar * (DIM * 2) + (size_t)ac * 16;
        sAb[i] = (uint32_t)(ar * AST + ac * 8) * 2;
        int wr = idx >> 4, wc = idx & 15;
        gW[i] = (size_t)wr * wrow_b + (size_t)wc * 16;
        sWb[i] = (uint32_t)(wr * WST + wc * 8) * 2;
    }

    auto load_async = [&](int c) {
        const int buf = c % NST;
        const uint32_t offA = (uint32_t)(buf * STG_ELEMS_A * 2);
        const uint32_t offW = (uint32_t)(buf * STG_ELEMS_W * 2);
        const size_t cbA = (size_t)c * (BK * 2);
        const size_t cbW = (size_t)c * BK * wrow_b;
#pragma unroll
        for (int i = 0; i < 2; i++) {
            cp16(sAh_u + offA + sAb[i], pAh + gA[i] + cbA);
            cp16(sAl_u + offA + sAb[i], pAl + gA[i] + cbA);
            cp16(sWh_u + offW + sWb[i], pWh + gW[i] + cbW);
            cp16(sWl_u + offW + sWb[i], pWl + gW[i] + cbW);
        }
        asm volatile("cp.async.commit_group;" ::: "memory");
    };

    float acc[4][4][4];
#pragma unroll
    for (int mt = 0; mt < 4; mt++)
#pragma unroll
        for (int nt = 0; nt < 4; nt++)
#pragma unroll
            for (int q = 0; q < 4; q++) acc[mt][nt][q] = 0.f;

    load_async(0);
    load_async(1);

    const int lrow = lane & 15;
    const int lcol8 = (lane >> 4) * 8;

    for (int t = 0; t < NTCH; t++) {
        if (t == NTCH - 1) asm volatile("cp.async.wait_group 0;" ::: "memory");
        else               asm volatile("cp.async.wait_group 1;" ::: "memory");
        __syncthreads();
        if (t + 2 < NTCH) load_async(t + 2);   // writes buffer last read at t-1: safe after barrier

        const int buf = t % NST;
        const uint32_t bA = (uint32_t)(buf * STG_ELEMS_A * 2);
        const uint32_t bW = (uint32_t)(buf * STG_ELEMS_W * 2);

#pragma unroll
        for (int ks = 0; ks < 2; ks++) {
            uint32_t ah[4][4], al[4][4], b[4][2];
#pragma unroll
            for (int mt = 0; mt < 4; mt++) {
                uint32_t off = bA + (uint32_t)((wm * 64 + mt * 16 + lrow) * AST +
                                               ks * 16 + lcol8) * 2;
                ldsm4(sAh_u + off, ah[mt][0], ah[mt][1], ah[mt][2], ah[mt][3]);
                ldsm4(sAl_u + off, al[mt][0], al[mt][1], al[mt][2], al[mt][3]);
            }
            // pass 1: W-hi fragments -> terms Ah*Bh and Al*Bh
#pragma unroll
            for (int np = 0; np < 2; np++) {
                uint32_t off = bW + (uint32_t)((ks * 16 + lrow) * WST +
                                               wn * 32 + np * 16 + lcol8) * 2;
                uint32_t r0, r1, r2, r3;
                ldsm4t(sWh_u + off, r0, r1, r2, r3);
                b[np * 2][0] = r0; b[np * 2][1] = r1;
                b[np * 2 + 1][0] = r2; b[np * 2 + 1][1] = r3;
            }
#pragma unroll
            for (int mt = 0; mt < 4; mt++)
#pragma unroll
                for (int nt = 0; nt < 4; nt++) mma16816(acc[mt][nt], ah[mt], b[nt]);
#pragma unroll
            for (int mt = 0; mt < 4; mt++)
#pragma unroll
                for (int nt = 0; nt < 4; nt++) mma16816(acc[mt][nt], al[mt], b[nt]);
            // pass 2: W-lo fragments (reuse b regs) -> term Ah*Bl
#pragma unroll
            for (int np = 0; np < 2; np++) {
                uint32_t off = bW + (uint32_t)((ks * 16 + lrow) * WST +
                                               wn * 32 + np * 16 + lcol8) * 2;
                uint32_t r0, r1, r2, r3;
                ldsm4t(sWl_u + off, r0, r1, r2, r3);
                b[np * 2][0] = r0; b[np * 2][1] = r1;
                b[np * 2 + 1][0] = r2; b[np * 2 + 1][1] = r3;
            }
#pragma unroll
            for (int mt = 0; mt < 4; mt++)
#pragma unroll
                for (int nt = 0; nt < 4; nt++) mma16816(acc[mt][nt], ah[mt], b[nt]);
        }
    }
    __syncthreads();   // protect smem before epilogue EPI==1 reuse

    // ---------------- epilogue ----------------
    const int g = lane >> 2;
    const int tg = lane & 3;

    if (EPI == 1) {
        float* tileF = (float*)smem;
#pragma unroll
        for (int mt = 0; mt < 4; mt++) {
            const int rl = wm * 64 + mt * 16 + g;
#pragma unroll
            for (int nt = 0; nt < 4; nt++) {
                const int cl = wn * 32 + nt * 8 + tg * 2;
                float2 bv = *(const float2*)(bias + bx * BN + cl);
                tileF[rl * TSTR + cl]           = fmaxf(acc[mt][nt][0] + bv.x, 0.f);
                tileF[rl * TSTR + cl + 1]       = fmaxf(acc[mt][nt][1] + bv.y, 0.f);
                tileF[(rl + 8) * TSTR + cl]     = fmaxf(acc[mt][nt][2] + bv.x, 0.f);
                tileF[(rl + 8) * TSTR + cl + 1] = fmaxf(acc[mt][nt][3] + bv.y, 0.f);
            }
        }
        float* sWlF = tileF + SWL_OFF;
        float* sblF = tileF + SBL_OFF;
#pragma unroll
        for (int i = 0; i < 4; i++) sWlF[i * 256 + tid] = mcW[(size_t)(bx * 4) * 256 + i * 256 + tid];
        if (tid < 64) sblF[tid] = mcB[bx * 64 + tid];
        __syncthreads();

#pragma unroll
        for (int it = 0; it < 2; it++) {
            int w = it * 256 + tid;
            int j = w & 3, row = w >> 2;
            const float* tr = tileF + row * TSTR + j * 32;
            float inh[16];
#pragma unroll
            for (int h = 0; h < 16; h++) inh[h] = tr[16 + h];
            float o[16];
#pragma unroll
            for (int k = 0; k < 16; k++) {
                float lat = sblF[j * 16 + k];
#pragma unroll
                for (int h = 0; h < 16; h++) lat += inh[h] * sWlF[j * 256 + h * 16 + k];
                o[k] = fmaxf(tr[k] - lat, 0.f);
            }
            uint32_t hu[8], lu[8];
#pragma unroll
            for (int p = 0; p < 8; p++) split2(o[2 * p], o[2 * p + 1], hu[p], lu[p]);
            size_t oo = (size_t)(by * 128 + row) * DIM + (bx * 4 + j) * 16;
            *(uint4*)(oHi + oo)     = make_uint4(hu[0], hu[1], hu[2], hu[3]);
            *(uint4*)(oHi + oo + 8) = make_uint4(hu[4], hu[5], hu[6], hu[7]);
            *(uint4*)(oLo + oo)     = make_uint4(lu[0], lu[1], lu[2], lu[3]);
            *(uint4*)(oLo + oo + 8) = make_uint4(lu[4], lu[5], lu[6], lu[7]);
        }
        return;
    }

#pragma unroll
    for (int mt = 0; mt < 4; mt++) {
        const int r0 = by * BM + wm * 64 + mt * 16 + g;
#pragma unroll
        for (int nt = 0; nt < 4; nt++) {
            const int col = bx * BN + wn * 32 + nt * 8 + tg * 2;
            float2 bv = bias ? *(const float2*)(bias + col) : make_float2(0.f, 0.f);
            float2 v0, v1;
            v0.x = acc[mt][nt][0] + bv.x;  v0.y = acc[mt][nt][1] + bv.y;
            v1.x = acc[mt][nt][2] + bv.x;  v1.y = acc[mt][nt][3] + bv.y;
            if (EPI >= 2) {
                float* p0 = oF + (size_t)r0 * N + col;
                float* p1 = oF + (size_t)(r0 + 8) * N + col;
                if (EPI == 3) {
                    float2 o0 = *(const float2*)p0;
                    float2 o1 = *(const float2*)p1;
                    v0.x += o0.x; v0.y += o0.y; v1.x += o1.x; v1.y += o1.y;
                }
                *(float2*)p0 = v0;
                *(float2*)p1 = v1;
            }
            uint32_t h0, l0, h1, l1;
            split2(v0.x, v0.y, h0, l0);
            split2(v1.x, v1.y, h1, l1);
            *(uint32_t*)(oHi + (size_t)r0 * N + col)       = h0;
            *(uint32_t*)(oLo + (size_t)r0 * N + col)       = l0;
            *(uint32_t*)(oHi + (size_t)(r0 + 8) * N + col) = h1;
            *(uint32_t*)(oLo + (size_t)(r0 + 8) * N + col) = l1;
        }
    }
}

// ---------------- driver ----------------
extern "C" void kernel_launch(void* const* d_in, const int* in_sizes, int n_in,
                              void* d_out, int out_size) {
    const float* x    = (const float*)d_in[0];
    const float* We   = (const float*)d_in[1];
    const float* be   = (const float*)d_in[2];
    const float* Wi   = (const float*)d_in[3];
    const float* bi   = (const float*)d_in[4];
    const float* Wl   = (const float*)d_in[5];
    const float* bl   = (const float*)d_in[6];
    const float* Wlat = (const float*)d_in[7];
    const float* blat = (const float*)d_in[8];
    const float* Wv   = (const float*)d_in[9];
    const float* bv   = (const float*)d_in[10];
    const float* Wo   = (const float*)d_in[11];
    const float* bo   = (const float*)d_in[12];
    const float* fbW  = (const float*)d_in[13];
    const float* fbb  = (const float*)d_in[14];
    float* out = (float*)d_out;

    const size_t BD = (size_t)BATCH * DIM;

    __nv_bfloat16 *w_h, *w_l, *actA_h, *actA_l, *actB_h, *actB_l, *mc_h, *mc_l;
    float *bei_p, *b3_p, *wvo_f;
    cudaGetSymbolAddress((void**)&w_h, g_w_h);
    cudaGetSymbolAddress((void**)&w_l, g_w_l);
    cudaGetSymbolAddress((void**)&actA_h, g_actA_h);
    cudaGetSymbolAddress((void**)&actA_l, g_actA_l);
    cudaGetSymbolAddress((void**)&actB_h, g_actB_h);
    cudaGetSymbolAddress((void**)&actB_l, g_actB_l);
    cudaGetSymbolAddress((void**)&mc_h, g_mc_h);
    cudaGetSymbolAddress((void**)&mc_l, g_mc_l);
    cudaGetSymbolAddress((void**)&bei_p, g_bei);
    cudaGetSymbolAddress((void**)&b3_p, g_b3);
    cudaGetSymbolAddress((void**)&wvo_f, g_wvo_f);

    cudaFuncSetAttribute((const void*)bgemm<0, false>, cudaFuncAttributeMaxDynamicSharedMemorySize, SMEM_BYTES);
    cudaFuncSetAttribute((const void*)bgemm<0, true>,  cudaFuncAttributeMaxDynamicSharedMemorySize, SMEM_BYTES);
    cudaFuncSetAttribute((const void*)bgemm<2, true>,  cudaFuncAttributeMaxDynamicSharedMemorySize, SMEM_BYTES);
    cudaFuncSetAttribute((const void*)bgemm<1, false>, cudaFuncAttributeMaxDynamicSharedMemorySize, SMEM_BYTES);
    cudaFuncSetAttribute((const void*)bgemm<2, false>, cudaFuncAttributeMaxDynamicSharedMemorySize, SMEM_BYTES);
    cudaFuncSetAttribute((const void*)bgemm<3, false>, cudaFuncAttributeMaxDynamicSharedMemorySize, SMEM_BYTES);

    // ---- packs + weight-side precompute ----
    {
        size_t tw = (size_t)NLAY * DIM * 2 * DIM;
        pack_wei<<<(unsigned)((tw + 255) / 256), 256>>>(We, Wi);
        pack_split<<<(unsigned)(6 * SQ / 4 / 256), 256>>>(Wlat, w_h + OFF_LAT, w_l + OFF_LAT, 6 * SQ);
        pack_split<<<(unsigned)(6 * SQ / 4 / 256), 256>>>(Wv,   w_h + OFF_V,   w_l + OFF_V,   6 * SQ);
        pack_split<<<(unsigned)(6 * SQ / 4 / 256), 256>>>(Wo,   w_h + OFF_O,   w_l + OFF_O,   6 * SQ);
        pack_split<<<(unsigned)(5 * SQ / 4 / 256), 256>>>(fbW,  w_h + OFF_FB,  w_l + OFF_FB,  5 * SQ);
        pack_split<<<(unsigned)(BD / 4 / 256), 256>>>(x, actA_h, actA_l, BD);
        pack_bias_kernel<<<(NLAY * 2 * DIM + 255) / 256, 256>>>(be, bi);
        bvo_kernel<<<dim3(4, NLAY), 256>>>(bv, Wo, bo);
        bgemm<2, true><<<dim3(8, 48), 256, SMEM_BYTES>>>(
            w_h + OFF_V, w_l + OFF_V, w_h + OFF_O, w_l + OFF_O, nullptr,
            w_h + OFF_VO, w_l + OFF_VO, wvo_f, 1024, nullptr, nullptr);
        bgemm<0, true><<<dim3(8, 48), 256, SMEM_BYTES>>>(
            w_h + OFF_LAT, w_l + OFF_LAT, w_h + OFF_VO, w_l + OFF_VO, nullptr,
            w_h + OFF_W3, w_l + OFF_W3, nullptr, 1024, nullptr, nullptr);
        b3_kernel<<<dim3(4, NLAY), 256>>>(blat);
    }

    dim3 blk(256);
    dim3 grid_wide(2 * DIM / BN, BATCH / BM);
    dim3 grid_sq(DIM / BN, BATCH / BM);

    for (int l = 0; l < NLAY; l++) {
        const size_t weOff = OFF_WEI + (size_t)l * 2048 * 1024;
        bgemm<1, false><<<grid_wide, blk, SMEM_BYTES>>>(
            actA_h, actA_l, w_h + weOff, w_l + weOff, bei_p + l * 2048,
            mc_h, mc_l, nullptr, 2048,
            Wl + (size_t)l * NMC * HW * HW, bl + (size_t)l * NMC * HW);
        bgemm<2, false><<<grid_sq, blk, SMEM_BYTES>>>(
            mc_h, mc_l, w_h + OFF_W3 + (size_t)l * SQ, w_l + OFF_W3 + (size_t)l * SQ,
            b3_p + l * DIM, actA_h, actA_l, out + (size_t)l * BD, 1024, nullptr, nullptr);
    }

    __nv_bfloat16 *fin_h = actA_h, *fin_l = actA_l, *fout_h = actB_h, *fout_l = actB_l;
    for (int i = 0; i < NLAY - 1; i++) {
        int idx = NLAY - 2 - i;
        bgemm<3, false><<<grid_sq, blk, SMEM_BYTES>>>(
            fin_h, fin_l, w_h + OFF_FB + (size_t)i * SQ, w_l + OFF_FB + (size_t)i * SQ,
            fbb + (size_t)i * DIM, fout_h, fout_l, out + (size_t)idx * BD, 1024,
            nullptr, nullptr);
        __nv_bfloat16* t;
        t = fin_h; fin_h = fout_h; fout_h = t;
        t = fin_l; fin_l = fout_l; fout_l = t;
    }
}

// round 11
// speedup vs baseline: 1.0137x; 1.0137x over previous
#include <cuda_runtime.h>
#include <cuda_bf16.h>
#include <cstdint>

#define BATCH 16384
#define DIM   1024
#define NLAY  6
#define NMC   64
#define HW    16

#define BM 128
#define BN 128
#define BK 32
#define AST 40     // A smem row stride (bf16 elems)
#define WST 136    // W smem row stride (bf16 elems)
#define NST 2      // cp.async double buffer
#define NTCH (DIM / BK)   // 32 K-chunks

#define STG_ELEMS_A (BM * AST)
#define STG_ELEMS_W (BK * WST)
#define SMEM_BYTES ((2 * NST * STG_ELEMS_A + 2 * NST * STG_ELEMS_W) * 2)  // 75776
// fused-mc epilogue smem layout (fp32 view of same buffer):
#define TSTR 132
#define SWL_OFF (128 * TSTR)
#define SBL_OFF (SWL_OFF + 4 * 256)

// ---------------- static device scratch ----------------
#define SQ ((size_t)1048576)
#define OFF_WEI ((size_t)0)
#define OFF_LAT ((size_t)(6 * 2048 * 1024))
#define OFF_V   (OFF_LAT + 6 * SQ)
#define OFF_O   (OFF_V + 6 * SQ)
#define OFF_FB  (OFF_O + 6 * SQ)
#define OFF_VO  (OFF_FB + 5 * SQ)
#define OFF_W3  (OFF_VO + 6 * SQ)
#define WT_TOT  (OFF_W3 + 6 * SQ)

__device__ __nv_bfloat16 g_w_h[WT_TOT];
__device__ __nv_bfloat16 g_w_l[WT_TOT];
__device__ float g_bei[NLAY * 2 * DIM];   // interleaved [mc][exc16|inh16]
__device__ float g_bvo[NLAY * DIM];
__device__ float g_b3[NLAY * DIM];
__device__ float g_wvo_f[6 * SQ];         // fp32 Wvo (for exact b3)

__device__ __nv_bfloat16 g_actA_h[(size_t)BATCH * DIM];
__device__ __nv_bfloat16 g_actA_l[(size_t)BATCH * DIM];
__device__ __nv_bfloat16 g_actB_h[(size_t)BATCH * DIM];
__device__ __nv_bfloat16 g_actB_l[(size_t)BATCH * DIM];
__device__ __nv_bfloat16 g_mc_h[(size_t)BATCH * DIM];
__device__ __nv_bfloat16 g_mc_l[(size_t)BATCH * DIM];

// ---------------- helpers ----------------
__device__ __forceinline__ uint32_t cvt_bf16x2(float lo_elem, float hi_elem) {
    uint32_t r;
    asm("cvt.rn.bf16x2.f32 %0, %1, %2;" : "=r"(r) : "f"(hi_elem), "f"(lo_elem));
    return r;
}
__device__ __forceinline__ void split2(float a, float b, uint32_t& h, uint32_t& l) {
    h = cvt_bf16x2(a, b);
    float ha = __uint_as_float(h << 16);
    float hb = __uint_as_float(h & 0xffff0000u);
    l = cvt_bf16x2(a - ha, b - hb);
}
__device__ __forceinline__ void cp16(uint32_t dst, const void* src) {
    asm volatile("cp.async.cg.shared.global [%0], [%1], 16;" :: "r"(dst), "l"(src));
}
__device__ __forceinline__ void ldsm4(uint32_t addr, uint32_t& r0, uint32_t& r1,
                                      uint32_t& r2, uint32_t& r3) {
    asm volatile("ldmatrix.sync.aligned.m8n8.x4.shared.b16 {%0,%1,%2,%3}, [%4];"
                 : "=r"(r0), "=r"(r1), "=r"(r2), "=r"(r3) : "r"(addr));
}
__device__ __forceinline__ void ldsm4t(uint32_t addr, uint32_t& r0, uint32_t& r1,
                                       uint32_t& r2, uint32_t& r3) {
    asm volatile("ldmatrix.sync.aligned.m8n8.x4.trans.shared.b16 {%0,%1,%2,%3}, [%4];"
                 : "=r"(r0), "=r"(r1), "=r"(r2), "=r"(r3) : "r"(addr));
}
__device__ __forceinline__ void mma16816(float* c, const uint32_t* a, const uint32_t* b) {
    asm volatile(
        "mma.sync.aligned.m16n8k16.row.col.f32.bf16.bf16.f32 "
        "{%0,%1,%2,%3}, {%4,%5,%6,%7}, {%8,%9}, {%0,%1,%2,%3};"
        : "+f"(c[0]), "+f"(c[1]), "+f"(c[2]), "+f"(c[3])
        : "r"(a[0]), "r"(a[1]), "r"(a[2]), "r"(a[3]), "r"(b[0]), "r"(b[1]));
}

// ---------------- pack kernels ----------------
__global__ void pack_wei(const float* __restrict__ We, const float* __restrict__ Wi) {
    size_t i = (size_t)blockIdx.x * blockDim.x + threadIdx.x;
    const size_t total = (size_t)NLAY * DIM * 2 * DIM;
    if (i >= total) return;
    int l = (int)(i / ((size_t)DIM * 2 * DIM));
    size_t r = i % ((size_t)DIM * 2 * DIM);
    int k = (int)(r / (2 * DIM));
    int n = (int)(r % (2 * DIM));
    int mc = n >> 5, rr = n & 31;
    const float* src;
    int h;
    if (rr < 16) { src = We; h = rr; } else { src = Wi; h = rr - 16; }
    float v = src[(((size_t)l * NMC + mc) * DIM + k) * HW + h];
    __nv_bfloat16 hb = __float2bfloat16(v);
    g_w_h[OFF_WEI + i] = hb;
    g_w_l[OFF_WEI + i] = __float2bfloat16(v - __bfloat162float(hb));
}

__global__ void pack_split(const float* __restrict__ src, __nv_bfloat16* __restrict__ dh,
                           __nv_bfloat16* __restrict__ dl, size_t total) {
    size_t i = ((size_t)blockIdx.x * blockDim.x + threadIdx.x) * 4;
    if (i >= total) return;
    float4 v = *(const float4*)(src + i);
    uint32_t h0, l0, h1, l1;
    split2(v.x, v.y, h0, l0);
    split2(v.z, v.w, h1, l1);
    *(uint2*)(dh + i) = make_uint2(h0, h1);
    *(uint2*)(dl + i) = make_uint2(l0, l1);
}

__global__ void pack_bias_kernel(const float* __restrict__ be, const float* __restrict__ bi) {
    int i = blockIdx.x * blockDim.x + threadIdx.x;
    if (i >= NLAY * 2 * DIM) return;
    int l = i / (2 * DIM);
    int n = i % (2 * DIM);
    int mc = n >> 5, rr = n & 31;
    g_bei[i] = (rr < 16) ? be[l * DIM + mc * HW + rr] : bi[l * DIM + mc * HW + (rr - 16)];
}

__global__ void bvo_kernel(const float* __restrict__ bv, const float* __restrict__ Wo,
                           const float* __restrict__ bo) {
    int l = blockIdx.y;
    int n = blockIdx.x * 256 + threadIdx.x;
    const float* w = Wo + (size_t)l * SQ + n;
    const float* b = bv + l * DIM;
    float s = bo[l * DIM + n];
    for (int k = 0; k < DIM; k++) s += b[k] * w[(size_t)k * DIM];
    g_bvo[l * DIM + n] = s;
}

__global__ void b3_kernel(const float* __restrict__ blat) {
    int l = blockIdx.y;
    int n = blockIdx.x * 256 + threadIdx.x;
    const float* w = g_wvo_f + (size_t)l * SQ + n;
    const float* b = blat + l * DIM;
    float s = g_bvo[l * DIM + n];
    for (int k = 0; k < DIM; k++) s += b[k] * w[(size_t)k * DIM];
    g_b3[l * DIM + n] = s;
}

// ---------------- bf16x3 HMMA GEMM, 2-stage cp.async, 2 CTAs/SM, 1 barrier/chunk ----------------
// EPI 0: bias + hi/lo split out
// EPI 1: fused minicolumn epilogue (wide GEMM): relu, block-diag lat, mc out
// EPI 2: bias + fp32 out + split      EPI 3: bias + fp32 out += + split
// BATCH6: 6 contiguous matrices; l = by>>3 selects W
template <int EPI, bool BATCH6>
__global__ __launch_bounds__(256, 2)
void bgemm(const __nv_bfloat16* __restrict__ Ah, const __nv_bfloat16* __restrict__ Al,
           const __nv_bfloat16* __restrict__ Wh, const __nv_bfloat16* __restrict__ Wl,
           const float* __restrict__ bias,
           __nv_bfloat16* __restrict__ oHi, __nv_bfloat16* __restrict__ oLo,
           float* __restrict__ oF, int N,
           const float* __restrict__ mcW, const float* __restrict__ mcB) {
    extern __shared__ __nv_bfloat16 smem[];
    __nv_bfloat16* sAh = smem;                          // [NST][BM][AST]
    __nv_bfloat16* sAl = sAh + NST * STG_ELEMS_A;
    __nv_bfloat16* sWh = sAl + NST * STG_ELEMS_A;       // [NST][BK][WST]
    __nv_bfloat16* sWl = sWh + NST * STG_ELEMS_W;
    const uint32_t sAh_u = (uint32_t)__cvta_generic_to_shared(sAh);
    const uint32_t sAl_u = (uint32_t)__cvta_generic_to_shared(sAl);
    const uint32_t sWh_u = (uint32_t)__cvta_generic_to_shared(sWh);
    const uint32_t sWl_u = (uint32_t)__cvta_generic_to_shared(sWl);

    const int tid = threadIdx.x;
    const int lane = tid & 31, wid = tid >> 5;
    const int wm = wid >> 2, wn = wid & 3;
    const int bx = blockIdx.x, by = blockIdx.y;

    if (BATCH6) {
        size_t ws = (size_t)(by >> 3) * SQ;
        Wh += ws; Wl += ws;
    }

    const char* pAh = (const char*)Ah + (size_t)by * BM * (DIM * 2);
    const char* pAl = (const char*)Al + (size_t)by * BM * (DIM * 2);
    const char* pWh = (const char*)Wh + (size_t)bx * BN * 2;
    const char* pWl = (const char*)Wl + (size_t)bx * BN * 2;
    const size_t wrow_b = (size_t)N * 2;

    uint32_t sAb[2], sWb[2];
    size_t gA[2], gW[2];
#pragma unroll
    for (int i = 0; i < 2; i++) {
        int idx = i * 256 + tid;
        int ar = idx >> 2, ac = idx & 3;
        gA[i] = (size_t)ar * (DIM * 2) + (size_t)ac * 16;
        sAb[i] = (uint32_t)(ar * AST + ac * 8) * 2;
        int wr = idx >> 4, wc = idx & 15;
        gW[i] = (size_t)wr * wrow_b + (size_t)wc * 16;
        sWb[i] = (uint32_t)(wr * WST + wc * 8) * 2;
    }

    auto load_async = [&](int c) {
        const int buf = c & 1;
        const uint32_t offA = (uint32_t)(buf * STG_ELEMS_A * 2);
        const uint32_t offW = (uint32_t)(buf * STG_ELEMS_W * 2);
        const size_t cbA = (size_t)c * (BK * 2);
        const size_t cbW = (size_t)c * BK * wrow_b;
#pragma unroll
        for (int i = 0; i < 2; i++) {
            cp16(sAh_u + offA + sAb[i], pAh + gA[i] + cbA);
            cp16(sAl_u + offA + sAb[i], pAl + gA[i] + cbA);
            cp16(sWh_u + offW + sWb[i], pWh + gW[i] + cbW);
            cp16(sWl_u + offW + sWb[i], pWl + gW[i] + cbW);
        }
        asm volatile("cp.async.commit_group;" ::: "memory");
    };

    float acc[4][4][4];
#pragma unroll
    for (int mt = 0; mt < 4; mt++)
#pragma unroll
        for (int nt = 0; nt < 4; nt++)
#pragma unroll
            for (int q = 0; q < 4; q++) acc[mt][nt][q] = 0.f;

    load_async(0);

    const int lrow = lane & 15;
    const int lcol8 = (lane >> 4) * 8;

    for (int t = 0; t < NTCH; t++) {
        asm volatile("cp.async.wait_group 0;" ::: "memory");
        __syncthreads();
        // Safe without a trailing barrier: this load writes buffer (t+1)&1, last READ
        // at iter t-1; all warps finished those reads before passing the barrier above.
        if (t + 1 < NTCH) load_async(t + 1);

        const int buf = t & 1;
        const uint32_t bA = (uint32_t)(buf * STG_ELEMS_A * 2);
        const uint32_t bW = (uint32_t)(buf * STG_ELEMS_W * 2);

#pragma unroll
        for (int ks = 0; ks < 2; ks++) {
            uint32_t ah[4][4], al[4][4], b[4][2];
#pragma unroll
            for (int mt = 0; mt < 4; mt++) {
                uint32_t off = bA + (uint32_t)((wm * 64 + mt * 16 + lrow) * AST +
                                               ks * 16 + lcol8) * 2;
                ldsm4(sAh_u + off, ah[mt][0], ah[mt][1], ah[mt][2], ah[mt][3]);
                ldsm4(sAl_u + off, al[mt][0], al[mt][1], al[mt][2], al[mt][3]);
            }
            // pass 1: W-hi fragments -> terms Ah*Bh and Al*Bh
#pragma unroll
            for (int np = 0; np < 2; np++) {
                uint32_t off = bW + (uint32_t)((ks * 16 + lrow) * WST +
                                               wn * 32 + np * 16 + lcol8) * 2;
                uint32_t r0, r1, r2, r3;
                ldsm4t(sWh_u + off, r0, r1, r2, r3);
                b[np * 2][0] = r0; b[np * 2][1] = r1;
                b[np * 2 + 1][0] = r2; b[np * 2 + 1][1] = r3;
            }
#pragma unroll
            for (int mt = 0; mt < 4; mt++)
#pragma unroll
                for (int nt = 0; nt < 4; nt++) mma16816(acc[mt][nt], ah[mt], b[nt]);
#pragma unroll
            for (int mt = 0; mt < 4; mt++)
#pragma unroll
                for (int nt = 0; nt < 4; nt++) mma16816(acc[mt][nt], al[mt], b[nt]);
            // pass 2: W-lo fragments (reuse b regs) -> term Ah*Bl
#pragma unroll
            for (int np = 0; np < 2; np++) {
                uint32_t off = bW + (uint32_t)((ks * 16 + lrow) * WST +
                                               wn * 32 + np * 16 + lcol8) * 2;
                uint32_t r0, r1, r2, r3;
                ldsm4t(sWl_u + off, r0, r1, r2, r3);
                b[np * 2][0] = r0; b[np * 2][1] = r1;
                b[np * 2 + 1][0] = r2; b[np * 2 + 1][1] = r3;
            }
#pragma unroll
            for (int mt = 0; mt < 4; mt++)
#pragma unroll
                for (int nt = 0; nt < 4; nt++) mma16816(acc[mt][nt], ah[mt], b[nt]);
        }
    }
    __syncthreads();   // protect smem before EPI==1 epilogue reuse

    // ---------------- epilogue ----------------
    const int g = lane >> 2;
    const int tg = lane & 3;

    if (EPI == 1) {
        float* tileF = (float*)smem;
#pragma unroll
        for (int mt = 0; mt < 4; mt++) {
            const int rl = wm * 64 + mt * 16 + g;
#pragma unroll
            for (int nt = 0; nt < 4; nt++) {
                const int cl = wn * 32 + nt * 8 + tg * 2;
                float2 bv = *(const float2*)(bias + bx * BN + cl);
                tileF[rl * TSTR + cl]           = fmaxf(acc[mt][nt][0] + bv.x, 0.f);
                tileF[rl * TSTR + cl + 1]       = fmaxf(acc[mt][nt][1] + bv.y, 0.f);
                tileF[(rl + 8) * TSTR + cl]     = fmaxf(acc[mt][nt][2] + bv.x, 0.f);
                tileF[(rl + 8) * TSTR + cl + 1] = fmaxf(acc[mt][nt][3] + bv.y, 0.f);
            }
        }
        float* sWlF = tileF + SWL_OFF;
        float* sblF = tileF + SBL_OFF;
#pragma unroll
        for (int i = 0; i < 4; i++) sWlF[i * 256 + tid] = mcW[(size_t)(bx * 4) * 256 + i * 256 + tid];
        if (tid < 64) sblF[tid] = mcB[bx * 64 + tid];
        __syncthreads();

#pragma unroll
        for (int it = 0; it < 2; it++) {
            int w = it * 256 + tid;
            int j = w & 3, row = w >> 2;
            const float* tr = tileF + row * TSTR + j * 32;
            float inh[16];
#pragma unroll
            for (int h = 0; h < 16; h++) inh[h] = tr[16 + h];
            float o[16];
#pragma unroll
            for (int k = 0; k < 16; k++) {
                float lat = sblF[j * 16 + k];
#pragma unroll
                for (int h = 0; h < 16; h++) lat += inh[h] * sWlF[j * 256 + h * 16 + k];
                o[k] = fmaxf(tr[k] - lat, 0.f);
            }
            uint32_t hu[8], lu[8];
#pragma unroll
            for (int p = 0; p < 8; p++) split2(o[2 * p], o[2 * p + 1], hu[p], lu[p]);
            size_t oo = (size_t)(by * 128 + row) * DIM + (bx * 4 + j) * 16;
            *(uint4*)(oHi + oo)     = make_uint4(hu[0], hu[1], hu[2], hu[3]);
            *(uint4*)(oHi + oo + 8) = make_uint4(hu[4], hu[5], hu[6], hu[7]);
            *(uint4*)(oLo + oo)     = make_uint4(lu[0], lu[1], lu[2], lu[3]);
            *(uint4*)(oLo + oo + 8) = make_uint4(lu[4], lu[5], lu[6], lu[7]);
        }
        return;
    }

#pragma unroll
    for (int mt = 0; mt < 4; mt++) {
        const int r0 = by * BM + wm * 64 + mt * 16 + g;
#pragma unroll
        for (int nt = 0; nt < 4; nt++) {
            const int col = bx * BN + wn * 32 + nt * 8 + tg * 2;
            float2 bv = bias ? *(const float2*)(bias + col) : make_float2(0.f, 0.f);
            float2 v0, v1;
            v0.x = acc[mt][nt][0] + bv.x;  v0.y = acc[mt][nt][1] + bv.y;
            v1.x = acc[mt][nt][2] + bv.x;  v1.y = acc[mt][nt][3] + bv.y;
            if (EPI >= 2) {
                float* p0 = oF + (size_t)r0 * N + col;
                float* p1 = oF + (size_t)(r0 + 8) * N + col;
                if (EPI == 3) {
                    float2 o0 = *(const float2*)p0;
                    float2 o1 = *(const float2*)p1;
                    v0.x += o0.x; v0.y += o0.y; v1.x += o1.x; v1.y += o1.y;
                }
                *(float2*)p0 = v0;
                *(float2*)p1 = v1;
            }
            uint32_t h0, l0, h1, l1;
            split2(v0.x, v0.y, h0, l0);
            split2(v1.x, v1.y, h1, l1);
            *(uint32_t*)(oHi + (size_t)r0 * N + col)       = h0;
            *(uint32_t*)(oLo + (size_t)r0 * N + col)       = l0;
            *(uint32_t*)(oHi + (size_t)(r0 + 8) * N + col) = h1;
            *(uint32_t*)(oLo + (size_t)(r0 + 8) * N + col) = l1;
        }
    }
}

// ---------------- driver ----------------
extern "C" void kernel_launch(void* const* d_in, const int* in_sizes, int n_in,
                              void* d_out, int out_size) {
    const float* x    = (const float*)d_in[0];
    const float* We   = (const float*)d_in[1];
    const float* be   = (const float*)d_in[2];
    const float* Wi   = (const float*)d_in[3];
    const float* bi   = (const float*)d_in[4];
    const float* Wl   = (const float*)d_in[5];
    const float* bl   = (const float*)d_in[6];
    const float* Wlat = (const float*)d_in[7];
    const float* blat = (const float*)d_in[8];
    const float* Wv   = (const float*)d_in[9];
    const float* bv   = (const float*)d_in[10];
    const float* Wo   = (const float*)d_in[11];
    const float* bo   = (const float*)d_in[12];
    const float* fbW  = (const float*)d_in[13];
    const float* fbb  = (const float*)d_in[14];
    float* out = (float*)d_out;

    const size_t BD = (size_t)BATCH * DIM;

    __nv_bfloat16 *w_h, *w_l, *actA_h, *actA_l, *actB_h, *actB_l, *mc_h, *mc_l;
    float *bei_p, *b3_p, *wvo_f;
    cudaGetSymbolAddress((void**)&w_h, g_w_h);
    cudaGetSymbolAddress((void**)&w_l, g_w_l);
    cudaGetSymbolAddress((void**)&actA_h, g_actA_h);
    cudaGetSymbolAddress((void**)&actA_l, g_actA_l);
    cudaGetSymbolAddress((void**)&actB_h, g_actB_h);
    cudaGetSymbolAddress((void**)&actB_l, g_actB_l);
    cudaGetSymbolAddress((void**)&mc_h, g_mc_h);
    cudaGetSymbolAddress((void**)&mc_l, g_mc_l);
    cudaGetSymbolAddress((void**)&bei_p, g_bei);
    cudaGetSymbolAddress((void**)&b3_p, g_b3);
    cudaGetSymbolAddress((void**)&wvo_f, g_wvo_f);

    cudaFuncSetAttribute((const void*)bgemm<0, false>, cudaFuncAttributeMaxDynamicSharedMemorySize, SMEM_BYTES);
    cudaFuncSetAttribute((const void*)bgemm<0, true>,  cudaFuncAttributeMaxDynamicSharedMemorySize, SMEM_BYTES);
    cudaFuncSetAttribute((const void*)bgemm<2, true>,  cudaFuncAttributeMaxDynamicSharedMemorySize, SMEM_BYTES);
    cudaFuncSetAttribute((const void*)bgemm<1, false>, cudaFuncAttributeMaxDynamicSharedMemorySize, SMEM_BYTES);
    cudaFuncSetAttribute((const void*)bgemm<2, false>, cudaFuncAttributeMaxDynamicSharedMemorySize, SMEM_BYTES);
    cudaFuncSetAttribute((const void*)bgemm<3, false>, cudaFuncAttributeMaxDynamicSharedMemorySize, SMEM_BYTES);

    // ---- packs + weight-side precompute ----
    {
        size_t tw = (size_t)NLAY * DIM * 2 * DIM;
        pack_wei<<<(unsigned)((tw + 255) / 256), 256>>>(We, Wi);
        pack_split<<<(unsigned)(6 * SQ / 4 / 256), 256>>>(Wlat, w_h + OFF_LAT, w_l + OFF_LAT, 6 * SQ);
        pack_split<<<(unsigned)(6 * SQ / 4 / 256), 256>>>(Wv,   w_h + OFF_V,   w_l + OFF_V,   6 * SQ);
        pack_split<<<(unsigned)(6 * SQ / 4 / 256), 256>>>(Wo,   w_h + OFF_O,   w_l + OFF_O,   6 * SQ);
        pack_split<<<(unsigned)(5 * SQ / 4 / 256), 256>>>(fbW,  w_h + OFF_FB,  w_l + OFF_FB,  5 * SQ);
        pack_split<<<(unsigned)(BD / 4 / 256), 256>>>(x, actA_h, actA_l, BD);
        pack_bias_kernel<<<(NLAY * 2 * DIM + 255) / 256, 256>>>(be, bi);
        bvo_kernel<<<dim3(4, NLAY), 256>>>(bv, Wo, bo);
        bgemm<2, true><<<dim3(8, 48), 256, SMEM_BYTES>>>(
            w_h + OFF_V, w_l + OFF_V, w_h + OFF_O, w_l + OFF_O, nullptr,
            w_h + OFF_VO, w_l + OFF_VO, wvo_f, 1024, nullptr, nullptr);
        bgemm<0, true><<<dim3(8, 48), 256, SMEM_BYTES>>>(
            w_h + OFF_LAT, w_l + OFF_LAT, w_h + OFF_VO, w_l + OFF_VO, nullptr,
            w_h + OFF_W3, w_l + OFF_W3, nullptr, 1024, nullptr, nullptr);
        b3_kernel<<<dim3(4, NLAY), 256>>>(blat);
    }

    dim3 blk(256);
    dim3 grid_wide(2 * DIM / BN, BATCH / BM);
    dim3 grid_sq(DIM / BN, BATCH / BM);

    for (int l = 0; l < NLAY; l++) {
        const size_t weOff = OFF_WEI + (size_t)l * 2048 * 1024;
        bgemm<1, false><<<grid_wide, blk, SMEM_BYTES>>>(
            actA_h, actA_l, w_h + weOff, w_l + weOff, bei_p + l * 2048,
            mc_h, mc_l, nullptr, 2048,
            Wl + (size_t)l * NMC * HW * HW, bl + (size_t)l * NMC * HW);
        bgemm<2, false><<<grid_sq, blk, SMEM_BYTES>>>(
            mc_h, mc_l, w_h + OFF_W3 + (size_t)l * SQ, w_l + OFF_W3 + (size_t)l * SQ,
            b3_p + l * DIM, actA_h, actA_l, out + (size_t)l * BD, 1024, nullptr, nullptr);
    }

    __nv_bfloat16 *fin_h = actA_h, *fin_l = actA_l, *fout_h = actB_h, *fout_l = actB_l;
    for (int i = 0; i < NLAY - 1; i++) {
        int idx = NLAY - 2 - i;
        bgemm<3, false><<<grid_sq, blk, SMEM_BYTES>>>(
            fin_h, fin_l, w_h + OFF_FB + (size_t)i * SQ, w_l + OFF_FB + (size_t)i * SQ,
            fbb + (size_t)i * DIM, fout_h, fout_l, out + (size_t)idx * BD, 1024,
            nullptr, nullptr);
        __nv_bfloat16* t;
        t = fin_h; fin_h = fout_h; fout_h = t;
        t = fin_l; fin_l = fout_l; fout_l = t;
    }
}

// round 12
// speedup vs baseline: 1.0289x; 1.0150x over previous
#include <cuda_runtime.h>
#include <cuda_bf16.h>
#include <cstdint>

#define BATCH 16384
#define DIM   1024
#define NLAY  6
#define NMC   64
#define HW    16

#define BM 128
#define BN 128
#define BK 32
#define AST 40     // A smem row stride (bf16 elems)
#define WST 136    // W smem row stride (bf16 elems)
#define NST 2      // cp.async double buffer
#define NTCH (DIM / BK)   // 32 K-chunks

#define STG_ELEMS_A (BM * AST)
#define STG_ELEMS_W (BK * WST)
#define SMEM_BYTES ((2 * NST * STG_ELEMS_A + 2 * NST * STG_ELEMS_W) * 2)  // 75776
// fused-mc epilogue smem layout (fp32 view of same buffer):
#define TSTR 132
#define SWL_OFF (128 * TSTR)
#define SBL_OFF (SWL_OFF + 4 * 256)

// ---------------- static device scratch ----------------
#define SQ ((size_t)1048576)
#define OFF_WEI ((size_t)0)
#define OFF_LAT ((size_t)(6 * 2048 * 1024))
#define OFF_V   (OFF_LAT + 6 * SQ)
#define OFF_O   (OFF_V + 6 * SQ)
#define OFF_FB  (OFF_O + 6 * SQ)
#define OFF_VO  (OFF_FB + 5 * SQ)
#define OFF_W3  (OFF_VO + 6 * SQ)
#define WT_TOT  (OFF_W3 + 6 * SQ)

__device__ __nv_bfloat16 g_w_h[WT_TOT];
__device__ __nv_bfloat16 g_w_l[WT_TOT];
__device__ float g_bei[NLAY * 2 * DIM];   // interleaved [mc][exc16|inh16]
__device__ float g_bvo[NLAY * DIM];
__device__ float g_b3[NLAY * DIM];
__device__ float g_wvo_f[6 * SQ];         // fp32 Wvo (for exact b3)

__device__ __nv_bfloat16 g_actA_h[(size_t)BATCH * DIM];
__device__ __nv_bfloat16 g_actA_l[(size_t)BATCH * DIM];
__device__ __nv_bfloat16 g_actB_h[(size_t)BATCH * DIM];
__device__ __nv_bfloat16 g_actB_l[(size_t)BATCH * DIM];
__device__ __nv_bfloat16 g_mc_h[(size_t)BATCH * DIM];
__device__ __nv_bfloat16 g_mc_l[(size_t)BATCH * DIM];

// ---------------- helpers ----------------
__device__ __forceinline__ uint32_t cvt_bf16x2(float lo_elem, float hi_elem) {
    uint32_t r;
    asm("cvt.rn.bf16x2.f32 %0, %1, %2;" : "=r"(r) : "f"(hi_elem), "f"(lo_elem));
    return r;
}
__device__ __forceinline__ void split2(float a, float b, uint32_t& h, uint32_t& l) {
    h = cvt_bf16x2(a, b);
    float ha = __uint_as_float(h << 16);
    float hb = __uint_as_float(h & 0xffff0000u);
    l = cvt_bf16x2(a - ha, b - hb);
}
__device__ __forceinline__ void cp16(uint32_t dst, const void* src) {
    asm volatile("cp.async.cg.shared.global [%0], [%1], 16;" :: "r"(dst), "l"(src));
}
__device__ __forceinline__ void ldsm4(uint32_t addr, uint32_t& r0, uint32_t& r1,
                                      uint32_t& r2, uint32_t& r3) {
    asm volatile("ldmatrix.sync.aligned.m8n8.x4.shared.b16 {%0,%1,%2,%3}, [%4];"
                 : "=r"(r0), "=r"(r1), "=r"(r2), "=r"(r3) : "r"(addr));
}
__device__ __forceinline__ void ldsm4t(uint32_t addr, uint32_t& r0, uint32_t& r1,
                                       uint32_t& r2, uint32_t& r3) {
    asm volatile("ldmatrix.sync.aligned.m8n8.x4.trans.shared.b16 {%0,%1,%2,%3}, [%4];"
                 : "=r"(r0), "=r"(r1), "=r"(r2), "=r"(r3) : "r"(addr));
}
__device__ __forceinline__ void mma16816(float* c, const uint32_t* a, const uint32_t* b) {
    asm volatile(
        "mma.sync.aligned.m16n8k16.row.col.f32.bf16.bf16.f32 "
        "{%0,%1,%2,%3}, {%4,%5,%6,%7}, {%8,%9}, {%0,%1,%2,%3};"
        : "+f"(c[0]), "+f"(c[1]), "+f"(c[2]), "+f"(c[3])
        : "r"(a[0]), "r"(a[1]), "r"(a[2]), "r"(a[3]), "r"(b[0]), "r"(b[1]));
}

// ---------------- pack kernels ----------------
__global__ void pack_wei(const float* __restrict__ We, const float* __restrict__ Wi) {
    size_t i = (size_t)blockIdx.x * blockDim.x + threadIdx.x;
    const size_t total = (size_t)NLAY * DIM * 2 * DIM;
    if (i >= total) return;
    int l = (int)(i / ((size_t)DIM * 2 * DIM));
    size_t r = i % ((size_t)DIM * 2 * DIM);
    int k = (int)(r / (2 * DIM));
    int n = (int)(r % (2 * DIM));
    int mc = n >> 5, rr = n & 31;
    const float* src;
    int h;
    if (rr < 16) { src = We; h = rr; } else { src = Wi; h = rr - 16; }
    float v = src[(((size_t)l * NMC + mc) * DIM + k) * HW + h];
    __nv_bfloat16 hb = __float2bfloat16(v);
    g_w_h[OFF_WEI + i] = hb;
    g_w_l[OFF_WEI + i] = __float2bfloat16(v - __bfloat162float(hb));
}

__global__ void pack_split(const float* __restrict__ src, __nv_bfloat16* __restrict__ dh,
                           __nv_bfloat16* __restrict__ dl, size_t total) {
    size_t i = ((size_t)blockIdx.x * blockDim.x + threadIdx.x) * 4;
    if (i >= total) return;
    float4 v = *(const float4*)(src + i);
    uint32_t h0, l0, h1, l1;
    split2(v.x, v.y, h0, l0);
    split2(v.z, v.w, h1, l1);
    *(uint2*)(dh + i) = make_uint2(h0, h1);
    *(uint2*)(dl + i) = make_uint2(l0, l1);
}

__global__ void pack_bias_kernel(const float* __restrict__ be, const float* __restrict__ bi) {
    int i = blockIdx.x * blockDim.x + threadIdx.x;
    if (i >= NLAY * 2 * DIM) return;
    int l = i / (2 * DIM);
    int n = i % (2 * DIM);
    int mc = n >> 5, rr = n & 31;
    g_bei[i] = (rr < 16) ? be[l * DIM + mc * HW + rr] : bi[l * DIM + mc * HW + (rr - 16)];
}

__global__ void bvo_kernel(const float* __restrict__ bv, const float* __restrict__ Wo,
                           const float* __restrict__ bo) {
    int l = blockIdx.y;
    int n = blockIdx.x * 256 + threadIdx.x;
    const float* w = Wo + (size_t)l * SQ + n;
    const float* b = bv + l * DIM;
    float s = bo[l * DIM + n];
    for (int k = 0; k < DIM; k++) s += b[k] * w[(size_t)k * DIM];
    g_bvo[l * DIM + n] = s;
}

__global__ void b3_kernel(const float* __restrict__ blat) {
    int l = blockIdx.y;
    int n = blockIdx.x * 256 + threadIdx.x;
    const float* w = g_wvo_f + (size_t)l * SQ + n;
    const float* b = blat + l * DIM;
    float s = g_bvo[l * DIM + n];
    for (int k = 0; k < DIM; k++) s += b[k] * w[(size_t)k * DIM];
    g_b3[l * DIM + n] = s;
}

// ---------------- bf16x3 HMMA GEMM, 2-stage cp.async, 2 CTAs/SM, 1 barrier/chunk ----------------
// EPI 0: bias + hi/lo split out
// EPI 1: fused minicolumn epilogue (wide GEMM): relu, block-diag lat, mc out
// EPI 2: bias + fp32 out + split      EPI 3: bias + fp32 out += + split
// BATCH6: 6 contiguous matrices; l = by>>3 selects W
template <int EPI, bool BATCH6>
__global__ __launch_bounds__(256, 2)
void bgemm(const __nv_bfloat16* __restrict__ Ah, const __nv_bfloat16* __restrict__ Al,
           const __nv_bfloat16* __restrict__ Wh, const __nv_bfloat16* __restrict__ Wl,
           const float* __restrict__ bias,
           __nv_bfloat16* __restrict__ oHi, __nv_bfloat16* __restrict__ oLo,
           float* __restrict__ oF, int N,
           const float* __restrict__ mcW, const float* __restrict__ mcB) {
    extern __shared__ __nv_bfloat16 smem[];
    __nv_bfloat16* sAh = smem;                          // [NST][BM][AST]
    __nv_bfloat16* sAl = sAh + NST * STG_ELEMS_A;
    __nv_bfloat16* sWh = sAl + NST * STG_ELEMS_A;       // [NST][BK][WST]
    __nv_bfloat16* sWl = sWh + NST * STG_ELEMS_W;
    const uint32_t sAh_u = (uint32_t)__cvta_generic_to_shared(sAh);
    const uint32_t sAl_u = (uint32_t)__cvta_generic_to_shared(sAl);
    const uint32_t sWh_u = (uint32_t)__cvta_generic_to_shared(sWh);
    const uint32_t sWl_u = (uint32_t)__cvta_generic_to_shared(sWl);

    const int tid = threadIdx.x;
    const int lane = tid & 31, wid = tid >> 5;
    const int wm = wid >> 2, wn = wid & 3;
    const int bx = blockIdx.x, by = blockIdx.y;

    if (BATCH6) {
        size_t ws = (size_t)(by >> 3) * SQ;
        Wh += ws; Wl += ws;
    }

    const char* pAh = (const char*)Ah + (size_t)by * BM * (DIM * 2);
    const char* pAl = (const char*)Al + (size_t)by * BM * (DIM * 2);
    const char* pWh = (const char*)Wh + (size_t)bx * BN * 2;
    const char* pWl = (const char*)Wl + (size_t)bx * BN * 2;
    const size_t wrow_b = (size_t)N * 2;

    uint32_t sAb[2], sWb[2];
    size_t gA[2], gW[2];
#pragma unroll
    for (int i = 0; i < 2; i++) {
        int idx = i * 256 + tid;
        int ar = idx >> 2, ac = idx & 3;
        gA[i] = (size_t)ar * (DIM * 2) + (size_t)ac * 16;
        sAb[i] = (uint32_t)(ar * AST + ac * 8) * 2;
        int wr = idx >> 4, wc = idx & 15;
        gW[i] = (size_t)wr * wrow_b + (size_t)wc * 16;
        sWb[i] = (uint32_t)(wr * WST + wc * 8) * 2;
    }

    auto load_async = [&](int c) {
        const int buf = c & 1;
        const uint32_t offA = (uint32_t)(buf * STG_ELEMS_A * 2);
        const uint32_t offW = (uint32_t)(buf * STG_ELEMS_W * 2);
        const size_t cbA = (size_t)c * (BK * 2);
        const size_t cbW = (size_t)c * BK * wrow_b;
#pragma unroll
        for (int i = 0; i < 2; i++) {
            cp16(sAh_u + offA + sAb[i], pAh + gA[i] + cbA);
            cp16(sAl_u + offA + sAb[i], pAl + gA[i] + cbA);
            cp16(sWh_u + offW + sWb[i], pWh + gW[i] + cbW);
            cp16(sWl_u + offW + sWb[i], pWl + gW[i] + cbW);
        }
        asm volatile("cp.async.commit_group;" ::: "memory");
    };

    float acc[4][4][4];
#pragma unroll
    for (int mt = 0; mt < 4; mt++)
#pragma unroll
        for (int nt = 0; nt < 4; nt++)
#pragma unroll
            for (int q = 0; q < 4; q++) acc[mt][nt][q] = 0.f;

    load_async(0);

    const int lrow = lane & 15;
    const int lcol8 = (lane >> 4) * 8;

    for (int t = 0; t < NTCH; t++) {
        asm volatile("cp.async.wait_group 0;" ::: "memory");
        __syncthreads();
        // No trailing barrier needed: this load writes buffer (t+1)&1, whose last
        // reads happened at iter t-1 — all warps finished them before passing the
        // barrier above.
        if (t + 1 < NTCH) load_async(t + 1);

        const int buf = t & 1;
        const uint32_t bA = (uint32_t)(buf * STG_ELEMS_A * 2);
        const uint32_t bW = (uint32_t)(buf * STG_ELEMS_W * 2);

#pragma unroll
        for (int ks = 0; ks < 2; ks++) {
            uint32_t ah[4][4], al[4][4], bh[4][2], bl[4][2];
#pragma unroll
            for (int mt = 0; mt < 4; mt++) {
                uint32_t off = bA + (uint32_t)((wm * 64 + mt * 16 + lrow) * AST +
                                               ks * 16 + lcol8) * 2;
                ldsm4(sAh_u + off, ah[mt][0], ah[mt][1], ah[mt][2], ah[mt][3]);
                ldsm4(sAl_u + off, al[mt][0], al[mt][1], al[mt][2], al[mt][3]);
            }
#pragma unroll
            for (int np = 0; np < 2; np++) {
                uint32_t off = bW + (uint32_t)((ks * 16 + lrow) * WST +
                                               wn * 32 + np * 16 + lcol8) * 2;
                uint32_t r0, r1, r2, r3;
                ldsm4t(sWh_u + off, r0, r1, r2, r3);
                bh[np * 2][0] = r0; bh[np * 2][1] = r1;
                bh[np * 2 + 1][0] = r2; bh[np * 2 + 1][1] = r3;
                ldsm4t(sWl_u + off, r0, r1, r2, r3);
                bl[np * 2][0] = r0; bl[np * 2][1] = r1;
                bl[np * 2 + 1][0] = r2; bl[np * 2 + 1][1] = r3;
            }
#pragma unroll
            for (int mt = 0; mt < 4; mt++)
#pragma unroll
                for (int nt = 0; nt < 4; nt++) mma16816(acc[mt][nt], ah[mt], bh[nt]);
#pragma unroll
            for (int mt = 0; mt < 4; mt++)
#pragma unroll
                for (int nt = 0; nt < 4; nt++) mma16816(acc[mt][nt], ah[mt], bl[nt]);
#pragma unroll
            for (int mt = 0; mt < 4; mt++)
#pragma unroll
                for (int nt = 0; nt < 4; nt++) mma16816(acc[mt][nt], al[mt], bh[nt]);
        }
    }
    __syncthreads();   // protect smem before EPI==1 epilogue reuse

    // ---------------- epilogue ----------------
    const int g = lane >> 2;
    const int tg = lane & 3;

    if (EPI == 1) {
        float* tileF = (float*)smem;
#pragma unroll
        for (int mt = 0; mt < 4; mt++) {
            const int rl = wm * 64 + mt * 16 + g;
#pragma unroll
            for (int nt = 0; nt < 4; nt++) {
                const int cl = wn * 32 + nt * 8 + tg * 2;
                float2 bv = *(const float2*)(bias + bx * BN + cl);
                tileF[rl * TSTR + cl]           = fmaxf(acc[mt][nt][0] + bv.x, 0.f);
                tileF[rl * TSTR + cl + 1]       = fmaxf(acc[mt][nt][1] + bv.y, 0.f);
                tileF[(rl + 8) * TSTR + cl]     = fmaxf(acc[mt][nt][2] + bv.x, 0.f);
                tileF[(rl + 8) * TSTR + cl + 1] = fmaxf(acc[mt][nt][3] + bv.y, 0.f);
            }
        }
        float* sWlF = tileF + SWL_OFF;
        float* sblF = tileF + SBL_OFF;
#pragma unroll
        for (int i = 0; i < 4; i++) sWlF[i * 256 + tid] = mcW[(size_t)(bx * 4) * 256 + i * 256 + tid];
        if (tid < 64) sblF[tid] = mcB[bx * 64 + tid];
        __syncthreads();

#pragma unroll
        for (int it = 0; it < 2; it++) {
            int w = it * 256 + tid;
            int j = w & 3, row = w >> 2;
            const float* tr = tileF + row * TSTR + j * 32;
            float inh[16];
#pragma unroll
            for (int h = 0; h < 16; h++) inh[h] = tr[16 + h];
            float o[16];
#pragma unroll
            for (int k = 0; k < 16; k++) {
                float lat = sblF[j * 16 + k];
#pragma unroll
                for (int h = 0; h < 16; h++) lat += inh[h] * sWlF[j * 256 + h * 16 + k];
                o[k] = fmaxf(tr[k] - lat, 0.f);
            }
            uint32_t hu[8], lu[8];
#pragma unroll
            for (int p = 0; p < 8; p++) split2(o[2 * p], o[2 * p + 1], hu[p], lu[p]);
            size_t oo = (size_t)(by * 128 + row) * DIM + (bx * 4 + j) * 16;
            *(uint4*)(oHi + oo)     = make_uint4(hu[0], hu[1], hu[2], hu[3]);
            *(uint4*)(oHi + oo + 8) = make_uint4(hu[4], hu[5], hu[6], hu[7]);
            *(uint4*)(oLo + oo)     = make_uint4(lu[0], lu[1], lu[2], lu[3]);
            *(uint4*)(oLo + oo + 8) = make_uint4(lu[4], lu[5], lu[6], lu[7]);
        }
        return;
    }

#pragma unroll
    for (int mt = 0; mt < 4; mt++) {
        const int r0 = by * BM + wm * 64 + mt * 16 + g;
#pragma unroll
        for (int nt = 0; nt < 4; nt++) {
            const int col = bx * BN + wn * 32 + nt * 8 + tg * 2;
            float2 bv = bias ? *(const float2*)(bias + col) : make_float2(0.f, 0.f);
            float2 v0, v1;
            v0.x = acc[mt][nt][0] + bv.x;  v0.y = acc[mt][nt][1] + bv.y;
            v1.x = acc[mt][nt][2] + bv.x;  v1.y = acc[mt][nt][3] + bv.y;
            if (EPI >= 2) {
                float* p0 = oF + (size_t)r0 * N + col;
                float* p1 = oF + (size_t)(r0 + 8) * N + col;
                if (EPI == 3) {
                    float2 o0 = *(const float2*)p0;
                    float2 o1 = *(const float2*)p1;
                    v0.x += o0.x; v0.y += o0.y; v1.x += o1.x; v1.y += o1.y;
                }
                *(float2*)p0 = v0;
                *(float2*)p1 = v1;
            }
            uint32_t h0, l0, h1, l1;
            split2(v0.x, v0.y, h0, l0);
            split2(v1.x, v1.y, h1, l1);
            *(uint32_t*)(oHi + (size_t)r0 * N + col)       = h0;
            *(uint32_t*)(oLo + (size_t)r0 * N + col)       = l0;
            *(uint32_t*)(oHi + (size_t)(r0 + 8) * N + col) = h1;
            *(uint32_t*)(oLo + (size_t)(r0 + 8) * N + col) = l1;
        }
    }
}

// ---------------- driver ----------------
extern "C" void kernel_launch(void* const* d_in, const int* in_sizes, int n_in,
                              void* d_out, int out_size) {
    const float* x    = (const float*)d_in[0];
    const float* We   = (const float*)d_in[1];
    const float* be   = (const float*)d_in[2];
    const float* Wi   = (const float*)d_in[3];
    const float* bi   = (const float*)d_in[4];
    const float* Wl   = (const float*)d_in[5];
    const float* bl   = (const float*)d_in[6];
    const float* Wlat = (const float*)d_in[7];
    const float* blat = (const float*)d_in[8];
    const float* Wv   = (const float*)d_in[9];
    const float* bv   = (const float*)d_in[10];
    const float* Wo   = (const float*)d_in[11];
    const float* bo   = (const float*)d_in[12];
    const float* fbW  = (const float*)d_in[13];
    const float* fbb  = (const float*)d_in[14];
    float* out = (float*)d_out;

    const size_t BD = (size_t)BATCH * DIM;

    __nv_bfloat16 *w_h, *w_l, *actA_h, *actA_l, *actB_h, *actB_l, *mc_h, *mc_l;
    float *bei_p, *b3_p, *wvo_f;
    cudaGetSymbolAddress((void**)&w_h, g_w_h);
    cudaGetSymbolAddress((void**)&w_l, g_w_l);
    cudaGetSymbolAddress((void**)&actA_h, g_actA_h);
    cudaGetSymbolAddress((void**)&actA_l, g_actA_l);
    cudaGetSymbolAddress((void**)&actB_h, g_actB_h);
    cudaGetSymbolAddress((void**)&actB_l, g_actB_l);
    cudaGetSymbolAddress((void**)&mc_h, g_mc_h);
    cudaGetSymbolAddress((void**)&mc_l, g_mc_l);
    cudaGetSymbolAddress((void**)&bei_p, g_bei);
    cudaGetSymbolAddress((void**)&b3_p, g_b3);
    cudaGetSymbolAddress((void**)&wvo_f, g_wvo_f);

    cudaFuncSetAttribute((const void*)bgemm<0, false>, cudaFuncAttributeMaxDynamicSharedMemorySize, SMEM_BYTES);
    cudaFuncSetAttribute((const void*)bgemm<0, true>,  cudaFuncAttributeMaxDynamicSharedMemorySize, SMEM_BYTES);
    cudaFuncSetAttribute((const void*)bgemm<2, true>,  cudaFuncAttributeMaxDynamicSharedMemorySize, SMEM_BYTES);
    cudaFuncSetAttribute((const void*)bgemm<1, false>, cudaFuncAttributeMaxDynamicSharedMemorySize, SMEM_BYTES);
    cudaFuncSetAttribute((const void*)bgemm<2, false>, cudaFuncAttributeMaxDynamicSharedMemorySize, SMEM_BYTES);
    cudaFuncSetAttribute((const void*)bgemm<3, false>, cudaFuncAttributeMaxDynamicSharedMemorySize, SMEM_BYTES);

    // ---- packs + weight-side precompute ----
    {
        size_t tw = (size_t)NLAY * DIM * 2 * DIM;
        pack_wei<<<(unsigned)((tw + 255) / 256), 256>>>(We, Wi);
        pack_split<<<(unsigned)(6 * SQ / 4 / 256), 256>>>(Wlat, w_h + OFF_LAT, w_l + OFF_LAT, 6 * SQ);
        pack_split<<<(unsigned)(6 * SQ / 4 / 256), 256>>>(Wv,   w_h + OFF_V,   w_l + OFF_V,   6 * SQ);
        pack_split<<<(unsigned)(6 * SQ / 4 / 256), 256>>>(Wo,   w_h + OFF_O,   w_l + OFF_O,   6 * SQ);
        pack_split<<<(unsigned)(5 * SQ / 4 / 256), 256>>>(fbW,  w_h + OFF_FB,  w_l + OFF_FB,  5 * SQ);
        pack_split<<<(unsigned)(BD / 4 / 256), 256>>>(x, actA_h, actA_l, BD);
        pack_bias_kernel<<<(NLAY * 2 * DIM + 255) / 256, 256>>>(be, bi);
        bvo_kernel<<<dim3(4, NLAY), 256>>>(bv, Wo, bo);
        bgemm<2, true><<<dim3(8, 48), 256, SMEM_BYTES>>>(
            w_h + OFF_V, w_l + OFF_V, w_h + OFF_O, w_l + OFF_O, nullptr,
            w_h + OFF_VO, w_l + OFF_VO, wvo_f, 1024, nullptr, nullptr);
        bgemm<0, true><<<dim3(8, 48), 256, SMEM_BYTES>>>(
            w_h + OFF_LAT, w_l + OFF_LAT, w_h + OFF_VO, w_l + OFF_VO, nullptr,
            w_h + OFF_W3, w_l + OFF_W3, nullptr, 1024, nullptr, nullptr);
        b3_kernel<<<dim3(4, NLAY), 256>>>(blat);
    }

    dim3 blk(256);
    dim3 grid_wide(2 * DIM / BN, BATCH / BM);
    dim3 grid_sq(DIM / BN, BATCH / BM);

    for (int l = 0; l < NLAY; l++) {
        const size_t weOff = OFF_WEI + (size_t)l * 2048 * 1024;
        bgemm<1, false><<<grid_wide, blk, SMEM_BYTES>>>(
            actA_h, actA_l, w_h + weOff, w_l + weOff, bei_p + l * 2048,
            mc_h, mc_l, nullptr, 2048,
            Wl + (size_t)l * NMC * HW * HW, bl + (size_t)l * NMC * HW);
        bgemm<2, false><<<grid_sq, blk, SMEM_BYTES>>>(
            mc_h, mc_l, w_h + OFF_W3 + (size_t)l * SQ, w_l + OFF_W3 + (size_t)l * SQ,
            b3_p + l * DIM, actA_h, actA_l, out + (size_t)l * BD, 1024, nullptr, nullptr);
    }

    __nv_bfloat16 *fin_h = actA_h, *fin_l = actA_l, *fout_h = actB_h, *fout_l = actB_l;
    for (int i = 0; i < NLAY - 1; i++) {
        int idx = NLAY - 2 - i;
        bgemm<3, false><<<grid_sq, blk, SMEM_BYTES>>>(
            fin_h, fin_l, w_h + OFF_FB + (size_t)i * SQ, w_l + OFF_FB + (size_t)i * SQ,
            fbb + (size_t)i * DIM, fout_h, fout_l, out + (size_t)idx * BD, 1024,
            nullptr, nullptr);
        __nv_bfloat16* t;
        t = fin_h; fin_h = fout_h; fout_h = t;
        t = fin_l; fin_l = fout_l; fout_l = t;
    }
}

// round 13
// speedup vs baseline: 1.0369x; 1.0078x over previous
#include <cuda_runtime.h>
#include <cuda_bf16.h>
#include <cstdint>

#define BATCH 16384
#define DIM   1024
#define NLAY  6
#define NMC   64
#define HW    16

#define BM 128
#define BN 128
#define BK 32
#define AST 40     // A smem row stride (bf16 elems)
#define WST 136    // W smem row stride (bf16 elems)
#define NST 2      // cp.async double buffer
#define NTCH (DIM / BK)   // 32 K-chunks

#define STG_ELEMS_A (BM * AST)
#define STG_ELEMS_W (BK * WST)
#define SMEM_BYTES ((2 * NST * STG_ELEMS_A + 2 * NST * STG_ELEMS_W) * 2)  // 75776
// fused-mc epilogue smem layout (fp32 view of same buffer):
#define TSTR 132
#define SWL_OFF (128 * TSTR)
#define SBL_OFF (SWL_OFF + 4 * 256)

// ---------------- static device scratch ----------------
#define SQ ((size_t)1048576)
#define OFF_WEI ((size_t)0)
#define OFF_LAT ((size_t)(6 * 2048 * 1024))
#define OFF_V   (OFF_LAT + 6 * SQ)
#define OFF_O   (OFF_V + 6 * SQ)
#define OFF_FB  (OFF_O + 6 * SQ)
#define OFF_VO  (OFF_FB + 5 * SQ)
#define OFF_W3  (OFF_VO + 6 * SQ)
#define WT_TOT  (OFF_W3 + 6 * SQ)

__device__ __nv_bfloat16 g_w_h[WT_TOT];
__device__ __nv_bfloat16 g_w_l[WT_TOT];
__device__ float g_bei[NLAY * 2 * DIM];   // interleaved [mc][exc16|inh16]
__device__ float g_bvo[NLAY * DIM];
__device__ float g_b3[NLAY * DIM];
__device__ float g_wvo_f[6 * SQ];         // fp32 Wvo (for exact b3)

__device__ __nv_bfloat16 g_actA_h[(size_t)BATCH * DIM];
__device__ __nv_bfloat16 g_actA_l[(size_t)BATCH * DIM];
__device__ __nv_bfloat16 g_actB_h[(size_t)BATCH * DIM];
__device__ __nv_bfloat16 g_actB_l[(size_t)BATCH * DIM];
__device__ __nv_bfloat16 g_mc_h[(size_t)BATCH * DIM];
__device__ __nv_bfloat16 g_mc_l[(size_t)BATCH * DIM];

// ---------------- helpers ----------------
__device__ __forceinline__ uint32_t cvt_bf16x2(float lo_elem, float hi_elem) {
    uint32_t r;
    asm("cvt.rn.bf16x2.f32 %0, %1, %2;" : "=r"(r) : "f"(hi_elem), "f"(lo_elem));
    return r;
}
__device__ __forceinline__ void split2(float a, float b, uint32_t& h, uint32_t& l) {
    h = cvt_bf16x2(a, b);
    float ha = __uint_as_float(h << 16);
    float hb = __uint_as_float(h & 0xffff0000u);
    l = cvt_bf16x2(a - ha, b - hb);
}
__device__ __forceinline__ void cp16(uint32_t dst, const void* src) {
    asm volatile("cp.async.cg.shared.global [%0], [%1], 16;" :: "r"(dst), "l"(src));
}
__device__ __forceinline__ void ldsm4(uint32_t addr, uint32_t& r0, uint32_t& r1,
                                      uint32_t& r2, uint32_t& r3) {
    asm volatile("ldmatrix.sync.aligned.m8n8.x4.shared.b16 {%0,%1,%2,%3}, [%4];"
                 : "=r"(r0), "=r"(r1), "=r"(r2), "=r"(r3) : "r"(addr));
}
__device__ __forceinline__ void ldsm4t(uint32_t addr, uint32_t& r0, uint32_t& r1,
                                       uint32_t& r2, uint32_t& r3) {
    asm volatile("ldmatrix.sync.aligned.m8n8.x4.trans.shared.b16 {%0,%1,%2,%3}, [%4];"
                 : "=r"(r0), "=r"(r1), "=r"(r2), "=r"(r3) : "r"(addr));
}
__device__ __forceinline__ void mma16816(float* c, const uint32_t* a, const uint32_t* b) {
    asm volatile(
        "mma.sync.aligned.m16n8k16.row.col.f32.bf16.bf16.f32 "
        "{%0,%1,%2,%3}, {%4,%5,%6,%7}, {%8,%9}, {%0,%1,%2,%3};"
        : "+f"(c[0]), "+f"(c[1]), "+f"(c[2]), "+f"(c[3])
        : "r"(a[0]), "r"(a[1]), "r"(a[2]), "r"(a[3]), "r"(b[0]), "r"(b[1]));
}

// ---------------- pack kernels ----------------
__global__ void pack_wei(const float* __restrict__ We, const float* __restrict__ Wi) {
    size_t i = (size_t)blockIdx.x * blockDim.x + threadIdx.x;
    const size_t total = (size_t)NLAY * DIM * 2 * DIM;
    if (i >= total) return;
    int l = (int)(i / ((size_t)DIM * 2 * DIM));
    size_t r = i % ((size_t)DIM * 2 * DIM);
    int k = (int)(r / (2 * DIM));
    int n = (int)(r % (2 * DIM));
    int mc = n >> 5, rr = n & 31;
    const float* src;
    int h;
    if (rr < 16) { src = We; h = rr; } else { src = Wi; h = rr - 16; }
    float v = src[(((size_t)l * NMC + mc) * DIM + k) * HW + h];
    __nv_bfloat16 hb = __float2bfloat16(v);
    g_w_h[OFF_WEI + i] = hb;
    g_w_l[OFF_WEI + i] = __float2bfloat16(v - __bfloat162float(hb));
}

__global__ void pack_split(const float* __restrict__ src, __nv_bfloat16* __restrict__ dh,
                           __nv_bfloat16* __restrict__ dl, size_t total) {
    size_t i = ((size_t)blockIdx.x * blockDim.x + threadIdx.x) * 4;
    if (i >= total) return;
    float4 v = *(const float4*)(src + i);
    uint32_t h0, l0, h1, l1;
    split2(v.x, v.y, h0, l0);
    split2(v.z, v.w, h1, l1);
    *(uint2*)(dh + i) = make_uint2(h0, h1);
    *(uint2*)(dl + i) = make_uint2(l0, l1);
}

__global__ void pack_bias_kernel(const float* __restrict__ be, const float* __restrict__ bi) {
    int i = blockIdx.x * blockDim.x + threadIdx.x;
    if (i >= NLAY * 2 * DIM) return;
    int l = i / (2 * DIM);
    int n = i % (2 * DIM);
    int mc = n >> 5, rr = n & 31;
    g_bei[i] = (rr < 16) ? be[l * DIM + mc * HW + rr] : bi[l * DIM + mc * HW + (rr - 16)];
}

__global__ void bvo_kernel(const float* __restrict__ bv, const float* __restrict__ Wo,
                           const float* __restrict__ bo) {
    int l = blockIdx.y;
    int n = blockIdx.x * 256 + threadIdx.x;
    const float* w = Wo + (size_t)l * SQ + n;
    const float* b = bv + l * DIM;
    float s = bo[l * DIM + n];
    for (int k = 0; k < DIM; k++) s += b[k] * w[(size_t)k * DIM];
    g_bvo[l * DIM + n] = s;
}

__global__ void b3_kernel(const float* __restrict__ blat) {
    int l = blockIdx.y;
    int n = blockIdx.x * 256 + threadIdx.x;
    const float* w = g_wvo_f + (size_t)l * SQ + n;
    const float* b = blat + l * DIM;
    float s = g_bvo[l * DIM + n];
    for (int k = 0; k < DIM; k++) s += b[k] * w[(size_t)k * DIM];
    g_b3[l * DIM + n] = s;
}

// ---------------- bf16x3 HMMA GEMM, 2-stage cp.async, 2 CTAs/SM, 1 barrier/chunk ----------------
// EPI 0: bias + hi/lo split out
// EPI 1: fused minicolumn epilogue (wide GEMM): relu, block-diag lat, mc out
// EPI 2: bias + fp32 out + split      EPI 3: bias + fp32 out += + split (skipped if oHi null)
// BATCH6: 6 contiguous matrices; l = by>>3 selects W
template <int EPI, bool BATCH6>
__global__ __launch_bounds__(256, 2)
void bgemm(const __nv_bfloat16* __restrict__ Ah, const __nv_bfloat16* __restrict__ Al,
           const __nv_bfloat16* __restrict__ Wh, const __nv_bfloat16* __restrict__ Wl,
           const float* __restrict__ bias,
           __nv_bfloat16* __restrict__ oHi, __nv_bfloat16* __restrict__ oLo,
           float* __restrict__ oF, int N,
           const float* __restrict__ mcW, const float* __restrict__ mcB) {
    extern __shared__ __nv_bfloat16 smem[];
    __nv_bfloat16* sAh = smem;                          // [NST][BM][AST]
    __nv_bfloat16* sAl = sAh + NST * STG_ELEMS_A;
    __nv_bfloat16* sWh = sAl + NST * STG_ELEMS_A;       // [NST][BK][WST]
    __nv_bfloat16* sWl = sWh + NST * STG_ELEMS_W;
    const uint32_t sAh_u = (uint32_t)__cvta_generic_to_shared(sAh);
    const uint32_t sAl_u = (uint32_t)__cvta_generic_to_shared(sAl);
    const uint32_t sWh_u = (uint32_t)__cvta_generic_to_shared(sWh);
    const uint32_t sWl_u = (uint32_t)__cvta_generic_to_shared(sWl);

    const int tid = threadIdx.x;
    const int lane = tid & 31, wid = tid >> 5;
    const int wm = wid >> 2, wn = wid & 3;
    const int bx = blockIdx.x, by = blockIdx.y;

    if (BATCH6) {
        size_t ws = (size_t)(by >> 3) * SQ;
        Wh += ws; Wl += ws;
    }

    const char* pAh = (const char*)Ah + (size_t)by * BM * (DIM * 2);
    const char* pAl = (const char*)Al + (size_t)by * BM * (DIM * 2);
    const char* pWh = (const char*)Wh + (size_t)bx * BN * 2;
    const char* pWl = (const char*)Wl + (size_t)bx * BN * 2;
    const size_t wrow_b = (size_t)N * 2;

    uint32_t sAb[2], sWb[2];
    size_t gA[2], gW[2];
#pragma unroll
    for (int i = 0; i < 2; i++) {
        int idx = i * 256 + tid;
        int ar = idx >> 2, ac = idx & 3;
        gA[i] = (size_t)ar * (DIM * 2) + (size_t)ac * 16;
        sAb[i] = (uint32_t)(ar * AST + ac * 8) * 2;
        int wr = idx >> 4, wc = idx & 15;
        gW[i] = (size_t)wr * wrow_b + (size_t)wc * 16;
        sWb[i] = (uint32_t)(wr * WST + wc * 8) * 2;
    }

    auto load_async = [&](int c) {
        const int buf = c & 1;
        const uint32_t offA = (uint32_t)(buf * STG_ELEMS_A * 2);
        const uint32_t offW = (uint32_t)(buf * STG_ELEMS_W * 2);
        const size_t cbA = (size_t)c * (BK * 2);
        const size_t cbW = (size_t)c * BK * wrow_b;
#pragma unroll
        for (int i = 0; i < 2; i++) {
            cp16(sAh_u + offA + sAb[i], pAh + gA[i] + cbA);
            cp16(sAl_u + offA + sAb[i], pAl + gA[i] + cbA);
            cp16(sWh_u + offW + sWb[i], pWh + gW[i] + cbW);
            cp16(sWl_u + offW + sWb[i], pWl + gW[i] + cbW);
        }
        asm volatile("cp.async.commit_group;" ::: "memory");
    };

    float acc[4][4][4];
#pragma unroll
    for (int mt = 0; mt < 4; mt++)
#pragma unroll
        for (int nt = 0; nt < 4; nt++)
#pragma unroll
            for (int q = 0; q < 4; q++) acc[mt][nt][q] = 0.f;

    load_async(0);

    const int lrow = lane & 15;
    const int lcol8 = (lane >> 4) * 8;

    for (int t = 0; t < NTCH; t++) {
        asm volatile("cp.async.wait_group 0;" ::: "memory");
        __syncthreads();
        // No trailing barrier needed: this load writes buffer (t+1)&1, whose last
        // reads happened at iter t-1 — all warps finished them before passing the
        // barrier above.
        if (t + 1 < NTCH) load_async(t + 1);

        const int buf = t & 1;
        const uint32_t bA = (uint32_t)(buf * STG_ELEMS_A * 2);
        const uint32_t bW = (uint32_t)(buf * STG_ELEMS_W * 2);

#pragma unroll
        for (int ks = 0; ks < 2; ks++) {
            uint32_t ah[4][4], al[4][4], bh[4][2], bl[4][2];
#pragma unroll
            for (int mt = 0; mt < 4; mt++) {
                uint32_t off = bA + (uint32_t)((wm * 64 + mt * 16 + lrow) * AST +
                                               ks * 16 + lcol8) * 2;
                ldsm4(sAh_u + off, ah[mt][0], ah[mt][1], ah[mt][2], ah[mt][3]);
                ldsm4(sAl_u + off, al[mt][0], al[mt][1], al[mt][2], al[mt][3]);
            }
#pragma unroll
            for (int np = 0; np < 2; np++) {
                uint32_t off = bW + (uint32_t)((ks * 16 + lrow) * WST +
                                               wn * 32 + np * 16 + lcol8) * 2;
                uint32_t r0, r1, r2, r3;
                ldsm4t(sWh_u + off, r0, r1, r2, r3);
                bh[np * 2][0] = r0; bh[np * 2][1] = r1;
                bh[np * 2 + 1][0] = r2; bh[np * 2 + 1][1] = r3;
                ldsm4t(sWl_u + off, r0, r1, r2, r3);
                bl[np * 2][0] = r0; bl[np * 2][1] = r1;
                bl[np * 2 + 1][0] = r2; bl[np * 2 + 1][1] = r3;
            }
#pragma unroll
            for (int mt = 0; mt < 4; mt++)
#pragma unroll
                for (int nt = 0; nt < 4; nt++) mma16816(acc[mt][nt], ah[mt], bh[nt]);
#pragma unroll
            for (int mt = 0; mt < 4; mt++)
#pragma unroll
                for (int nt = 0; nt < 4; nt++) mma16816(acc[mt][nt], ah[mt], bl[nt]);
#pragma unroll
            for (int mt = 0; mt < 4; mt++)
#pragma unroll
                for (int nt = 0; nt < 4; nt++) mma16816(acc[mt][nt], al[mt], bh[nt]);
        }
    }
    __syncthreads();   // protect smem before EPI==1 epilogue reuse

    // ---------------- epilogue ----------------
    const int g = lane >> 2;
    const int tg = lane & 3;

    if (EPI == 1) {
        float* tileF = (float*)smem;
#pragma unroll
        for (int mt = 0; mt < 4; mt++) {
            const int rl = wm * 64 + mt * 16 + g;
#pragma unroll
            for (int nt = 0; nt < 4; nt++) {
                const int cl = wn * 32 + nt * 8 + tg * 2;
                float2 bv = *(const float2*)(bias + bx * BN + cl);
                tileF[rl * TSTR + cl]           = fmaxf(acc[mt][nt][0] + bv.x, 0.f);
                tileF[rl * TSTR + cl + 1]       = fmaxf(acc[mt][nt][1] + bv.y, 0.f);
                tileF[(rl + 8) * TSTR + cl]     = fmaxf(acc[mt][nt][2] + bv.x, 0.f);
                tileF[(rl + 8) * TSTR + cl + 1] = fmaxf(acc[mt][nt][3] + bv.y, 0.f);
            }
        }
        float* sWlF = tileF + SWL_OFF;
        float* sblF = tileF + SBL_OFF;
#pragma unroll
        for (int i = 0; i < 4; i++) sWlF[i * 256 + tid] = mcW[(size_t)(bx * 4) * 256 + i * 256 + tid];
        if (tid < 64) sblF[tid] = mcB[bx * 64 + tid];
        __syncthreads();

#pragma unroll
        for (int it = 0; it < 2; it++) {
            int w = it * 256 + tid;
            int j = w & 3, row = w >> 2;
            const float* tr = tileF + row * TSTR + j * 32;
            float inh[16];
#pragma unroll
            for (int h = 0; h < 16; h++) inh[h] = tr[16 + h];
            float o[16];
#pragma unroll
            for (int k = 0; k < 16; k++) {
                float lat = sblF[j * 16 + k];
#pragma unroll
                for (int h = 0; h < 16; h++) lat += inh[h] * sWlF[j * 256 + h * 16 + k];
                o[k] = fmaxf(tr[k] - lat, 0.f);
            }
            uint32_t hu[8], lu[8];
#pragma unroll
            for (int p = 0; p < 8; p++) split2(o[2 * p], o[2 * p + 1], hu[p], lu[p]);
            size_t oo = (size_t)(by * 128 + row) * DIM + (bx * 4 + j) * 16;
            *(uint4*)(oHi + oo)     = make_uint4(hu[0], hu[1], hu[2], hu[3]);
            *(uint4*)(oHi + oo + 8) = make_uint4(hu[4], hu[5], hu[6], hu[7]);
            *(uint4*)(oLo + oo)     = make_uint4(lu[0], lu[1], lu[2], lu[3]);
            *(uint4*)(oLo + oo + 8) = make_uint4(lu[4], lu[5], lu[6], lu[7]);
        }
        return;
    }

    const bool do_split = (EPI != 3) || (oHi != nullptr);
#pragma unroll
    for (int mt = 0; mt < 4; mt++) {
        const int r0 = by * BM + wm * 64 + mt * 16 + g;
#pragma unroll
        for (int nt = 0; nt < 4; nt++) {
            const int col = bx * BN + wn * 32 + nt * 8 + tg * 2;
            float2 bv = bias ? *(const float2*)(bias + col) : make_float2(0.f, 0.f);
            float2 v0, v1;
            v0.x = acc[mt][nt][0] + bv.x;  v0.y = acc[mt][nt][1] + bv.y;
            v1.x = acc[mt][nt][2] + bv.x;  v1.y = acc[mt][nt][3] + bv.y;
            if (EPI >= 2) {
                float* p0 = oF + (size_t)r0 * N + col;
                float* p1 = oF + (size_t)(r0 + 8) * N + col;
                if (EPI == 3) {
                    float2 o0 = *(const float2*)p0;
                    float2 o1 = *(const float2*)p1;
                    v0.x += o0.x; v0.y += o0.y; v1.x += o1.x; v1.y += o1.y;
                }
                *(float2*)p0 = v0;
                *(float2*)p1 = v1;
            }
            if (do_split) {
                uint32_t h0, l0, h1, l1;
                split2(v0.x, v0.y, h0, l0);
                split2(v1.x, v1.y, h1, l1);
                *(uint32_t*)(oHi + (size_t)r0 * N + col)       = h0;
                *(uint32_t*)(oLo + (size_t)r0 * N + col)       = l0;
                *(uint32_t*)(oHi + (size_t)(r0 + 8) * N + col) = h1;
                *(uint32_t*)(oLo + (size_t)(r0 + 8) * N + col) = l1;
            }
        }
    }
}

// ---------------- driver ----------------
extern "C" void kernel_launch(void* const* d_in, const int* in_sizes, int n_in,
                              void* d_out, int out_size) {
    const float* x    = (const float*)d_in[0];
    const float* We   = (const float*)d_in[1];
    const float* be   = (const float*)d_in[2];
    const float* Wi   = (const float*)d_in[3];
    const float* bi   = (const float*)d_in[4];
    const float* Wl   = (const float*)d_in[5];
    const float* bl   = (const float*)d_in[6];
    const float* Wlat = (const float*)d_in[7];
    const float* blat = (const float*)d_in[8];
    const float* Wv   = (const float*)d_in[9];
    const float* bv   = (const float*)d_in[10];
    const float* Wo   = (const float*)d_in[11];
    const float* bo   = (const float*)d_in[12];
    const float* fbW  = (const float*)d_in[13];
    const float* fbb  = (const float*)d_in[14];
    float* out = (float*)d_out;

    const size_t BD = (size_t)BATCH * DIM;

    __nv_bfloat16 *w_h, *w_l, *actA_h, *actA_l, *actB_h, *actB_l, *mc_h, *mc_l;
    float *bei_p, *b3_p, *wvo_f;
    cudaGetSymbolAddress((void**)&w_h, g_w_h);
    cudaGetSymbolAddress((void**)&w_l, g_w_l);
    cudaGetSymbolAddress((void**)&actA_h, g_actA_h);
    cudaGetSymbolAddress((void**)&actA_l, g_actA_l);
    cudaGetSymbolAddress((void**)&actB_h, g_actB_h);
    cudaGetSymbolAddress((void**)&actB_l, g_actB_l);
    cudaGetSymbolAddress((void**)&mc_h, g_mc_h);
    cudaGetSymbolAddress((void**)&mc_l, g_mc_l);
    cudaGetSymbolAddress((void**)&bei_p, g_bei);
    cudaGetSymbolAddress((void**)&b3_p, g_b3);
    cudaGetSymbolAddress((void**)&wvo_f, g_wvo_f);

    cudaFuncSetAttribute((const void*)bgemm<0, false>, cudaFuncAttributeMaxDynamicSharedMemorySize, SMEM_BYTES);
    cudaFuncSetAttribute((const void*)bgemm<0, true>,  cudaFuncAttributeMaxDynamicSharedMemorySize, SMEM_BYTES);
    cudaFuncSetAttribute((const void*)bgemm<2, true>,  cudaFuncAttributeMaxDynamicSharedMemorySize, SMEM_BYTES);
    cudaFuncSetAttribute((const void*)bgemm<1, false>, cudaFuncAttributeMaxDynamicSharedMemorySize, SMEM_BYTES);
    cudaFuncSetAttribute((const void*)bgemm<2, false>, cudaFuncAttributeMaxDynamicSharedMemorySize, SMEM_BYTES);
    cudaFuncSetAttribute((const void*)bgemm<3, false>, cudaFuncAttributeMaxDynamicSharedMemorySize, SMEM_BYTES);

    // side stream for weight-side precompute (fresh per call; few calls total, never replayed)
    cudaStream_t s2;
    cudaStreamCreateWithFlags(&s2, cudaStreamNonBlocking);
    cudaEvent_t evFork, evJoin;
    cudaEventCreateWithFlags(&evFork, cudaEventDisableTiming);
    cudaEventCreateWithFlags(&evJoin, cudaEventDisableTiming);

    // ---- packs needed by layer-0 wide GEMM (main stream) ----
    {
        size_t tw = (size_t)NLAY * DIM * 2 * DIM;
        pack_wei<<<(unsigned)((tw + 255) / 256), 256>>>(We, Wi);
        pack_split<<<(unsigned)(BD / 4 / 256), 256>>>(x, actA_h, actA_l, BD);
        pack_bias_kernel<<<(NLAY * 2 * DIM + 255) / 256, 256>>>(be, bi);
    }

    // ---- fork: weight-side precompute on s2, overlapped with layer-0 wide GEMM ----
    cudaEventRecord(evFork, 0);
    cudaStreamWaitEvent(s2, evFork, 0);
    {
        pack_split<<<(unsigned)(6 * SQ / 4 / 256), 256, 0, s2>>>(Wlat, w_h + OFF_LAT, w_l + OFF_LAT, 6 * SQ);
        pack_split<<<(unsigned)(6 * SQ / 4 / 256), 256, 0, s2>>>(Wv,   w_h + OFF_V,   w_l + OFF_V,   6 * SQ);
        pack_split<<<(unsigned)(6 * SQ / 4 / 256), 256, 0, s2>>>(Wo,   w_h + OFF_O,   w_l + OFF_O,   6 * SQ);
        pack_split<<<(unsigned)(5 * SQ / 4 / 256), 256, 0, s2>>>(fbW,  w_h + OFF_FB,  w_l + OFF_FB,  5 * SQ);
        bvo_kernel<<<dim3(4, NLAY), 256, 0, s2>>>(bv, Wo, bo);
        bgemm<2, true><<<dim3(8, 48), 256, SMEM_BYTES, s2>>>(
            w_h + OFF_V, w_l + OFF_V, w_h + OFF_O, w_l + OFF_O, nullptr,
            w_h + OFF_VO, w_l + OFF_VO, wvo_f, 1024, nullptr, nullptr);
        bgemm<0, true><<<dim3(8, 48), 256, SMEM_BYTES, s2>>>(
            w_h + OFF_LAT, w_l + OFF_LAT, w_h + OFF_VO, w_l + OFF_VO, nullptr,
            w_h + OFF_W3, w_l + OFF_W3, nullptr, 1024, nullptr, nullptr);
        b3_kernel<<<dim3(4, NLAY), 256, 0, s2>>>(blat);
    }
    cudaEventRecord(evJoin, s2);

    dim3 blk(256);
    dim3 grid_wide(2 * DIM / BN, BATCH / BM);
    dim3 grid_sq(DIM / BN, BATCH / BM);

    bool joined = false;
    for (int l = 0; l < NLAY; l++) {
        const size_t weOff = OFF_WEI + (size_t)l * 2048 * 1024;
        bgemm<1, false><<<grid_wide, blk, SMEM_BYTES>>>(
            actA_h, actA_l, w_h + weOff, w_l + weOff, bei_p + l * 2048,
            mc_h, mc_l, nullptr, 2048,
            Wl + (size_t)l * NMC * HW * HW, bl + (size_t)l * NMC * HW);
        if (!joined) {   // join before first use of W3/b3 (after wide-l0 is in flight)
            cudaStreamWaitEvent(0, evJoin, 0);
            joined = true;
        }
        bgemm<2, false><<<grid_sq, blk, SMEM_BYTES>>>(
            mc_h, mc_l, w_h + OFF_W3 + (size_t)l * SQ, w_l + OFF_W3 + (size_t)l * SQ,
            b3_p + l * DIM, actA_h, actA_l, out + (size_t)l * BD, 1024, nullptr, nullptr);
    }

    __nv_bfloat16 *fin_h = actA_h, *fin_l = actA_l, *fout_h = actB_h, *fout_l = actB_l;
    for (int i = 0; i < NLAY - 1; i++) {
        int idx = NLAY - 2 - i;
        const bool last = (i == NLAY - 2);
        bgemm<3, false><<<grid_sq, blk, SMEM_BYTES>>>(
            fin_h, fin_l, w_h + OFF_FB + (size_t)i * SQ, w_l + OFF_FB + (size_t)i * SQ,
            fbb + (size_t)i * DIM,
            last ? nullptr : fout_h, last ? nullptr : fout_l,
            out + (size_t)idx * BD, 1024, nullptr, nullptr);
        __nv_bfloat16* t;
        t = fin_h; fin_h = fout_h; fout_h = t;
        t = fin_l; fin_l = fout_l; fout_l = t;
    }
}

// round 14
// speedup vs baseline: 1.0548x; 1.0172x over previous
#include <cuda_runtime.h>
#include <cuda_bf16.h>
#include <cstdint>

#define BATCH 16384
#define DIM   1024
#define NLAY  6
#define NMC   64
#define HW    16

#define BM 128
#define BN 128
#define BK 32
#define AST 40
#define WST 136
#define NST 2
#define NTCH (DIM / BK)

#define STG_ELEMS_A (BM * AST)
#define STG_ELEMS_W (BK * WST)
#define SMEM_BYTES ((2 * NST * STG_ELEMS_A + 2 * NST * STG_ELEMS_W) * 2)  // 75776
#define TSTR 132
#define SWL_OFF (128 * TSTR)
#define SBL_OFF (SWL_OFF + 4 * 256)

// ---------------- static device scratch ----------------
#define SQ ((size_t)1048576)
#define OFF_WEI ((size_t)0)
#define OFF_LAT ((size_t)(6 * 2048 * 1024))
#define OFF_V   (OFF_LAT + 6 * SQ)
#define OFF_O   (OFF_V + 6 * SQ)
#define OFF_FB  (OFF_O + 6 * SQ)
#define OFF_VO  (OFF_FB + 5 * SQ)
#define OFF_W3  (OFF_VO + 6 * SQ)
#define WT_TOT  (OFF_W3 + 6 * SQ)

#define NSLOT 12

__device__ __nv_bfloat16 g_w_h[WT_TOT];
__device__ __nv_bfloat16 g_w_l[WT_TOT];
__device__ float g_bei[NLAY * 2 * DIM];
__device__ float g_bvo[NLAY * DIM];
__device__ float g_b3[NLAY * DIM];
__device__ float g_wvo_f[6 * SQ];
__device__ unsigned g_ctr[NSLOT][128];

__device__ __nv_bfloat16 g_actA_h[(size_t)BATCH * DIM];
__device__ __nv_bfloat16 g_actA_l[(size_t)BATCH * DIM];
__device__ __nv_bfloat16 g_actB_h[(size_t)BATCH * DIM];
__device__ __nv_bfloat16 g_actB_l[(size_t)BATCH * DIM];
__device__ __nv_bfloat16 g_mc_h[(size_t)BATCH * DIM];
__device__ __nv_bfloat16 g_mc_l[(size_t)BATCH * DIM];

// ---------------- helpers ----------------
__device__ __forceinline__ uint32_t cvt_bf16x2(float lo_elem, float hi_elem) {
    uint32_t r;
    asm("cvt.rn.bf16x2.f32 %0, %1, %2;" : "=r"(r) : "f"(hi_elem), "f"(lo_elem));
    return r;
}
__device__ __forceinline__ void split2(float a, float b, uint32_t& h, uint32_t& l) {
    h = cvt_bf16x2(a, b);
    float ha = __uint_as_float(h << 16);
    float hb = __uint_as_float(h & 0xffff0000u);
    l = cvt_bf16x2(a - ha, b - hb);
}
__device__ __forceinline__ void cp16(uint32_t dst, const void* src) {
    asm volatile("cp.async.cg.shared.global [%0], [%1], 16;" :: "r"(dst), "l"(src));
}
__device__ __forceinline__ void ldsm4(uint32_t addr, uint32_t& r0, uint32_t& r1,
                                      uint32_t& r2, uint32_t& r3) {
    asm volatile("ldmatrix.sync.aligned.m8n8.x4.shared.b16 {%0,%1,%2,%3}, [%4];"
                 : "=r"(r0), "=r"(r1), "=r"(r2), "=r"(r3) : "r"(addr));
}
__device__ __forceinline__ void ldsm4t(uint32_t addr, uint32_t& r0, uint32_t& r1,
                                       uint32_t& r2, uint32_t& r3) {
    asm volatile("ldmatrix.sync.aligned.m8n8.x4.trans.shared.b16 {%0,%1,%2,%3}, [%4];"
                 : "=r"(r0), "=r"(r1), "=r"(r2), "=r"(r3) : "r"(addr));
}
__device__ __forceinline__ void mma16816(float* c, const uint32_t* a, const uint32_t* b) {
    asm volatile(
        "mma.sync.aligned.m16n8k16.row.col.f32.bf16.bf16.f32 "
        "{%0,%1,%2,%3}, {%4,%5,%6,%7}, {%8,%9}, {%0,%1,%2,%3};"
        : "+f"(c[0]), "+f"(c[1]), "+f"(c[2]), "+f"(c[3])
        : "r"(a[0]), "r"(a[1]), "r"(a[2]), "r"(a[3]), "r"(b[0]), "r"(b[1]));
}

// ---------------- pack kernels ----------------
__global__ void zero_ctr_kernel() {
    int i = threadIdx.x;
    unsigned* p = &g_ctr[0][0];
    for (; i < NSLOT * 128; i += 256) p[i] = 0u;
}

__global__ void pack_wei(const float* __restrict__ We, const float* __restrict__ Wi) {
    size_t i = (size_t)blockIdx.x * blockDim.x + threadIdx.x;
    const size_t total = (size_t)NLAY * DIM * 2 * DIM;
    if (i >= total) return;
    int l = (int)(i / ((size_t)DIM * 2 * DIM));
    size_t r = i % ((size_t)DIM * 2 * DIM);
    int k = (int)(r / (2 * DIM));
    int n = (int)(r % (2 * DIM));
    int mc = n >> 5, rr = n & 31;
    const float* src;
    int h;
    if (rr < 16) { src = We; h = rr; } else { src = Wi; h = rr - 16; }
    float v = src[(((size_t)l * NMC + mc) * DIM + k) * HW + h];
    __nv_bfloat16 hb = __float2bfloat16(v);
    g_w_h[OFF_WEI + i] = hb;
    g_w_l[OFF_WEI + i] = __float2bfloat16(v - __bfloat162float(hb));
}

__global__ void pack_split(const float* __restrict__ src, __nv_bfloat16* __restrict__ dh,
                           __nv_bfloat16* __restrict__ dl, size_t total) {
    size_t i = ((size_t)blockIdx.x * blockDim.x + threadIdx.x) * 4;
    if (i >= total) return;
    float4 v = *(const float4*)(src + i);
    uint32_t h0, l0, h1, l1;
    split2(v.x, v.y, h0, l0);
    split2(v.z, v.w, h1, l1);
    *(uint2*)(dh + i) = make_uint2(h0, h1);
    *(uint2*)(dl + i) = make_uint2(l0, l1);
}

__global__ void pack_bias_kernel(const float* __restrict__ be, const float* __restrict__ bi) {
    int i = blockIdx.x * blockDim.x + threadIdx.x;
    if (i >= NLAY * 2 * DIM) return;
    int l = i / (2 * DIM);
    int n = i % (2 * DIM);
    int mc = n >> 5, rr = n & 31;
    g_bei[i] = (rr < 16) ? be[l * DIM + mc * HW + rr] : bi[l * DIM + mc * HW + (rr - 16)];
}

__global__ void bvo_kernel(const float* __restrict__ bv, const float* __restrict__ Wo,
                           const float* __restrict__ bo) {
    int l = blockIdx.y;
    int n = blockIdx.x * 256 + threadIdx.x;
    const float* w = Wo + (size_t)l * SQ + n;
    const float* b = bv + l * DIM;
    float s = bo[l * DIM + n];
    for (int k = 0; k < DIM; k++) s += b[k] * w[(size_t)k * DIM];
    g_bvo[l * DIM + n] = s;
}

__global__ void b3_kernel(const float* __restrict__ blat) {
    int l = blockIdx.y;
    int n = blockIdx.x * 256 + threadIdx.x;
    const float* w = g_wvo_f + (size_t)l * SQ + n;
    const float* b = blat + l * DIM;
    float s = g_bvo[l * DIM + n];
    for (int k = 0; k < DIM; k++) s += b[k] * w[(size_t)k * DIM];
    g_b3[l * DIM + n] = s;
}

// ---------------- GEMM core (bf16x3 HMMA, 2-stage cp.async) ----------------
// EPI 0: bias + split   1: fused minicolumn   2: fp32 out + split   3: fp32 += + split (skip if oHi null)
template <int EPI>
__device__ __forceinline__ void gemm_core(
    const __nv_bfloat16* __restrict__ Ah, const __nv_bfloat16* __restrict__ Al,
    const __nv_bfloat16* __restrict__ Wh, const __nv_bfloat16* __restrict__ Wl,
    const float* __restrict__ bias,
    __nv_bfloat16* __restrict__ oHi, __nv_bfloat16* __restrict__ oLo,
    float* __restrict__ oF, int N,
    const float* __restrict__ mcW, const float* __restrict__ mcB,
    int bx, int by, int waitSlot, int waitCount, int sigSlot) {
    extern __shared__ __nv_bfloat16 smem[];
    __nv_bfloat16* sAh = smem;
    __nv_bfloat16* sAl = sAh + NST * STG_ELEMS_A;
    __nv_bfloat16* sWh = sAl + NST * STG_ELEMS_A;
    __nv_bfloat16* sWl = sWh + NST * STG_ELEMS_W;
    const uint32_t sAh_u = (uint32_t)__cvta_generic_to_shared(sAh);
    const uint32_t sAl_u = (uint32_t)__cvta_generic_to_shared(sAl);
    const uint32_t sWh_u = (uint32_t)__cvta_generic_to_shared(sWh);
    const uint32_t sWl_u = (uint32_t)__cvta_generic_to_shared(sWl);

    const int tid = threadIdx.x;
    const int lane = tid & 31, wid = tid >> 5;
    const int wm = wid >> 2, wn = wid & 3;

    // row-block dependency wait (producers have smaller blockIdx -> dispatched earlier)
    if (waitSlot >= 0) {
        if (tid == 0) {
            volatile unsigned* p = &g_ctr[waitSlot][by];
            while (*p < (unsigned)waitCount) __nanosleep(200);
        }
        __syncthreads();
        __threadfence();
    }

    const char* pAh = (const char*)Ah + (size_t)by * BM * (DIM * 2);
    const char* pAl = (const char*)Al + (size_t)by * BM * (DIM * 2);
    const char* pWh = (const char*)Wh + (size_t)bx * BN * 2;
    const char* pWl = (const char*)Wl + (size_t)bx * BN * 2;
    const size_t wrow_b = (size_t)N * 2;

    uint32_t sAb[2], sWb[2];
    size_t gA[2], gW[2];
#pragma unroll
    for (int i = 0; i < 2; i++) {
        int idx = i * 256 + tid;
        int ar = idx >> 2, ac = idx & 3;
        gA[i] = (size_t)ar * (DIM * 2) + (size_t)ac * 16;
        sAb[i] = (uint32_t)(ar * AST + ac * 8) * 2;
        int wr = idx >> 4, wc = idx & 15;
        gW[i] = (size_t)wr * wrow_b + (size_t)wc * 16;
        sWb[i] = (uint32_t)(wr * WST + wc * 8) * 2;
    }

    auto load_async = [&](int c) {
        const int buf = c & 1;
        const uint32_t offA = (uint32_t)(buf * STG_ELEMS_A * 2);
        const uint32_t offW = (uint32_t)(buf * STG_ELEMS_W * 2);
        const size_t cbA = (size_t)c * (BK * 2);
        const size_t cbW = (size_t)c * BK * wrow_b;
#pragma unroll
        for (int i = 0; i < 2; i++) {
            cp16(sAh_u + offA + sAb[i], pAh + gA[i] + cbA);
            cp16(sAl_u + offA + sAb[i], pAl + gA[i] + cbA);
            cp16(sWh_u + offW + sWb[i], pWh + gW[i] + cbW);
            cp16(sWl_u + offW + sWb[i], pWl + gW[i] + cbW);
        }
        asm volatile("cp.async.commit_group;" ::: "memory");
    };

    float acc[4][4][4];
#pragma unroll
    for (int mt = 0; mt < 4; mt++)
#pragma unroll
        for (int nt = 0; nt < 4; nt++)
#pragma unroll
            for (int q = 0; q < 4; q++) acc[mt][nt][q] = 0.f;

    load_async(0);

    const int lrow = lane & 15;
    const int lcol8 = (lane >> 4) * 8;

    for (int t = 0; t < NTCH; t++) {
        asm volatile("cp.async.wait_group 0;" ::: "memory");
        __syncthreads();
        if (t + 1 < NTCH) load_async(t + 1);

        const int buf = t & 1;
        const uint32_t bA = (uint32_t)(buf * STG_ELEMS_A * 2);
        const uint32_t bW = (uint32_t)(buf * STG_ELEMS_W * 2);

#pragma unroll
        for (int ks = 0; ks < 2; ks++) {
            uint32_t ah[4][4], al[4][4], bh[4][2], bl[4][2];
#pragma unroll
            for (int mt = 0; mt < 4; mt++) {
                uint32_t off = bA + (uint32_t)((wm * 64 + mt * 16 + lrow) * AST +
                                               ks * 16 + lcol8) * 2;
                ldsm4(sAh_u + off, ah[mt][0], ah[mt][1], ah[mt][2], ah[mt][3]);
                ldsm4(sAl_u + off, al[mt][0], al[mt][1], al[mt][2], al[mt][3]);
            }
#pragma unroll
            for (int np = 0; np < 2; np++) {
                uint32_t off = bW + (uint32_t)((ks * 16 + lrow) * WST +
                                               wn * 32 + np * 16 + lcol8) * 2;
                uint32_t r0, r1, r2, r3;
                ldsm4t(sWh_u + off, r0, r1, r2, r3);
                bh[np * 2][0] = r0; bh[np * 2][1] = r1;
                bh[np * 2 + 1][0] = r2; bh[np * 2 + 1][1] = r3;
                ldsm4t(sWl_u + off, r0, r1, r2, r3);
                bl[np * 2][0] = r0; bl[np * 2][1] = r1;
                bl[np * 2 + 1][0] = r2; bl[np * 2 + 1][1] = r3;
            }
#pragma unroll
            for (int mt = 0; mt < 4; mt++)
#pragma unroll
                for (int nt = 0; nt < 4; nt++) mma16816(acc[mt][nt], ah[mt], bh[nt]);
#pragma unroll
            for (int mt = 0; mt < 4; mt++)
#pragma unroll
                for (int nt = 0; nt < 4; nt++) mma16816(acc[mt][nt], ah[mt], bl[nt]);
#pragma unroll
            for (int mt = 0; mt < 4; mt++)
#pragma unroll
                for (int nt = 0; nt < 4; nt++) mma16816(acc[mt][nt], al[mt], bh[nt]);
        }
    }
    __syncthreads();

    const int g = lane >> 2;
    const int tg = lane & 3;

    if (EPI == 1) {
        float* tileF = (float*)smem;
#pragma unroll
        for (int mt = 0; mt < 4; mt++) {
            const int rl = wm * 64 + mt * 16 + g;
#pragma unroll
            for (int nt = 0; nt < 4; nt++) {
                const int cl = wn * 32 + nt * 8 + tg * 2;
                float2 bv = *(const float2*)(bias + bx * BN + cl);
                tileF[rl * TSTR + cl]           = fmaxf(acc[mt][nt][0] + bv.x, 0.f);
                tileF[rl * TSTR + cl + 1]       = fmaxf(acc[mt][nt][1] + bv.y, 0.f);
                tileF[(rl + 8) * TSTR + cl]     = fmaxf(acc[mt][nt][2] + bv.x, 0.f);
                tileF[(rl + 8) * TSTR + cl + 1] = fmaxf(acc[mt][nt][3] + bv.y, 0.f);
            }
        }
        float* sWlF = tileF + SWL_OFF;
        float* sblF = tileF + SBL_OFF;
#pragma unroll
        for (int i = 0; i < 4; i++) sWlF[i * 256 + tid] = mcW[(size_t)(bx * 4) * 256 + i * 256 + tid];
        if (tid < 64) sblF[tid] = mcB[bx * 64 + tid];
        __syncthreads();

#pragma unroll
        for (int it = 0; it < 2; it++) {
            int w = it * 256 + tid;
            int j = w & 3, row = w >> 2;
            const float* tr = tileF + row * TSTR + j * 32;
            float inh[16];
#pragma unroll
            for (int h = 0; h < 16; h++) inh[h] = tr[16 + h];
            float o[16];
#pragma unroll
            for (int k = 0; k < 16; k++) {
                float lat = sblF[j * 16 + k];
#pragma unroll
                for (int h = 0; h < 16; h++) lat += inh[h] * sWlF[j * 256 + h * 16 + k];
                o[k] = fmaxf(tr[k] - lat, 0.f);
            }
            uint32_t hu[8], lu[8];
#pragma unroll
            for (int p = 0; p < 8; p++) split2(o[2 * p], o[2 * p + 1], hu[p], lu[p]);
            size_t oo = (size_t)(by * 128 + row) * DIM + (bx * 4 + j) * 16;
            *(uint4*)(oHi + oo)     = make_uint4(hu[0], hu[1], hu[2], hu[3]);
            *(uint4*)(oHi + oo + 8) = make_uint4(hu[4], hu[5], hu[6], hu[7]);
            *(uint4*)(oLo + oo)     = make_uint4(lu[0], lu[1], lu[2], lu[3]);
            *(uint4*)(oLo + oo + 8) = make_uint4(lu[4], lu[5], lu[6], lu[7]);
        }
    } else {
        const bool do_split = (EPI != 3) || (oHi != nullptr);
#pragma unroll
        for (int mt = 0; mt < 4; mt++) {
            const int r0 = by * BM + wm * 64 + mt * 16 + g;
#pragma unroll
            for (int nt = 0; nt < 4; nt++) {
                const int col = bx * BN + wn * 32 + nt * 8 + tg * 2;
                float2 bv = bias ? *(const float2*)(bias + col) : make_float2(0.f, 0.f);
                float2 v0, v1;
                v0.x = acc[mt][nt][0] + bv.x;  v0.y = acc[mt][nt][1] + bv.y;
                v1.x = acc[mt][nt][2] + bv.x;  v1.y = acc[mt][nt][3] + bv.y;
                if (EPI >= 2) {
                    float* p0 = oF + (size_t)r0 * N + col;
                    float* p1 = oF + (size_t)(r0 + 8) * N + col;
                    if (EPI == 3) {
                        float2 o0 = *(const float2*)p0;
                        float2 o1 = *(const float2*)p1;
                        v0.x += o0.x; v0.y += o0.y; v1.x += o1.x; v1.y += o1.y;
                    }
                    *(float2*)p0 = v0;
                    *(float2*)p1 = v1;
                }
                if (do_split) {
                    uint32_t h0, l0, h1, l1;
                    split2(v0.x, v0.y, h0, l0);
                    split2(v1.x, v1.y, h1, l1);
                    *(uint32_t*)(oHi + (size_t)r0 * N + col)       = h0;
                    *(uint32_t*)(oLo + (size_t)r0 * N + col)       = l0;
                    *(uint32_t*)(oHi + (size_t)(r0 + 8) * N + col) = h1;
                    *(uint32_t*)(oLo + (size_t)(r0 + 8) * N + col) = l1;
                }
            }
        }
    }

    if (sigSlot >= 0) {
        __threadfence();
        __syncthreads();
        if (tid == 0) atomicAdd(&g_ctr[sigSlot][by], 1u);
    }
}

// ---------------- standalone GEMM wrappers ----------------
template <int EPI, bool BATCH6>
__global__ __launch_bounds__(256, 2)
void bgemm(const __nv_bfloat16* __restrict__ Ah, const __nv_bfloat16* __restrict__ Al,
           const __nv_bfloat16* __restrict__ Wh, const __nv_bfloat16* __restrict__ Wl,
           const float* __restrict__ bias,
           __nv_bfloat16* __restrict__ oHi, __nv_bfloat16* __restrict__ oLo,
           float* __restrict__ oF, int N,
           const float* __restrict__ mcW, const float* __restrict__ mcB) {
    if (BATCH6) {
        size_t ws = (size_t)(blockIdx.y >> 3) * SQ;
        Wh += ws; Wl += ws;
    }
    gemm_core<EPI>(Ah, Al, Wh, Wl, bias, oHi, oLo, oF, N, mcW, mcB,
                   blockIdx.x, blockIdx.y, -1, 0, -1);
}

// ---------------- fused [W3(l) -> wide(l+1)] launch (1D grid 3072) ----------------
__global__ __launch_bounds__(256, 2)
void fused_kernel(int l,
                  __nv_bfloat16* __restrict__ w_h, __nv_bfloat16* __restrict__ w_l,
                  __nv_bfloat16* __restrict__ actA_h, __nv_bfloat16* __restrict__ actA_l,
                  __nv_bfloat16* __restrict__ mc_h, __nv_bfloat16* __restrict__ mc_l,
                  const float* __restrict__ b3, const float* __restrict__ bei,
                  float* __restrict__ out,
                  const float* __restrict__ Wl_mc, const float* __restrict__ bl_mc) {
    const int bid = blockIdx.x;
    if (bid < 1024) {
        // phase A: W3(l): attended = mc @ W3 + b3 -> out[l] fp32 + actA split; signal slot l
        int bx = bid & 7, by = bid >> 3;
        gemm_core<2>(mc_h, mc_l,
                     w_h + OFF_W3 + (size_t)l * SQ, w_l + OFF_W3 + (size_t)l * SQ,
                     b3 + l * DIM, actA_h, actA_l,
                     out + (size_t)l * BATCH * DIM, 1024, nullptr, nullptr,
                     bx, by, -1, 0, l);
    } else {
        // phase B: wide(l+1): exc|inh GEMM + minicolumn -> mc; wait slot l (count 8)
        int t = bid - 1024;
        int bx = t & 15, by = t >> 4;
        int lw = l + 1;
        gemm_core<1>(actA_h, actA_l,
                     w_h + OFF_WEI + (size_t)lw * 2048 * 1024,
                     w_l + OFF_WEI + (size_t)lw * 2048 * 1024,
                     bei + lw * 2048, mc_h, mc_l, nullptr, 2048,
                     Wl_mc + (size_t)lw * NMC * HW * HW, bl_mc + (size_t)lw * NMC * HW,
                     bx, by, l, 8, -1);
    }
}

// ---------------- feedback mega-launch: W3(5) + 5 feedback GEMMs (1D grid 6144) ----------------
__global__ __launch_bounds__(256, 2)
void fbmega_kernel(__nv_bfloat16* __restrict__ w_h, __nv_bfloat16* __restrict__ w_l,
                   __nv_bfloat16* __restrict__ actA_h, __nv_bfloat16* __restrict__ actA_l,
                   __nv_bfloat16* __restrict__ actB_h, __nv_bfloat16* __restrict__ actB_l,
                   __nv_bfloat16* __restrict__ mc_h, __nv_bfloat16* __restrict__ mc_l,
                   const float* __restrict__ b3, const float* __restrict__ fbb,
                   float* __restrict__ out) {
    const int bid = blockIdx.x;
    const int p = bid >> 10;
    const int t = bid & 1023;
    const int bx = t & 7, by = t >> 3;
    const size_t BD = (size_t)BATCH * DIM;

    if (p == 0) {
        // W3(5): mc @ W3 -> out[5] + actA split; signal slot 5
        gemm_core<2>(mc_h, mc_l,
                     w_h + OFF_W3 + (size_t)5 * SQ, w_l + OFF_W3 + (size_t)5 * SQ,
                     b3 + 5 * DIM, actA_h, actA_l, out + 5 * BD, 1024, nullptr, nullptr,
                     bx, by, -1, 0, 5);
    } else {
        const int i = p - 1;           // feedback index 0..4
        const int idx = 4 - i;
        const bool last = (i == 4);
        __nv_bfloat16 *fin_h, *fin_l, *fout_h, *fout_l;
        if ((i & 1) == 0) { fin_h = actA_h; fin_l = actA_l; fout_h = actB_h; fout_l = actB_l; }
        else              { fin_h = actB_h; fin_l = actB_l; fout_h = actA_h; fout_l = actA_l; }
        gemm_core<3>(fin_h, fin_l,
                     w_h + OFF_FB + (size_t)i * SQ, w_l + OFF_FB + (size_t)i * SQ,
                     fbb + i * DIM,
                     last ? nullptr : fout_h, last ? nullptr : fout_l,
                     out + (size_t)idx * BD, 1024, nullptr, nullptr,
                     bx, by, 4 + p, 8, last ? -1 : (5 + p));
    }
}

// ---------------- driver ----------------
extern "C" void kernel_launch(void* const* d_in, const int* in_sizes, int n_in,
                              void* d_out, int out_size) {
    const float* x    = (const float*)d_in[0];
    const float* We   = (const float*)d_in[1];
    const float* be   = (const float*)d_in[2];
    const float* Wi   = (const float*)d_in[3];
    const float* bi   = (const float*)d_in[4];
    const float* Wl   = (const float*)d_in[5];
    const float* bl   = (const float*)d_in[6];
    const float* Wlat = (const float*)d_in[7];
    const float* blat = (const float*)d_in[8];
    const float* Wv   = (const float*)d_in[9];
    const float* bv   = (const float*)d_in[10];
    const float* Wo   = (const float*)d_in[11];
    const float* bo   = (const float*)d_in[12];
    const float* fbW  = (const float*)d_in[13];
    const float* fbb  = (const float*)d_in[14];
    float* out = (float*)d_out;

    const size_t BD = (size_t)BATCH * DIM;

    __nv_bfloat16 *w_h, *w_l, *actA_h, *actA_l, *actB_h, *actB_l, *mc_h, *mc_l;
    float *bei_p, *b3_p, *wvo_f;
    cudaGetSymbolAddress((void**)&w_h, g_w_h);
    cudaGetSymbolAddress((void**)&w_l, g_w_l);
    cudaGetSymbolAddress((void**)&actA_h, g_actA_h);
    cudaGetSymbolAddress((void**)&actA_l, g_actA_l);
    cudaGetSymbolAddress((void**)&actB_h, g_actB_h);
    cudaGetSymbolAddress((void**)&actB_l, g_actB_l);
    cudaGetSymbolAddress((void**)&mc_h, g_mc_h);
    cudaGetSymbolAddress((void**)&mc_l, g_mc_l);
    cudaGetSymbolAddress((void**)&bei_p, g_bei);
    cudaGetSymbolAddress((void**)&b3_p, g_b3);
    cudaGetSymbolAddress((void**)&wvo_f, g_wvo_f);

    cudaFuncSetAttribute((const void*)bgemm<0, true>,  cudaFuncAttributeMaxDynamicSharedMemorySize, SMEM_BYTES);
    cudaFuncSetAttribute((const void*)bgemm<2, true>,  cudaFuncAttributeMaxDynamicSharedMemorySize, SMEM_BYTES);
    cudaFuncSetAttribute((const void*)bgemm<1, false>, cudaFuncAttributeMaxDynamicSharedMemorySize, SMEM_BYTES);
    cudaFuncSetAttribute((const void*)fused_kernel,    cudaFuncAttributeMaxDynamicSharedMemorySize, SMEM_BYTES);
    cudaFuncSetAttribute((const void*)fbmega_kernel,   cudaFuncAttributeMaxDynamicSharedMemorySize, SMEM_BYTES);

    cudaStream_t s2;
    cudaStreamCreateWithFlags(&s2, cudaStreamNonBlocking);
    cudaEvent_t evFork, evJoin;
    cudaEventCreateWithFlags(&evFork, cudaEventDisableTiming);
    cudaEventCreateWithFlags(&evJoin, cudaEventDisableTiming);

    // ---- main-stream setup needed by layer-0 wide GEMM ----
    zero_ctr_kernel<<<1, 256>>>();
    {
        size_t tw = (size_t)NLAY * DIM * 2 * DIM;
        pack_wei<<<(unsigned)((tw + 255) / 256), 256>>>(We, Wi);
        pack_split<<<(unsigned)(BD / 4 / 256), 256>>>(x, actA_h, actA_l, BD);
        pack_bias_kernel<<<(NLAY * 2 * DIM + 255) / 256, 256>>>(be, bi);
    }

    // ---- fork: weight-side precompute on s2, overlapped with layer-0 wide GEMM ----
    cudaEventRecord(evFork, 0);
    cudaStreamWaitEvent(s2, evFork, 0);
    {
        pack_split<<<(unsigned)(6 * SQ / 4 / 256), 256, 0, s2>>>(Wlat, w_h + OFF_LAT, w_l + OFF_LAT, 6 * SQ);
        pack_split<<<(unsigned)(6 * SQ / 4 / 256), 256, 0, s2>>>(Wv,   w_h + OFF_V,   w_l + OFF_V,   6 * SQ);
        pack_split<<<(unsigned)(6 * SQ / 4 / 256), 256, 0, s2>>>(Wo,   w_h + OFF_O,   w_l + OFF_O,   6 * SQ);
        pack_split<<<(unsigned)(5 * SQ / 4 / 256), 256, 0, s2>>>(fbW,  w_h + OFF_FB,  w_l + OFF_FB,  5 * SQ);
        bvo_kernel<<<dim3(4, NLAY), 256, 0, s2>>>(bv, Wo, bo);
        bgemm<2, true><<<dim3(8, 48), 256, SMEM_BYTES, s2>>>(
            w_h + OFF_V, w_l + OFF_V, w_h + OFF_O, w_l + OFF_O, nullptr,
            w_h + OFF_VO, w_l + OFF_VO, wvo_f, 1024, nullptr, nullptr);
        bgemm<0, true><<<dim3(8, 48), 256, SMEM_BYTES, s2>>>(
            w_h + OFF_LAT, w_l + OFF_LAT, w_h + OFF_VO, w_l + OFF_VO, nullptr,
            w_h + OFF_W3, w_l + OFF_W3, nullptr, 1024, nullptr, nullptr);
        b3_kernel<<<dim3(4, NLAY), 256, 0, s2>>>(blat);
    }
    cudaEventRecord(evJoin, s2);

    dim3 blk(256);
    dim3 grid_wide(2 * DIM / BN, BATCH / BM);

    // wide(0): standalone (reads only pack outputs)
    bgemm<1, false><<<grid_wide, blk, SMEM_BYTES>>>(
        actA_h, actA_l, w_h + OFF_WEI, w_l + OFF_WEI, bei_p,
        mc_h, mc_l, nullptr, 2048, Wl, bl);

    // join before anything that needs W3 weights / b3
    cudaStreamWaitEvent(0, evJoin, 0);

    // fused [W3(l), wide(l+1)] for l = 0..4
    for (int l = 0; l < 5; l++) {
        fused_kernel<<<3072, blk, SMEM_BYTES>>>(
            l, w_h, w_l, actA_h, actA_l, mc_h, mc_l, b3_p, bei_p, out, Wl, bl);
    }

    // W3(5) + feedback chain in one mega-launch
    fbmega_kernel<<<6144, blk, SMEM_BYTES>>>(
        w_h, w_l, actA_h, actA_l, actB_h, actB_l, mc_h, mc_l, b3_p, fbb, out);
}

// round 15
// speedup vs baseline: 1.0808x; 1.0247x over previous
#include <cuda_runtime.h>
#include <cuda_bf16.h>
#include <cstdint>

#define BATCH 16384
#define DIM   1024
#define NLAY  6
#define NMC   64
#define HW    16

#define BM 128
#define BN 128
#define BK 32
#define AST 40
#define WST 136
#define NST 2
#define NTCH (DIM / BK)

#define STG_ELEMS_A (BM * AST)
#define STG_ELEMS_W (BK * WST)
#define SMEM_BYTES ((2 * NST * STG_ELEMS_A + 2 * NST * STG_ELEMS_W) * 2)  // 75776
#define TSTR 132
#define SWL_OFF (128 * TSTR)
#define SBL_OFF (SWL_OFF + 4 * 256)

// ---------------- static device scratch ----------------
#define SQ ((size_t)1048576)
#define OFF_WEI ((size_t)0)
#define OFF_LAT ((size_t)(6 * 2048 * 1024))
#define OFF_V   (OFF_LAT + 6 * SQ)
#define OFF_O   (OFF_V + 6 * SQ)
#define OFF_FB  (OFF_O + 6 * SQ)
#define OFF_VO  (OFF_FB + 5 * SQ)
#define OFF_W3  (OFF_VO + 6 * SQ)
#define WT_TOT  (OFF_W3 + 6 * SQ)

#define NSLOT 16   // 0..5: W3(l), 6..10: wide(l) l=1..5, 11..14: fb(i) i=0..3

__device__ __nv_bfloat16 g_w_h[WT_TOT];
__device__ __nv_bfloat16 g_w_l[WT_TOT];
__device__ float g_bei[NLAY * 2 * DIM];
__device__ float g_bvo[NLAY * DIM];
__device__ float g_b3[NLAY * DIM];
__device__ float g_wvo_f[6 * SQ];
__device__ unsigned g_ctr[NSLOT][128];

__device__ __nv_bfloat16 g_actA_h[(size_t)BATCH * DIM];
__device__ __nv_bfloat16 g_actA_l[(size_t)BATCH * DIM];
__device__ __nv_bfloat16 g_actB_h[(size_t)BATCH * DIM];
__device__ __nv_bfloat16 g_actB_l[(size_t)BATCH * DIM];
__device__ __nv_bfloat16 g_mc_h[(size_t)BATCH * DIM];
__device__ __nv_bfloat16 g_mc_l[(size_t)BATCH * DIM];

// ---------------- helpers ----------------
__device__ __forceinline__ uint32_t cvt_bf16x2(float lo_elem, float hi_elem) {
    uint32_t r;
    asm("cvt.rn.bf16x2.f32 %0, %1, %2;" : "=r"(r) : "f"(hi_elem), "f"(lo_elem));
    return r;
}
__device__ __forceinline__ void split2(float a, float b, uint32_t& h, uint32_t& l) {
    h = cvt_bf16x2(a, b);
    float ha = __uint_as_float(h << 16);
    float hb = __uint_as_float(h & 0xffff0000u);
    l = cvt_bf16x2(a - ha, b - hb);
}
__device__ __forceinline__ void cp16(uint32_t dst, const void* src) {
    asm volatile("cp.async.cg.shared.global [%0], [%1], 16;" :: "r"(dst), "l"(src));
}
__device__ __forceinline__ void ldsm4(uint32_t addr, uint32_t& r0, uint32_t& r1,
                                      uint32_t& r2, uint32_t& r3) {
    asm volatile("ldmatrix.sync.aligned.m8n8.x4.shared.b16 {%0,%1,%2,%3}, [%4];"
                 : "=r"(r0), "=r"(r1), "=r"(r2), "=r"(r3) : "r"(addr));
}
__device__ __forceinline__ void ldsm4t(uint32_t addr, uint32_t& r0, uint32_t& r1,
                                       uint32_t& r2, uint32_t& r3) {
    asm volatile("ldmatrix.sync.aligned.m8n8.x4.trans.shared.b16 {%0,%1,%2,%3}, [%4];"
                 : "=r"(r0), "=r"(r1), "=r"(r2), "=r"(r3) : "r"(addr));
}
__device__ __forceinline__ void mma16816(float* c, const uint32_t* a, const uint32_t* b) {
    asm volatile(
        "mma.sync.aligned.m16n8k16.row.col.f32.bf16.bf16.f32 "
        "{%0,%1,%2,%3}, {%4,%5,%6,%7}, {%8,%9}, {%0,%1,%2,%3};"
        : "+f"(c[0]), "+f"(c[1]), "+f"(c[2]), "+f"(c[3])
        : "r"(a[0]), "r"(a[1]), "r"(a[2]), "r"(a[3]), "r"(b[0]), "r"(b[1]));
}

// ---------------- pack kernels ----------------
__global__ void zero_ctr_kernel() {
    int i = threadIdx.x;
    unsigned* p = &g_ctr[0][0];
    for (; i < NSLOT * 128; i += 256) p[i] = 0u;
}

__global__ void pack_wei(const float* __restrict__ We, const float* __restrict__ Wi) {
    size_t i = (size_t)blockIdx.x * blockDim.x + threadIdx.x;
    const size_t total = (size_t)NLAY * DIM * 2 * DIM;
    if (i >= total) return;
    int l = (int)(i / ((size_t)DIM * 2 * DIM));
    size_t r = i % ((size_t)DIM * 2 * DIM);
    int k = (int)(r / (2 * DIM));
    int n = (int)(r % (2 * DIM));
    int mc = n >> 5, rr = n & 31;
    const float* src;
    int h;
    if (rr < 16) { src = We; h = rr; } else { src = Wi; h = rr - 16; }
    float v = src[(((size_t)l * NMC + mc) * DIM + k) * HW + h];
    __nv_bfloat16 hb = __float2bfloat16(v);
    g_w_h[OFF_WEI + i] = hb;
    g_w_l[OFF_WEI + i] = __float2bfloat16(v - __bfloat162float(hb));
}

__global__ void pack_split(const float* __restrict__ src, __nv_bfloat16* __restrict__ dh,
                           __nv_bfloat16* __restrict__ dl, size_t total) {
    size_t i = ((size_t)blockIdx.x * blockDim.x + threadIdx.x) * 4;
    if (i >= total) return;
    float4 v = *(const float4*)(src + i);
    uint32_t h0, l0, h1, l1;
    split2(v.x, v.y, h0, l0);
    split2(v.z, v.w, h1, l1);
    *(uint2*)(dh + i) = make_uint2(h0, h1);
    *(uint2*)(dl + i) = make_uint2(l0, l1);
}

__global__ void pack_bias_kernel(const float* __restrict__ be, const float* __restrict__ bi) {
    int i = blockIdx.x * blockDim.x + threadIdx.x;
    if (i >= NLAY * 2 * DIM) return;
    int l = i / (2 * DIM);
    int n = i % (2 * DIM);
    int mc = n >> 5, rr = n & 31;
    g_bei[i] = (rr < 16) ? be[l * DIM + mc * HW + rr] : bi[l * DIM + mc * HW + (rr - 16)];
}

__global__ void bvo_kernel(const float* __restrict__ bv, const float* __restrict__ Wo,
                           const float* __restrict__ bo) {
    int l = blockIdx.y;
    int n = blockIdx.x * 256 + threadIdx.x;
    const float* w = Wo + (size_t)l * SQ + n;
    const float* b = bv + l * DIM;
    float s = bo[l * DIM + n];
    for (int k = 0; k < DIM; k++) s += b[k] * w[(size_t)k * DIM];
    g_bvo[l * DIM + n] = s;
}

__global__ void b3_kernel(const float* __restrict__ blat) {
    int l = blockIdx.y;
    int n = blockIdx.x * 256 + threadIdx.x;
    const float* w = g_wvo_f + (size_t)l * SQ + n;
    const float* b = blat + l * DIM;
    float s = g_bvo[l * DIM + n];
    for (int k = 0; k < DIM; k++) s += b[k] * w[(size_t)k * DIM];
    g_b3[l * DIM + n] = s;
}

// ---------------- GEMM core (bf16x3 HMMA, 2-stage cp.async) ----------------
// EPI 0: bias + split   1: fused minicolumn   2: fp32 out + split   3: fp32 += + split (skip if oHi null)
template <int EPI>
__device__ __forceinline__ void gemm_core(
    const __nv_bfloat16* __restrict__ Ah, const __nv_bfloat16* __restrict__ Al,
    const __nv_bfloat16* __restrict__ Wh, const __nv_bfloat16* __restrict__ Wl,
    const float* __restrict__ bias,
    __nv_bfloat16* __restrict__ oHi, __nv_bfloat16* __restrict__ oLo,
    float* __restrict__ oF, int N,
    const float* __restrict__ mcW, const float* __restrict__ mcB,
    int bx, int by, int waitSlot, int waitCount, int sigSlot) {
    extern __shared__ __nv_bfloat16 smem[];
    __nv_bfloat16* sAh = smem;
    __nv_bfloat16* sAl = sAh + NST * STG_ELEMS_A;
    __nv_bfloat16* sWh = sAl + NST * STG_ELEMS_A;
    __nv_bfloat16* sWl = sWh + NST * STG_ELEMS_W;
    const uint32_t sAh_u = (uint32_t)__cvta_generic_to_shared(sAh);
    const uint32_t sAl_u = (uint32_t)__cvta_generic_to_shared(sAl);
    const uint32_t sWh_u = (uint32_t)__cvta_generic_to_shared(sWh);
    const uint32_t sWl_u = (uint32_t)__cvta_generic_to_shared(sWl);

    const int tid = threadIdx.x;
    const int lane = tid & 31, wid = tid >> 5;
    const int wm = wid >> 2, wn = wid & 3;

    if (waitSlot >= 0) {
        if (tid == 0) {
            volatile unsigned* p = &g_ctr[waitSlot][by];
            while (*p < (unsigned)waitCount) __nanosleep(200);
        }
        __syncthreads();
        __threadfence();
    }

    const char* pAh = (const char*)Ah + (size_t)by * BM * (DIM * 2);
    const char* pAl = (const char*)Al + (size_t)by * BM * (DIM * 2);
    const char* pWh = (const char*)Wh + (size_t)bx * BN * 2;
    const char* pWl = (const char*)Wl + (size_t)bx * BN * 2;
    const size_t wrow_b = (size_t)N * 2;

    uint32_t sAb[2], sWb[2];
    size_t gA[2], gW[2];
#pragma unroll
    for (int i = 0; i < 2; i++) {
        int idx = i * 256 + tid;
        int ar = idx >> 2, ac = idx & 3;
        gA[i] = (size_t)ar * (DIM * 2) + (size_t)ac * 16;
        sAb[i] = (uint32_t)(ar * AST + ac * 8) * 2;
        int wr = idx >> 4, wc = idx & 15;
        gW[i] = (size_t)wr * wrow_b + (size_t)wc * 16;
        sWb[i] = (uint32_t)(wr * WST + wc * 8) * 2;
    }

    auto load_async = [&](int c) {
        const int buf = c & 1;
        const uint32_t offA = (uint32_t)(buf * STG_ELEMS_A * 2);
        const uint32_t offW = (uint32_t)(buf * STG_ELEMS_W * 2);
        const size_t cbA = (size_t)c * (BK * 2);
        const size_t cbW = (size_t)c * BK * wrow_b;
#pragma unroll
        for (int i = 0; i < 2; i++) {
            cp16(sAh_u + offA + sAb[i], pAh + gA[i] + cbA);
            cp16(sAl_u + offA + sAb[i], pAl + gA[i] + cbA);
            cp16(sWh_u + offW + sWb[i], pWh + gW[i] + cbW);
            cp16(sWl_u + offW + sWb[i], pWl + gW[i] + cbW);
        }
        asm volatile("cp.async.commit_group;" ::: "memory");
    };

    float acc[4][4][4];
#pragma unroll
    for (int mt = 0; mt < 4; mt++)
#pragma unroll
        for (int nt = 0; nt < 4; nt++)
#pragma unroll
            for (int q = 0; q < 4; q++) acc[mt][nt][q] = 0.f;

    load_async(0);

    const int lrow = lane & 15;
    const int lcol8 = (lane >> 4) * 8;

    for (int t = 0; t < NTCH; t++) {
        asm volatile("cp.async.wait_group 0;" ::: "memory");
        __syncthreads();
        if (t + 1 < NTCH) load_async(t + 1);

        const int buf = t & 1;
        const uint32_t bA = (uint32_t)(buf * STG_ELEMS_A * 2);
        const uint32_t bW = (uint32_t)(buf * STG_ELEMS_W * 2);

#pragma unroll
        for (int ks = 0; ks < 2; ks++) {
            uint32_t ah[4][4], al[4][4], bh[4][2], bl[4][2];
#pragma unroll
            for (int mt = 0; mt < 4; mt++) {
                uint32_t off = bA + (uint32_t)((wm * 64 + mt * 16 + lrow) * AST +
                                               ks * 16 + lcol8) * 2;
                ldsm4(sAh_u + off, ah[mt][0], ah[mt][1], ah[mt][2], ah[mt][3]);
                ldsm4(sAl_u + off, al[mt][0], al[mt][1], al[mt][2], al[mt][3]);
            }
#pragma unroll
            for (int np = 0; np < 2; np++) {
                uint32_t off = bW + (uint32_t)((ks * 16 + lrow) * WST +
                                               wn * 32 + np * 16 + lcol8) * 2;
                uint32_t r0, r1, r2, r3;
                ldsm4t(sWh_u + off, r0, r1, r2, r3);
                bh[np * 2][0] = r0; bh[np * 2][1] = r1;
                bh[np * 2 + 1][0] = r2; bh[np * 2 + 1][1] = r3;
                ldsm4t(sWl_u + off, r0, r1, r2, r3);
                bl[np * 2][0] = r0; bl[np * 2][1] = r1;
                bl[np * 2 + 1][0] = r2; bl[np * 2 + 1][1] = r3;
            }
#pragma unroll
            for (int mt = 0; mt < 4; mt++)
#pragma unroll
                for (int nt = 0; nt < 4; nt++) mma16816(acc[mt][nt], ah[mt], bh[nt]);
#pragma unroll
            for (int mt = 0; mt < 4; mt++)
#pragma unroll
                for (int nt = 0; nt < 4; nt++) mma16816(acc[mt][nt], ah[mt], bl[nt]);
#pragma unroll
            for (int mt = 0; mt < 4; mt++)
#pragma unroll
                for (int nt = 0; nt < 4; nt++) mma16816(acc[mt][nt], al[mt], bh[nt]);
        }
    }
    __syncthreads();

    const int g = lane >> 2;
    const int tg = lane & 3;

    if (EPI == 1) {
        float* tileF = (float*)smem;
#pragma unroll
        for (int mt = 0; mt < 4; mt++) {
            const int rl = wm * 64 + mt * 16 + g;
#pragma unroll
            for (int nt = 0; nt < 4; nt++) {
                const int cl = wn * 32 + nt * 8 + tg * 2;
                float2 bv = *(const float2*)(bias + bx * BN + cl);
                tileF[rl * TSTR + cl]           = fmaxf(acc[mt][nt][0] + bv.x, 0.f);
                tileF[rl * TSTR + cl + 1]       = fmaxf(acc[mt][nt][1] + bv.y, 0.f);
                tileF[(rl + 8) * TSTR + cl]     = fmaxf(acc[mt][nt][2] + bv.x, 0.f);
                tileF[(rl + 8) * TSTR + cl + 1] = fmaxf(acc[mt][nt][3] + bv.y, 0.f);
            }
        }
        float* sWlF = tileF + SWL_OFF;
        float* sblF = tileF + SBL_OFF;
#pragma unroll
        for (int i = 0; i < 4; i++) sWlF[i * 256 + tid] = mcW[(size_t)(bx * 4) * 256 + i * 256 + tid];
        if (tid < 64) sblF[tid] = mcB[bx * 64 + tid];
        __syncthreads();

#pragma unroll
        for (int it = 0; it < 2; it++) {
            int w = it * 256 + tid;
            int j = w & 3, row = w >> 2;
            const float* tr = tileF + row * TSTR + j * 32;
            float inh[16];
#pragma unroll
            for (int h = 0; h < 16; h++) inh[h] = tr[16 + h];
            float o[16];
#pragma unroll
            for (int k = 0; k < 16; k++) {
                float lat = sblF[j * 16 + k];
#pragma unroll
                for (int h = 0; h < 16; h++) lat += inh[h] * sWlF[j * 256 + h * 16 + k];
                o[k] = fmaxf(tr[k] - lat, 0.f);
            }
            uint32_t hu[8], lu[8];
#pragma unroll
            for (int p = 0; p < 8; p++) split2(o[2 * p], o[2 * p + 1], hu[p], lu[p]);
            size_t oo = (size_t)(by * 128 + row) * DIM + (bx * 4 + j) * 16;
            *(uint4*)(oHi + oo)     = make_uint4(hu[0], hu[1], hu[2], hu[3]);
            *(uint4*)(oHi + oo + 8) = make_uint4(hu[4], hu[5], hu[6], hu[7]);
            *(uint4*)(oLo + oo)     = make_uint4(lu[0], lu[1], lu[2], lu[3]);
            *(uint4*)(oLo + oo + 8) = make_uint4(lu[4], lu[5], lu[6], lu[7]);
        }
    } else {
        const bool do_split = (EPI != 3) || (oHi != nullptr);
#pragma unroll
        for (int mt = 0; mt < 4; mt++) {
            const int r0 = by * BM + wm * 64 + mt * 16 + g;
#pragma unroll
            for (int nt = 0; nt < 4; nt++) {
                const int col = bx * BN + wn * 32 + nt * 8 + tg * 2;
                float2 bv = bias ? *(const float2*)(bias + col) : make_float2(0.f, 0.f);
                float2 v0, v1;
                v0.x = acc[mt][nt][0] + bv.x;  v0.y = acc[mt][nt][1] + bv.y;
                v1.x = acc[mt][nt][2] + bv.x;  v1.y = acc[mt][nt][3] + bv.y;
                if (EPI >= 2) {
                    float* p0 = oF + (size_t)r0 * N + col;
                    float* p1 = oF + (size_t)(r0 + 8) * N + col;
                    if (EPI == 3) {
                        float2 o0 = *(const float2*)p0;
                        float2 o1 = *(const float2*)p1;
                        v0.x += o0.x; v0.y += o0.y; v1.x += o1.x; v1.y += o1.y;
                    }
                    *(float2*)p0 = v0;
                    *(float2*)p1 = v1;
                }
                if (do_split) {
                    uint32_t h0, l0, h1, l1;
                    split2(v0.x, v0.y, h0, l0);
                    split2(v1.x, v1.y, h1, l1);
                    *(uint32_t*)(oHi + (size_t)r0 * N + col)       = h0;
                    *(uint32_t*)(oLo + (size_t)r0 * N + col)       = l0;
                    *(uint32_t*)(oHi + (size_t)(r0 + 8) * N + col) = h1;
                    *(uint32_t*)(oLo + (size_t)(r0 + 8) * N + col) = l1;
                }
            }
        }
    }

    if (sigSlot >= 0) {
        __threadfence();
        __syncthreads();
        if (tid == 0) atomicAdd(&g_ctr[sigSlot][by], 1u);
    }
}

// ---------------- standalone GEMM wrappers ----------------
template <int EPI, bool BATCH6>
__global__ __launch_bounds__(256, 2)
void bgemm(const __nv_bfloat16* __restrict__ Ah, const __nv_bfloat16* __restrict__ Al,
           const __nv_bfloat16* __restrict__ Wh, const __nv_bfloat16* __restrict__ Wl,
           const float* __restrict__ bias,
           __nv_bfloat16* __restrict__ oHi, __nv_bfloat16* __restrict__ oLo,
           float* __restrict__ oF, int N,
           const float* __restrict__ mcW, const float* __restrict__ mcB) {
    if (BATCH6) {
        size_t ws = (size_t)(blockIdx.y >> 3) * SQ;
        Wh += ws; Wl += ws;
    }
    gemm_core<EPI>(Ah, Al, Wh, Wl, bias, oHi, oLo, oF, N, mcW, mcB,
                   blockIdx.x, blockIdx.y, -1, 0, -1);
}

// ---------------- mega kernel: W3(0) .. W3(5) + wide(1..5) + fb(0..4), 21504 CTAs ----------------
// slots: W3(l) -> l (0..5), wide(l) -> 5+l (6..10), fb(i) -> 11+i (11..14)
__global__ __launch_bounds__(256, 2)
void mega_kernel(__nv_bfloat16* __restrict__ w_h, __nv_bfloat16* __restrict__ w_l,
                 __nv_bfloat16* __restrict__ actA_h, __nv_bfloat16* __restrict__ actA_l,
                 __nv_bfloat16* __restrict__ actB_h, __nv_bfloat16* __restrict__ actB_l,
                 __nv_bfloat16* __restrict__ mc_h, __nv_bfloat16* __restrict__ mc_l,
                 const float* __restrict__ b3, const float* __restrict__ bei,
                 const float* __restrict__ fbb, float* __restrict__ out,
                 const float* __restrict__ Wl_mc, const float* __restrict__ bl_mc) {
    const size_t BD = (size_t)BATCH * DIM;
    int bid = blockIdx.x;

    if (bid < 1024) {
        // W3(0): mc @ W3(0) -> out[0] + actA split (wide(0) done: prior launch)
        int bx = bid & 7, by = bid >> 3;
        gemm_core<2>(mc_h, mc_l, w_h + OFF_W3, w_l + OFF_W3, b3,
                     actA_h, actA_l, out, 1024, nullptr, nullptr,
                     bx, by, -1, 0, 0);
        return;
    }
    bid -= 1024;
    if (bid < 5 * 3072) {
        const int l = bid / 3072 + 1;       // 1..5
        int t = bid % 3072;
        if (t < 2048) {
            // wide(l): actA @ Wei(l) + minicolumn -> mc; wait W3(l-1), signal wide(l)
            int bx = t & 15, by = t >> 4;
            gemm_core<1>(actA_h, actA_l,
                         w_h + OFF_WEI + (size_t)l * 2048 * 1024,
                         w_l + OFF_WEI + (size_t)l * 2048 * 1024,
                         bei + l * 2048, mc_h, mc_l, nullptr, 2048,
                         Wl_mc + (size_t)l * NMC * HW * HW, bl_mc + (size_t)l * NMC * HW,
                         bx, by, l - 1, 8, 5 + l);
        } else {
            // W3(l): mc @ W3(l) -> out[l] + actA split; wait wide(l), signal W3(l)
            t -= 2048;
            int bx = t & 7, by = t >> 3;
            gemm_core<2>(mc_h, mc_l,
                         w_h + OFF_W3 + (size_t)l * SQ, w_l + OFF_W3 + (size_t)l * SQ,
                         b3 + l * DIM, actA_h, actA_l, out + (size_t)l * BD, 1024,
                         nullptr, nullptr, bx, by, 5 + l, 16, l);
        }
        return;
    }
    bid -= 5 * 3072;
    {
        const int i = bid >> 10;            // fb index 0..4
        const int t = bid & 1023;
        const int bx = t & 7, by = t >> 3;
        const int idx = 4 - i;
        const bool last = (i == 4);
        __nv_bfloat16 *fin_h, *fin_l, *fout_h, *fout_l;
        if ((i & 1) == 0) { fin_h = actA_h; fin_l = actA_l; fout_h = actB_h; fout_l = actB_l; }
        else              { fin_h = actB_h; fin_l = actB_l; fout_h = actA_h; fout_l = actA_l; }
        gemm_core<3>(fin_h, fin_l,
                     w_h + OFF_FB + (size_t)i * SQ, w_l + OFF_FB + (size_t)i * SQ,
                     fbb + i * DIM,
                     last ? nullptr : fout_h, last ? nullptr : fout_l,
                     out + (size_t)idx * BD, 1024, nullptr, nullptr,
                     bx, by, (i == 0) ? 5 : (11 + i - 1), 8, last ? -1 : (11 + i));
    }
}

// ---------------- driver ----------------
extern "C" void kernel_launch(void* const* d_in, const int* in_sizes, int n_in,
                              void* d_out, int out_size) {
    const float* x    = (const float*)d_in[0];
    const float* We   = (const float*)d_in[1];
    const float* be   = (const float*)d_in[2];
    const float* Wi   = (const float*)d_in[3];
    const float* bi   = (const float*)d_in[4];
    const float* Wl   = (const float*)d_in[5];
    const float* bl   = (const float*)d_in[6];
    const float* Wlat = (const float*)d_in[7];
    const float* blat = (const float*)d_in[8];
    const float* Wv   = (const float*)d_in[9];
    const float* bv   = (const float*)d_in[10];
    const float* Wo   = (const float*)d_in[11];
    const float* bo   = (const float*)d_in[12];
    const float* fbW  = (const float*)d_in[13];
    const float* fbb  = (const float*)d_in[14];
    float* out = (float*)d_out;

    const size_t BD = (size_t)BATCH * DIM;

    __nv_bfloat16 *w_h, *w_l, *actA_h, *actA_l, *actB_h, *actB_l, *mc_h, *mc_l;
    float *bei_p, *b3_p, *wvo_f;
    cudaGetSymbolAddress((void**)&w_h, g_w_h);
    cudaGetSymbolAddress((void**)&w_l, g_w_l);
    cudaGetSymbolAddress((void**)&actA_h, g_actA_h);
    cudaGetSymbolAddress((void**)&actA_l, g_actA_l);
    cudaGetSymbolAddress((void**)&actB_h, g_actB_h);
    cudaGetSymbolAddress((void**)&actB_l, g_actB_l);
    cudaGetSymbolAddress((void**)&mc_h, g_mc_h);
    cudaGetSymbolAddress((void**)&mc_l, g_mc_l);
    cudaGetSymbolAddress((void**)&bei_p, g_bei);
    cudaGetSymbolAddress((void**)&b3_p, g_b3);
    cudaGetSymbolAddress((void**)&wvo_f, g_wvo_f);

    cudaFuncSetAttribute((const void*)bgemm<0, true>,  cudaFuncAttributeMaxDynamicSharedMemorySize, SMEM_BYTES);
    cudaFuncSetAttribute((const void*)bgemm<2, true>,  cudaFuncAttributeMaxDynamicSharedMemorySize, SMEM_BYTES);
    cudaFuncSetAttribute((const void*)bgemm<1, false>, cudaFuncAttributeMaxDynamicSharedMemorySize, SMEM_BYTES);
    cudaFuncSetAttribute((const void*)mega_kernel,     cudaFuncAttributeMaxDynamicSharedMemorySize, SMEM_BYTES);

    cudaStream_t s2;
    cudaStreamCreateWithFlags(&s2, cudaStreamNonBlocking);
    cudaEvent_t evFork, evJoin;
    cudaEventCreateWithFlags(&evFork, cudaEventDisableTiming);
    cudaEventCreateWithFlags(&evJoin, cudaEventDisableTiming);

    // ---- main-stream setup needed by layer-0 wide GEMM ----
    zero_ctr_kernel<<<1, 256>>>();
    {
        size_t tw = (size_t)NLAY * DIM * 2 * DIM;
        pack_wei<<<(unsigned)((tw + 255) / 256), 256>>>(We, Wi);
        pack_split<<<(unsigned)(BD / 4 / 256), 256>>>(x, actA_h, actA_l, BD);
        pack_bias_kernel<<<(NLAY * 2 * DIM + 255) / 256, 256>>>(be, bi);
    }

    // ---- fork: weight-side precompute on s2, overlapped with layer-0 wide GEMM ----
    cudaEventRecord(evFork, 0);
    cudaStreamWaitEvent(s2, evFork, 0);
    {
        pack_split<<<(unsigned)(6 * SQ / 4 / 256), 256, 0, s2>>>(Wlat, w_h + OFF_LAT, w_l + OFF_LAT, 6 * SQ);
        pack_split<<<(unsigned)(6 * SQ / 4 / 256), 256, 0, s2>>>(Wv,   w_h + OFF_V,   w_l + OFF_V,   6 * SQ);
        pack_split<<<(unsigned)(6 * SQ / 4 / 256), 256, 0, s2>>>(Wo,   w_h + OFF_O,   w_l + OFF_O,   6 * SQ);
        pack_split<<<(unsigned)(5 * SQ / 4 / 256), 256, 0, s2>>>(fbW,  w_h + OFF_FB,  w_l + OFF_FB,  5 * SQ);
        bvo_kernel<<<dim3(4, NLAY), 256, 0, s2>>>(bv, Wo, bo);
        bgemm<2, true><<<dim3(8, 48), 256, SMEM_BYTES, s2>>>(
            w_h + OFF_V, w_l + OFF_V, w_h + OFF_O, w_l + OFF_O, nullptr,
            w_h + OFF_VO, w_l + OFF_VO, wvo_f, 1024, nullptr, nullptr);
        bgemm<0, true><<<dim3(8, 48), 256, SMEM_BYTES, s2>>>(
            w_h + OFF_LAT, w_l + OFF_LAT, w_h + OFF_VO, w_l + OFF_VO, nullptr,
            w_h + OFF_W3, w_l + OFF_W3, nullptr, 1024, nullptr, nullptr);
        b3_kernel<<<dim3(4, NLAY), 256, 0, s2>>>(blat);
    }
    cudaEventRecord(evJoin, s2);

    dim3 blk(256);
    dim3 grid_wide(2 * DIM / BN, BATCH / BM);

    // wide(0): standalone launch (overlaps s2 precompute)
    bgemm<1, false><<<grid_wide, blk, SMEM_BYTES>>>(
        actA_h, actA_l, w_h + OFF_WEI, w_l + OFF_WEI, bei_p,
        mc_h, mc_l, nullptr, 2048, Wl, bl);

    // join, then the entire rest of the network in one flagged mega-launch
    cudaStreamWaitEvent(0, evJoin, 0);
    mega_kernel<<<21504, blk, SMEM_BYTES>>>(
        w_h, w_l, actA_h, actA_l, actB_h, actB_l, mc_h, mc_l,
        b3_p, bei_p, fbb, out, Wl, bl);
}

// round 16
// speedup vs baseline: 1.0815x; 1.0006x over previous
#include <cuda_runtime.h>
#include <cuda_bf16.h>
#include <cstdint>

#define BATCH 16384
#define DIM   1024
#define NLAY  6
#define NMC   64
#define HW    16

#define BM 128
#define BN 128
#define BK 32
#define AST 40
#define WST 136
#define NST 2
#define NTCH (DIM / BK)

#define STG_ELEMS_A (BM * AST)
#define STG_ELEMS_W (BK * WST)
#define SMEM_BYTES ((2 * NST * STG_ELEMS_A + 2 * NST * STG_ELEMS_W) * 2)  // 75776
#define TSTR 132
#define SWL_OFF (128 * TSTR)
#define SBL_OFF (SWL_OFF + 4 * 256)

// ---------------- static device scratch ----------------
#define SQ ((size_t)1048576)
#define OFF_WEI ((size_t)0)
#define OFF_LAT ((size_t)(6 * 2048 * 1024))
#define OFF_V   (OFF_LAT + 6 * SQ)
#define OFF_O   (OFF_V + 6 * SQ)
#define OFF_FB  (OFF_O + 6 * SQ)
#define OFF_VO  (OFF_FB + 5 * SQ)
#define OFF_W3  (OFF_VO + 6 * SQ)
#define WT_TOT  (OFF_W3 + 6 * SQ)

#define NSLOT 16   // 0..5: W3(l), 6..10: wide(l) l=1..5, 11..14: fb(i)

__device__ __nv_bfloat16 g_w_h[WT_TOT];
__device__ __nv_bfloat16 g_w_l[WT_TOT];
__device__ float g_bei[NLAY * 2 * DIM];
__device__ float g_bvo[NLAY * DIM];
__device__ float g_b3[NLAY * DIM];
__device__ float g_wvo_f[6 * SQ];
__device__ unsigned g_ctr[NSLOT][128];

__device__ __nv_bfloat16 g_actA_h[(size_t)BATCH * DIM];
__device__ __nv_bfloat16 g_actA_l[(size_t)BATCH * DIM];
__device__ __nv_bfloat16 g_actB_h[(size_t)BATCH * DIM];
__device__ __nv_bfloat16 g_actB_l[(size_t)BATCH * DIM];
__device__ __nv_bfloat16 g_mc_h[(size_t)BATCH * DIM];
__device__ __nv_bfloat16 g_mc_l[(size_t)BATCH * DIM];

// ---------------- helpers ----------------
__device__ __forceinline__ uint32_t cvt_bf16x2(float lo_elem, float hi_elem) {
    uint32_t r;
    asm("cvt.rn.bf16x2.f32 %0, %1, %2;" : "=r"(r) : "f"(hi_elem), "f"(lo_elem));
    return r;
}
__device__ __forceinline__ void split2(float a, float b, uint32_t& h, uint32_t& l) {
    h = cvt_bf16x2(a, b);
    float ha = __uint_as_float(h << 16);
    float hb = __uint_as_float(h & 0xffff0000u);
    l = cvt_bf16x2(a - ha, b - hb);
}
__device__ __forceinline__ void cp16(uint32_t dst, const void* src) {
    asm volatile("cp.async.cg.shared.global [%0], [%1], 16;" :: "r"(dst), "l"(src));
}
__device__ __forceinline__ void ldsm4(uint32_t addr, uint32_t& r0, uint32_t& r1,
                                      uint32_t& r2, uint32_t& r3) {
    asm volatile("ldmatrix.sync.aligned.m8n8.x4.shared.b16 {%0,%1,%2,%3}, [%4];"
                 : "=r"(r0), "=r"(r1), "=r"(r2), "=r"(r3) : "r"(addr));
}
__device__ __forceinline__ void ldsm4t(uint32_t addr, uint32_t& r0, uint32_t& r1,
                                       uint32_t& r2, uint32_t& r3) {
    asm volatile("ldmatrix.sync.aligned.m8n8.x4.trans.shared.b16 {%0,%1,%2,%3}, [%4];"
                 : "=r"(r0), "=r"(r1), "=r"(r2), "=r"(r3) : "r"(addr));
}
__device__ __forceinline__ void mma16816(float* c, const uint32_t* a, const uint32_t* b) {
    asm volatile(
        "mma.sync.aligned.m16n8k16.row.col.f32.bf16.bf16.f32 "
        "{%0,%1,%2,%3}, {%4,%5,%6,%7}, {%8,%9}, {%0,%1,%2,%3};"
        : "+f"(c[0]), "+f"(c[1]), "+f"(c[2]), "+f"(c[3])
        : "r"(a[0]), "r"(a[1]), "r"(a[2]), "r"(a[3]), "r"(b[0]), "r"(b[1]));
}

// ---------------- pack kernels ----------------
// packs layers [l0, l0+cnt) of fused interleaved Wei
__global__ void pack_wei(const float* __restrict__ We, const float* __restrict__ Wi,
                         int l0, int cnt) {
    size_t i = (size_t)blockIdx.x * blockDim.x + threadIdx.x;
    const size_t total = (size_t)cnt * DIM * 2 * DIM;
    if (i >= total) return;
    int l = l0 + (int)(i / ((size_t)DIM * 2 * DIM));
    size_t r = i % ((size_t)DIM * 2 * DIM);
    int k = (int)(r / (2 * DIM));
    int n = (int)(r % (2 * DIM));
    int mc = n >> 5, rr = n & 31;
    const float* src;
    int h;
    if (rr < 16) { src = We; h = rr; } else { src = Wi; h = rr - 16; }
    float v = src[(((size_t)l * NMC + mc) * DIM + k) * HW + h];
    __nv_bfloat16 hb = __float2bfloat16(v);
    size_t o = (size_t)l * DIM * 2 * DIM + r;
    g_w_h[OFF_WEI + o] = hb;
    g_w_l[OFF_WEI + o] = __float2bfloat16(v - __bfloat162float(hb));
}

__global__ void pack_split(const float* __restrict__ src, __nv_bfloat16* __restrict__ dh,
                           __nv_bfloat16* __restrict__ dl, size_t total) {
    size_t i = ((size_t)blockIdx.x * blockDim.x + threadIdx.x) * 4;
    if (i >= total) return;
    float4 v = *(const float4*)(src + i);
    uint32_t h0, l0, h1, l1;
    split2(v.x, v.y, h0, l0);
    split2(v.z, v.w, h1, l1);
    *(uint2*)(dh + i) = make_uint2(h0, h1);
    *(uint2*)(dl + i) = make_uint2(l0, l1);
}

// pack biases AND zero the dependency counters (block 0)
__global__ void pack_bias_kernel(const float* __restrict__ be, const float* __restrict__ bi) {
    if (blockIdx.x == 0) {
        unsigned* p = &g_ctr[0][0];
        for (int j = threadIdx.x; j < NSLOT * 128; j += 256) p[j] = 0u;
    }
    int i = blockIdx.x * blockDim.x + threadIdx.x;
    if (i >= NLAY * 2 * DIM) return;
    int l = i / (2 * DIM);
    int n = i % (2 * DIM);
    int mc = n >> 5, rr = n & 31;
    g_bei[i] = (rr < 16) ? be[l * DIM + mc * HW + rr] : bi[l * DIM + mc * HW + (rr - 16)];
}

__global__ void bvo_kernel(const float* __restrict__ bv, const float* __restrict__ Wo,
                           const float* __restrict__ bo) {
    int l = blockIdx.y;
    int n = blockIdx.x * 256 + threadIdx.x;
    const float* w = Wo + (size_t)l * SQ + n;
    const float* b = bv + l * DIM;
    float s = bo[l * DIM + n];
    for (int k = 0; k < DIM; k++) s += b[k] * w[(size_t)k * DIM];
    g_bvo[l * DIM + n] = s;
}

__global__ void b3_kernel(const float* __restrict__ blat) {
    int l = blockIdx.y;
    int n = blockIdx.x * 256 + threadIdx.x;
    const float* w = g_wvo_f + (size_t)l * SQ + n;
    const float* b = blat + l * DIM;
    float s = g_bvo[l * DIM + n];
    for (int k = 0; k < DIM; k++) s += b[k] * w[(size_t)k * DIM];
    g_b3[l * DIM + n] = s;
}

// ---------------- GEMM core (bf16x3 HMMA, 2-stage cp.async) ----------------
// EPI 0: bias + split   1: fused minicolumn   2: fp32 out + split   3: fp32 += + split (skip if oHi null)
template <int EPI>
__device__ __forceinline__ void gemm_core(
    const __nv_bfloat16* __restrict__ Ah, const __nv_bfloat16* __restrict__ Al,
    const __nv_bfloat16* __restrict__ Wh, const __nv_bfloat16* __restrict__ Wl,
    const float* __restrict__ bias,
    __nv_bfloat16* __restrict__ oHi, __nv_bfloat16* __restrict__ oLo,
    float* __restrict__ oF, int N,
    const float* __restrict__ mcW, const float* __restrict__ mcB,
    int bx, int by, int waitSlot, int waitCount, int sigSlot) {
    extern __shared__ __nv_bfloat16 smem[];
    __nv_bfloat16* sAh = smem;
    __nv_bfloat16* sAl = sAh + NST * STG_ELEMS_A;
    __nv_bfloat16* sWh = sAl + NST * STG_ELEMS_A;
    __nv_bfloat16* sWl = sWh + NST * STG_ELEMS_W;
    const uint32_t sAh_u = (uint32_t)__cvta_generic_to_shared(sAh);
    const uint32_t sAl_u = (uint32_t)__cvta_generic_to_shared(sAl);
    const uint32_t sWh_u = (uint32_t)__cvta_generic_to_shared(sWh);
    const uint32_t sWl_u = (uint32_t)__cvta_generic_to_shared(sWl);

    const int tid = threadIdx.x;
    const int lane = tid & 31, wid = tid >> 5;
    const int wm = wid >> 2, wn = wid & 3;

    if (waitSlot >= 0) {
        if (tid == 0) {
            volatile unsigned* p = &g_ctr[waitSlot][by];
            while (*p < (unsigned)waitCount) __nanosleep(200);
        }
        __syncthreads();
        __threadfence();
    }

    const char* pAh = (const char*)Ah + (size_t)by * BM * (DIM * 2);
    const char* pAl = (const char*)Al + (size_t)by * BM * (DIM * 2);
    const char* pWh = (const char*)Wh + (size_t)bx * BN * 2;
    const char* pWl = (const char*)Wl + (size_t)bx * BN * 2;
    const size_t wrow_b = (size_t)N * 2;

    uint32_t sAb[2], sWb[2];
    size_t gA[2], gW[2];
#pragma unroll
    for (int i = 0; i < 2; i++) {
        int idx = i * 256 + tid;
        int ar = idx >> 2, ac = idx & 3;
        gA[i] = (size_t)ar * (DIM * 2) + (size_t)ac * 16;
        sAb[i] = (uint32_t)(ar * AST + ac * 8) * 2;
        int wr = idx >> 4, wc = idx & 15;
        gW[i] = (size_t)wr * wrow_b + (size_t)wc * 16;
        sWb[i] = (uint32_t)(wr * WST + wc * 8) * 2;
    }

    auto load_async = [&](int c) {
        const int buf = c & 1;
        const uint32_t offA = (uint32_t)(buf * STG_ELEMS_A * 2);
        const uint32_t offW = (uint32_t)(buf * STG_ELEMS_W * 2);
        const size_t cbA = (size_t)c * (BK * 2);
        const size_t cbW = (size_t)c * BK * wrow_b;
#pragma unroll
        for (int i = 0; i < 2; i++) {
            cp16(sAh_u + offA + sAb[i], pAh + gA[i] + cbA);
            cp16(sAl_u + offA + sAb[i], pAl + gA[i] + cbA);
            cp16(sWh_u + offW + sWb[i], pWh + gW[i] + cbW);
            cp16(sWl_u + offW + sWb[i], pWl + gW[i] + cbW);
        }
        asm volatile("cp.async.commit_group;" ::: "memory");
    };

    float acc[4][4][4];
#pragma unroll
    for (int mt = 0; mt < 4; mt++)
#pragma unroll
        for (int nt = 0; nt < 4; nt++)
#pragma unroll
            for (int q = 0; q < 4; q++) acc[mt][nt][q] = 0.f;

    load_async(0);

    const int lrow = lane & 15;
    const int lcol8 = (lane >> 4) * 8;

    for (int t = 0; t < NTCH; t++) {
        asm volatile("cp.async.wait_group 0;" ::: "memory");
        __syncthreads();
        if (t + 1 < NTCH) load_async(t + 1);

        const int buf = t & 1;
        const uint32_t bA = (uint32_t)(buf * STG_ELEMS_A * 2);
        const uint32_t bW = (uint32_t)(buf * STG_ELEMS_W * 2);

#pragma unroll
        for (int ks = 0; ks < 2; ks++) {
            uint32_t ah[4][4], al[4][4], bh[4][2], bl[4][2];
#pragma unroll
            for (int mt = 0; mt < 4; mt++) {
                uint32_t off = bA + (uint32_t)((wm * 64 + mt * 16 + lrow) * AST +
                                               ks * 16 + lcol8) * 2;
                ldsm4(sAh_u + off, ah[mt][0], ah[mt][1], ah[mt][2], ah[mt][3]);
                ldsm4(sAl_u + off, al[mt][0], al[mt][1], al[mt][2], al[mt][3]);
            }
#pragma unroll
            for (int np = 0; np < 2; np++) {
                uint32_t off = bW + (uint32_t)((ks * 16 + lrow) * WST +
                                               wn * 32 + np * 16 + lcol8) * 2;
                uint32_t r0, r1, r2, r3;
                ldsm4t(sWh_u + off, r0, r1, r2, r3);
                bh[np * 2][0] = r0; bh[np * 2][1] = r1;
                bh[np * 2 + 1][0] = r2; bh[np * 2 + 1][1] = r3;
                ldsm4t(sWl_u + off, r0, r1, r2, r3);
                bl[np * 2][0] = r0; bl[np * 2][1] = r1;
                bl[np * 2 + 1][0] = r2; bl[np * 2 + 1][1] = r3;
            }
#pragma unroll
            for (int mt = 0; mt < 4; mt++)
#pragma unroll
                for (int nt = 0; nt < 4; nt++) mma16816(acc[mt][nt], ah[mt], bh[nt]);
#pragma unroll
            for (int mt = 0; mt < 4; mt++)
#pragma unroll
                for (int nt = 0; nt < 4; nt++) mma16816(acc[mt][nt], ah[mt], bl[nt]);
#pragma unroll
            for (int mt = 0; mt < 4; mt++)
#pragma unroll
                for (int nt = 0; nt < 4; nt++) mma16816(acc[mt][nt], al[mt], bh[nt]);
        }
    }
    __syncthreads();

    const int g = lane >> 2;
    const int tg = lane & 3;

    if (EPI == 1) {
        float* tileF = (float*)smem;
#pragma unroll
        for (int mt = 0; mt < 4; mt++) {
            const int rl = wm * 64 + mt * 16 + g;
#pragma unroll
            for (int nt = 0; nt < 4; nt++) {
                const int cl = wn * 32 + nt * 8 + tg * 2;
                float2 bv = *(const float2*)(bias + bx * BN + cl);
                tileF[rl * TSTR + cl]           = fmaxf(acc[mt][nt][0] + bv.x, 0.f);
                tileF[rl * TSTR + cl + 1]       = fmaxf(acc[mt][nt][1] + bv.y, 0.f);
                tileF[(rl + 8) * TSTR + cl]     = fmaxf(acc[mt][nt][2] + bv.x, 0.f);
                tileF[(rl + 8) * TSTR + cl + 1] = fmaxf(acc[mt][nt][3] + bv.y, 0.f);
            }
        }
        float* sWlF = tileF + SWL_OFF;
        float* sblF = tileF + SBL_OFF;
#pragma unroll
        for (int i = 0; i < 4; i++) sWlF[i * 256 + tid] = mcW[(size_t)(bx * 4) * 256 + i * 256 + tid];
        if (tid < 64) sblF[tid] = mcB[bx * 64 + tid];
        __syncthreads();

#pragma unroll
        for (int it = 0; it < 2; it++) {
            int w = it * 256 + tid;
            int j = w & 3, row = w >> 2;
            const float* tr = tileF + row * TSTR + j * 32;
            float inh[16];
#pragma unroll
            for (int h = 0; h < 16; h++) inh[h] = tr[16 + h];
            float o[16];
#pragma unroll
            for (int k = 0; k < 16; k++) {
                float lat = sblF[j * 16 + k];
#pragma unroll
                for (int h = 0; h < 16; h++) lat += inh[h] * sWlF[j * 256 + h * 16 + k];
                o[k] = fmaxf(tr[k] - lat, 0.f);
            }
            uint32_t hu[8], lu[8];
#pragma unroll
            for (int p = 0; p < 8; p++) split2(o[2 * p], o[2 * p + 1], hu[p], lu[p]);
            size_t oo = (size_t)(by * 128 + row) * DIM + (bx * 4 + j) * 16;
            *(uint4*)(oHi + oo)     = make_uint4(hu[0], hu[1], hu[2], hu[3]);
            *(uint4*)(oHi + oo + 8) = make_uint4(hu[4], hu[5], hu[6], hu[7]);
            *(uint4*)(oLo + oo)     = make_uint4(lu[0], lu[1], lu[2], lu[3]);
            *(uint4*)(oLo + oo + 8) = make_uint4(lu[4], lu[5], lu[6], lu[7]);
        }
    } else {
        const bool do_split = (EPI != 3) || (oHi != nullptr);
#pragma unroll
        for (int mt = 0; mt < 4; mt++) {
            const int r0 = by * BM + wm * 64 + mt * 16 + g;
#pragma unroll
            for (int nt = 0; nt < 4; nt++) {
                const int col = bx * BN + wn * 32 + nt * 8 + tg * 2;
                float2 bv = bias ? *(const float2*)(bias + col) : make_float2(0.f, 0.f);
                float2 v0, v1;
                v0.x = acc[mt][nt][0] + bv.x;  v0.y = acc[mt][nt][1] + bv.y;
                v1.x = acc[mt][nt][2] + bv.x;  v1.y = acc[mt][nt][3] + bv.y;
                if (EPI >= 2) {
                    float* p0 = oF + (size_t)r0 * N + col;
                    float* p1 = oF + (size_t)(r0 + 8) * N + col;
                    if (EPI == 3) {
                        float2 o0 = *(const float2*)p0;
                        float2 o1 = *(const float2*)p1;
                        v0.x += o0.x; v0.y += o0.y; v1.x += o1.x; v1.y += o1.y;
                    }
                    *(float2*)p0 = v0;
                    *(float2*)p1 = v1;
                }
                if (do_split) {
                    uint32_t h0, l0, h1, l1;
                    split2(v0.x, v0.y, h0, l0);
                    split2(v1.x, v1.y, h1, l1);
                    *(uint32_t*)(oHi + (size_t)r0 * N + col)       = h0;
                    *(uint32_t*)(oLo + (size_t)r0 * N + col)       = l0;
                    *(uint32_t*)(oHi + (size_t)(r0 + 8) * N + col) = h1;
                    *(uint32_t*)(oLo + (size_t)(r0 + 8) * N + col) = l1;
                }
            }
        }
    }

    if (sigSlot >= 0) {
        __threadfence();
        __syncthreads();
        if (tid == 0) atomicAdd(&g_ctr[sigSlot][by], 1u);
    }
}

// ---------------- standalone GEMM wrappers ----------------
template <int EPI, bool BATCH6>
__global__ __launch_bounds__(256, 2)
void bgemm(const __nv_bfloat16* __restrict__ Ah, const __nv_bfloat16* __restrict__ Al,
           const __nv_bfloat16* __restrict__ Wh, const __nv_bfloat16* __restrict__ Wl,
           const float* __restrict__ bias,
           __nv_bfloat16* __restrict__ oHi, __nv_bfloat16* __restrict__ oLo,
           float* __restrict__ oF, int N,
           const float* __restrict__ mcW, const float* __restrict__ mcB) {
    if (BATCH6) {
        size_t ws = (size_t)(blockIdx.y >> 3) * SQ;
        Wh += ws; Wl += ws;
    }
    gemm_core<EPI>(Ah, Al, Wh, Wl, bias, oHi, oLo, oF, N, mcW, mcB,
                   blockIdx.x, blockIdx.y, -1, 0, -1);
}

// ---------------- mega kernel: W3(0..5) + wide(1..5) + fb(0..4), 21504 CTAs ----------------
__global__ __launch_bounds__(256, 2)
void mega_kernel(__nv_bfloat16* __restrict__ w_h, __nv_bfloat16* __restrict__ w_l,
                 __nv_bfloat16* __restrict__ actA_h, __nv_bfloat16* __restrict__ actA_l,
                 __nv_bfloat16* __restrict__ actB_h, __nv_bfloat16* __restrict__ actB_l,
                 __nv_bfloat16* __restrict__ mc_h, __nv_bfloat16* __restrict__ mc_l,
                 const float* __restrict__ b3, const float* __restrict__ bei,
                 const float* __restrict__ fbb, float* __restrict__ out,
                 const float* __restrict__ Wl_mc, const float* __restrict__ bl_mc) {
    const size_t BD = (size_t)BATCH * DIM;
    int bid = blockIdx.x;

    if (bid < 1024) {
        int bx = bid & 7, by = bid >> 3;
        gemm_core<2>(mc_h, mc_l, w_h + OFF_W3, w_l + OFF_W3, b3,
                     actA_h, actA_l, out, 1024, nullptr, nullptr,
                     bx, by, -1, 0, 0);
        return;
    }
    bid -= 1024;
    if (bid < 5 * 3072) {
        const int l = bid / 3072 + 1;
        int t = bid % 3072;
        if (t < 2048) {
            int bx = t & 15, by = t >> 4;
            gemm_core<1>(actA_h, actA_l,
                         w_h + OFF_WEI + (size_t)l * 2048 * 1024,
                         w_l + OFF_WEI + (size_t)l * 2048 * 1024,
                         bei + l * 2048, mc_h, mc_l, nullptr, 2048,
                         Wl_mc + (size_t)l * NMC * HW * HW, bl_mc + (size_t)l * NMC * HW,
                         bx, by, l - 1, 8, 5 + l);
        } else {
            t -= 2048;
            int bx = t & 7, by = t >> 3;
            gemm_core<2>(mc_h, mc_l,
                         w_h + OFF_W3 + (size_t)l * SQ, w_l + OFF_W3 + (size_t)l * SQ,
                         b3 + l * DIM, actA_h, actA_l, out + (size_t)l * BD, 1024,
                         nullptr, nullptr, bx, by, 5 + l, 16, l);
        }
        return;
    }
    bid -= 5 * 3072;
    {
        const int i = bid >> 10;
        const int t = bid & 1023;
        const int bx = t & 7, by = t >> 3;
        const int idx = 4 - i;
        const bool last = (i == 4);
        __nv_bfloat16 *fin_h, *fin_l, *fout_h, *fout_l;
        if ((i & 1) == 0) { fin_h = actA_h; fin_l = actA_l; fout_h = actB_h; fout_l = actB_l; }
        else              { fin_h = actB_h; fin_l = actB_l; fout_h = actA_h; fout_l = actA_l; }
        gemm_core<3>(fin_h, fin_l,
                     w_h + OFF_FB + (size_t)i * SQ, w_l + OFF_FB + (size_t)i * SQ,
                     fbb + i * DIM,
                     last ? nullptr : fout_h, last ? nullptr : fout_l,
                     out + (size_t)idx * BD, 1024, nullptr, nullptr,
                     bx, by, (i == 0) ? 5 : (11 + i - 1), 8, last ? -1 : (11 + i));
    }
}

// ---------------- driver ----------------
extern "C" void kernel_launch(void* const* d_in, const int* in_sizes, int n_in,
                              void* d_out, int out_size) {
    const float* x    = (const float*)d_in[0];
    const float* We   = (const float*)d_in[1];
    const float* be   = (const float*)d_in[2];
    const float* Wi   = (const float*)d_in[3];
    const float* bi   = (const float*)d_in[4];
    const float* Wl   = (const float*)d_in[5];
    const float* bl   = (const float*)d_in[6];
    const float* Wlat = (const float*)d_in[7];
    const float* blat = (const float*)d_in[8];
    const float* Wv   = (const float*)d_in[9];
    const float* bv   = (const float*)d_in[10];
    const float* Wo   = (const float*)d_in[11];
    const float* bo   = (const float*)d_in[12];
    const float* fbW  = (const float*)d_in[13];
    const float* fbb  = (const float*)d_in[14];
    float* out = (float*)d_out;

    const size_t BD = (size_t)BATCH * DIM;

    __nv_bfloat16 *w_h, *w_l, *actA_h, *actA_l, *actB_h, *actB_l, *mc_h, *mc_l;
    float *bei_p, *b3_p, *wvo_f;
    cudaGetSymbolAddress((void**)&w_h, g_w_h);
    cudaGetSymbolAddress((void**)&w_l, g_w_l);
    cudaGetSymbolAddress((void**)&actA_h, g_actA_h);
    cudaGetSymbolAddress((void**)&actA_l, g_actA_l);
    cudaGetSymbolAddress((void**)&actB_h, g_actB_h);
    cudaGetSymbolAddress((void**)&actB_l, g_actB_l);
    cudaGetSymbolAddress((void**)&mc_h, g_mc_h);
    cudaGetSymbolAddress((void**)&mc_l, g_mc_l);
    cudaGetSymbolAddress((void**)&bei_p, g_bei);
    cudaGetSymbolAddress((void**)&b3_p, g_b3);
    cudaGetSymbolAddress((void**)&wvo_f, g_wvo_f);

    cudaFuncSetAttribute((const void*)bgemm<0, true>,  cudaFuncAttributeMaxDynamicSharedMemorySize, SMEM_BYTES);
    cudaFuncSetAttribute((const void*)bgemm<2, true>,  cudaFuncAttributeMaxDynamicSharedMemorySize, SMEM_BYTES);
    cudaFuncSetAttribute((const void*)bgemm<1, false>, cudaFuncAttributeMaxDynamicSharedMemorySize, SMEM_BYTES);
    cudaFuncSetAttribute((const void*)mega_kernel,     cudaFuncAttributeMaxDynamicSharedMemorySize, SMEM_BYTES);

    cudaStream_t s2;
    cudaStreamCreateWithFlags(&s2, cudaStreamNonBlocking);
    cudaEvent_t evFork, evJoin;
    cudaEventCreateWithFlags(&evFork, cudaEventDisableTiming);
    cudaEventCreateWithFlags(&evJoin, cudaEventDisableTiming);

    // ---- minimal main-stream prefix: only what wide(0) needs ----
    const size_t tw1 = (size_t)DIM * 2 * DIM;   // one layer of Wei
    pack_wei<<<(unsigned)((tw1 + 255) / 256), 256>>>(We, Wi, 0, 1);
    pack_split<<<(unsigned)(BD / 4 / 256), 256>>>(x, actA_h, actA_l, BD);
    pack_bias_kernel<<<(NLAY * 2 * DIM + 255) / 256, 256>>>(be, bi);  // also zeroes counters

    // ---- fork: everything else on s2, overlapped with wide(0) ----
    cudaEventRecord(evFork, 0);
    cudaStreamWaitEvent(s2, evFork, 0);
    {
        pack_wei<<<(unsigned)((5 * tw1 + 255) / 256), 256, 0, s2>>>(We, Wi, 1, 5);
        pack_split<<<(unsigned)(6 * SQ / 4 / 256), 256, 0, s2>>>(Wlat, w_h + OFF_LAT, w_l + OFF_LAT, 6 * SQ);
        pack_split<<<(unsigned)(6 * SQ / 4 / 256), 256, 0, s2>>>(Wv,   w_h + OFF_V,   w_l + OFF_V,   6 * SQ);
        pack_split<<<(unsigned)(6 * SQ / 4 / 256), 256, 0, s2>>>(Wo,   w_h + OFF_O,   w_l + OFF_O,   6 * SQ);
        pack_split<<<(unsigned)(5 * SQ / 4 / 256), 256, 0, s2>>>(fbW,  w_h + OFF_FB,  w_l + OFF_FB,  5 * SQ);
        bvo_kernel<<<dim3(4, NLAY), 256, 0, s2>>>(bv, Wo, bo);
        bgemm<2, true><<<dim3(8, 48), 256, SMEM_BYTES, s2>>>(
            w_h + OFF_V, w_l + OFF_V, w_h + OFF_O, w_l + OFF_O, nullptr,
            w_h + OFF_VO, w_l + OFF_VO, wvo_f, 1024, nullptr, nullptr);
        bgemm<0, true><<<dim3(8, 48), 256, SMEM_BYTES, s2>>>(
            w_h + OFF_LAT, w_l + OFF_LAT, w_h + OFF_VO, w_l + OFF_VO, nullptr,
            w_h + OFF_W3, w_l + OFF_W3, nullptr, 1024, nullptr, nullptr);
        b3_kernel<<<dim3(4, NLAY), 256, 0, s2>>>(blat);
    }
    cudaEventRecord(evJoin, s2);

    dim3 blk(256);
    dim3 grid_wide(2 * DIM / BN, BATCH / BM);

    // wide(0): standalone launch (overlaps s2 precompute)
    bgemm<1, false><<<grid_wide, blk, SMEM_BYTES>>>(
        actA_h, actA_l, w_h + OFF_WEI, w_l + OFF_WEI, bei_p,
        mc_h, mc_l, nullptr, 2048, Wl, bl);

    // join, then the entire rest of the network in one flagged mega-launch
    cudaStreamWaitEvent(0, evJoin, 0);
    mega_kernel<<<21504, blk, SMEM_BYTES>>>(
        w_h, w_l, actA_h, actA_l, actB_h, actB_l, mc_h, mc_l,
        b3_p, bei_p, fbb, out, Wl, bl);
}

// round 17
// speedup vs baseline: 1.1040x; 1.0208x over previous
#include <cuda_runtime.h>
#include <cuda_bf16.h>
#include <cstdint>

#define BATCH 16384
#define DIM   1024
#define NLAY  6
#define NMC   64
#define HW    16

#define BM 128
#define BN 128
#define BK 32
#define AST 40
#define WST 136
#define NST 2
#define NTCH (DIM / BK)

#define STG_ELEMS_A (BM * AST)
#define STG_ELEMS_W (BK * WST)
#define SMEM_BYTES ((2 * NST * STG_ELEMS_A + 2 * NST * STG_ELEMS_W) * 2)  // 75776
#define TSTR 132
#define SWL_OFF (128 * TSTR)
#define SBL_OFF (SWL_OFF + 4 * 256)

// ---------------- static device scratch ----------------
#define SQ ((size_t)1048576)
#define OFF_WEI ((size_t)0)
#define OFF_LAT ((size_t)(6 * 2048 * 1024))
#define OFF_V   (OFF_LAT + 6 * SQ)
#define OFF_O   (OFF_V + 6 * SQ)
#define OFF_FB  (OFF_O + 6 * SQ)
#define OFF_VO  (OFF_FB + 5 * SQ)
#define OFF_W3  (OFF_VO + 6 * SQ)
#define WT_TOT  (OFF_W3 + 6 * SQ)

#define NSLOT 16   // 0..5: W3(l), 6..10: wide(l) l=1..5, 11..14: fb(i)

__device__ __nv_bfloat16 g_w_h[WT_TOT];
__device__ __nv_bfloat16 g_w_l[WT_TOT];
__device__ float g_bei[NLAY * 2 * DIM];
__device__ float g_bvo[NLAY * DIM];
__device__ float g_b3[NLAY * DIM];
__device__ float g_wvo_f[6 * SQ];
__device__ unsigned g_ctr[NSLOT][128];

__device__ __nv_bfloat16 g_actA_h[(size_t)BATCH * DIM];
__device__ __nv_bfloat16 g_actA_l[(size_t)BATCH * DIM];
__device__ __nv_bfloat16 g_actB_h[(size_t)BATCH * DIM];
__device__ __nv_bfloat16 g_actB_l[(size_t)BATCH * DIM];
__device__ __nv_bfloat16 g_mc_h[(size_t)BATCH * DIM];
__device__ __nv_bfloat16 g_mc_l[(size_t)BATCH * DIM];

// ---------------- helpers ----------------
__device__ __forceinline__ uint32_t cvt_bf16x2(float lo_elem, float hi_elem) {
    uint32_t r;
    asm("cvt.rn.bf16x2.f32 %0, %1, %2;" : "=r"(r) : "f"(hi_elem), "f"(lo_elem));
    return r;
}
__device__ __forceinline__ void split2(float a, float b, uint32_t& h, uint32_t& l) {
    h = cvt_bf16x2(a, b);
    float ha = __uint_as_float(h << 16);
    float hb = __uint_as_float(h & 0xffff0000u);
    l = cvt_bf16x2(a - ha, b - hb);
}
__device__ __forceinline__ void cp16(uint32_t dst, const void* src) {
    asm volatile("cp.async.ca.shared.global [%0], [%1], 16;" :: "r"(dst), "l"(src));
}
__device__ __forceinline__ void ldsm4(uint32_t addr, uint32_t& r0, uint32_t& r1,
                                      uint32_t& r2, uint32_t& r3) {
    asm volatile("ldmatrix.sync.aligned.m8n8.x4.shared.b16 {%0,%1,%2,%3}, [%4];"
                 : "=r"(r0), "=r"(r1), "=r"(r2), "=r"(r3) : "r"(addr));
}
__device__ __forceinline__ void ldsm4t(uint32_t addr, uint32_t& r0, uint32_t& r1,
                                       uint32_t& r2, uint32_t& r3) {
    asm volatile("ldmatrix.sync.aligned.m8n8.x4.trans.shared.b16 {%0,%1,%2,%3}, [%4];"
                 : "=r"(r0), "=r"(r1), "=r"(r2), "=r"(r3) : "r"(addr));
}
__device__ __forceinline__ void mma16816(float* c, const uint32_t* a, const uint32_t* b) {
    asm volatile(
        "mma.sync.aligned.m16n8k16.row.col.f32.bf16.bf16.f32 "
        "{%0,%1,%2,%3}, {%4,%5,%6,%7}, {%8,%9}, {%0,%1,%2,%3};"
        : "+f"(c[0]), "+f"(c[1]), "+f"(c[2]), "+f"(c[3])
        : "r"(a[0]), "r"(a[1]), "r"(a[2]), "r"(a[3]), "r"(b[0]), "r"(b[1]));
}

// ---------------- pack kernels ----------------
__global__ void pack_wei(const float* __restrict__ We, const float* __restrict__ Wi,
                         int l0, int cnt) {
    size_t i = (size_t)blockIdx.x * blockDim.x + threadIdx.x;
    const size_t total = (size_t)cnt * DIM * 2 * DIM;
    if (i >= total) return;
    int l = l0 + (int)(i / ((size_t)DIM * 2 * DIM));
    size_t r = i % ((size_t)DIM * 2 * DIM);
    int k = (int)(r / (2 * DIM));
    int n = (int)(r % (2 * DIM));
    int mc = n >> 5, rr = n & 31;
    const float* src;
    int h;
    if (rr < 16) { src = We; h = rr; } else { src = Wi; h = rr - 16; }
    float v = src[(((size_t)l * NMC + mc) * DIM + k) * HW + h];
    __nv_bfloat16 hb = __float2bfloat16(v);
    size_t o = (size_t)l * DIM * 2 * DIM + r;
    g_w_h[OFF_WEI + o] = hb;
    g_w_l[OFF_WEI + o] = __float2bfloat16(v - __bfloat162float(hb));
}

__global__ void pack_split(const float* __restrict__ src, __nv_bfloat16* __restrict__ dh,
                           __nv_bfloat16* __restrict__ dl, size_t total) {
    size_t i = ((size_t)blockIdx.x * blockDim.x + threadIdx.x) * 4;
    if (i >= total) return;
    float4 v = *(const float4*)(src + i);
    uint32_t h0, l0, h1, l1;
    split2(v.x, v.y, h0, l0);
    split2(v.z, v.w, h1, l1);
    *(uint2*)(dh + i) = make_uint2(h0, h1);
    *(uint2*)(dl + i) = make_uint2(l0, l1);
}

__global__ void pack_bias_kernel(const float* __restrict__ be, const float* __restrict__ bi) {
    if (blockIdx.x == 0) {
        unsigned* p = &g_ctr[0][0];
        for (int j = threadIdx.x; j < NSLOT * 128; j += 256) p[j] = 0u;
    }
    int i = blockIdx.x * blockDim.x + threadIdx.x;
    if (i >= NLAY * 2 * DIM) return;
    int l = i / (2 * DIM);
    int n = i % (2 * DIM);
    int mc = n >> 5, rr = n & 31;
    g_bei[i] = (rr < 16) ? be[l * DIM + mc * HW + rr] : bi[l * DIM + mc * HW + (rr - 16)];
}

__global__ void bvo_kernel(const float* __restrict__ bv, const float* __restrict__ Wo,
                           const float* __restrict__ bo) {
    int l = blockIdx.y;
    int n = blockIdx.x * 256 + threadIdx.x;
    const float* w = Wo + (size_t)l * SQ + n;
    const float* b = bv + l * DIM;
    float s = bo[l * DIM + n];
    for (int k = 0; k < DIM; k++) s += b[k] * w[(size_t)k * DIM];
    g_bvo[l * DIM + n] = s;
}

__global__ void b3_kernel(const float* __restrict__ blat) {
    int l = blockIdx.y;
    int n = blockIdx.x * 256 + threadIdx.x;
    const float* w = g_wvo_f + (size_t)l * SQ + n;
    const float* b = blat + l * DIM;
    float s = g_bvo[l * DIM + n];
    for (int k = 0; k < DIM; k++) s += b[k] * w[(size_t)k * DIM];
    g_b3[l * DIM + n] = s;
}

// ---------------- GEMM core (bf16x3 HMMA, 2-stage cp.async) ----------------
// EPI 0: bias + split   1: fused minicolumn   2: fp32 out + split   3: fp32 += + split (skip if oHi null)
template <int EPI>
__device__ __forceinline__ void gemm_core(
    const __nv_bfloat16* __restrict__ Ah, const __nv_bfloat16* __restrict__ Al,
    const __nv_bfloat16* __restrict__ Wh, const __nv_bfloat16* __restrict__ Wl,
    const float* __restrict__ bias,
    __nv_bfloat16* __restrict__ oHi, __nv_bfloat16* __restrict__ oLo,
    float* __restrict__ oF, int N,
    const float* __restrict__ mcW, const float* __restrict__ mcB,
    int bx, int by, int waitSlot, int waitCount, int sigSlot) {
    extern __shared__ __nv_bfloat16 smem[];
    __nv_bfloat16* sAh = smem;
    __nv_bfloat16* sAl = sAh + NST * STG_ELEMS_A;
    __nv_bfloat16* sWh = sAl + NST * STG_ELEMS_A;
    __nv_bfloat16* sWl = sWh + NST * STG_ELEMS_W;
    const uint32_t sAh_u = (uint32_t)__cvta_generic_to_shared(sAh);
    const uint32_t sAl_u = (uint32_t)__cvta_generic_to_shared(sAl);
    const uint32_t sWh_u = (uint32_t)__cvta_generic_to_shared(sWh);
    const uint32_t sWl_u = (uint32_t)__cvta_generic_to_shared(sWl);

    const int tid = threadIdx.x;
    const int lane = tid & 31, wid = tid >> 5;
    const int wm = wid >> 2, wn = wid & 3;

    if (waitSlot >= 0) {
        if (tid == 0) {
            volatile unsigned* p = &g_ctr[waitSlot][by];
            while (*p < (unsigned)waitCount) __nanosleep(200);
        }
        __syncthreads();
        __threadfence();
    }

    const char* pAh = (const char*)Ah + (size_t)by * BM * (DIM * 2);
    const char* pAl = (const char*)Al + (size_t)by * BM * (DIM * 2);
    const char* pWh = (const char*)Wh + (size_t)bx * BN * 2;
    const char* pWl = (const char*)Wl + (size_t)bx * BN * 2;
    const size_t wrow_b = (size_t)N * 2;

    uint32_t sAb[2], sWb[2];
    size_t gA[2], gW[2];
#pragma unroll
    for (int i = 0; i < 2; i++) {
        int idx = i * 256 + tid;
        int ar = idx >> 2, ac = idx & 3;
        gA[i] = (size_t)ar * (DIM * 2) + (size_t)ac * 16;
        sAb[i] = (uint32_t)(ar * AST + ac * 8) * 2;
        int wr = idx >> 4, wc = idx & 15;
        gW[i] = (size_t)wr * wrow_b + (size_t)wc * 16;
        sWb[i] = (uint32_t)(wr * WST + wc * 8) * 2;
    }

    auto load_async = [&](int c) {
        const int buf = c & 1;
        const uint32_t offA = (uint32_t)(buf * STG_ELEMS_A * 2);
        const uint32_t offW = (uint32_t)(buf * STG_ELEMS_W * 2);
        const size_t cbA = (size_t)c * (BK * 2);
        const size_t cbW = (size_t)c * BK * wrow_b;
#pragma unroll
        for (int i = 0; i < 2; i++) {
            cp16(sAh_u + offA + sAb[i], pAh + gA[i] + cbA);
            cp16(sAl_u + offA + sAb[i], pAl + gA[i] + cbA);
            cp16(sWh_u + offW + sWb[i], pWh + gW[i] + cbW);
            cp16(sWl_u + offW + sWb[i], pWl + gW[i] + cbW);
        }
        asm volatile("cp.async.commit_group;" ::: "memory");
    };

    float acc[4][4][4];
#pragma unroll
    for (int mt = 0; mt < 4; mt++)
#pragma unroll
        for (int nt = 0; nt < 4; nt++)
#pragma unroll
            for (int q = 0; q < 4; q++) acc[mt][nt][q] = 0.f;

    load_async(0);

    const int lrow = lane & 15;
    const int lcol8 = (lane >> 4) * 8;

    for (int t = 0; t < NTCH; t++) {
        asm volatile("cp.async.wait_group 0;" ::: "memory");
        __syncthreads();
        if (t + 1 < NTCH) load_async(t + 1);

        const int buf = t & 1;
        const uint32_t bA = (uint32_t)(buf * STG_ELEMS_A * 2);
        const uint32_t bW = (uint32_t)(buf * STG_ELEMS_W * 2);

#pragma unroll
        for (int ks = 0; ks < 2; ks++) {
            uint32_t ah[4][4], al[4][4], bh[4][2], bl[4][2];
#pragma unroll
            for (int mt = 0; mt < 4; mt++) {
                uint32_t off = bA + (uint32_t)((wm * 64 + mt * 16 + lrow) * AST +
                                               ks * 16 + lcol8) * 2;
                ldsm4(sAh_u + off, ah[mt][0], ah[mt][1], ah[mt][2], ah[mt][3]);
                ldsm4(sAl_u + off, al[mt][0], al[mt][1], al[mt][2], al[mt][3]);
            }
#pragma unroll
            for (int np = 0; np < 2; np++) {
                uint32_t off = bW + (uint32_t)((ks * 16 + lrow) * WST +
                                               wn * 32 + np * 16 + lcol8) * 2;
                uint32_t r0, r1, r2, r3;
                ldsm4t(sWh_u + off, r0, r1, r2, r3);
                bh[np * 2][0] = r0; bh[np * 2][1] = r1;
                bh[np * 2 + 1][0] = r2; bh[np * 2 + 1][1] = r3;
                ldsm4t(sWl_u + off, r0, r1, r2, r3);
                bl[np * 2][0] = r0; bl[np * 2][1] = r1;
                bl[np * 2 + 1][0] = r2; bl[np * 2 + 1][1] = r3;
            }
#pragma unroll
            for (int mt = 0; mt < 4; mt++)
#pragma unroll
                for (int nt = 0; nt < 4; nt++) mma16816(acc[mt][nt], ah[mt], bh[nt]);
#pragma unroll
            for (int mt = 0; mt < 4; mt++)
#pragma unroll
                for (int nt = 0; nt < 4; nt++) mma16816(acc[mt][nt], ah[mt], bl[nt]);
#pragma unroll
            for (int mt = 0; mt < 4; mt++)
#pragma unroll
                for (int nt = 0; nt < 4; nt++) mma16816(acc[mt][nt], al[mt], bh[nt]);
        }
    }
    __syncthreads();

    const int g = lane >> 2;
    const int tg = lane & 3;

    if (EPI == 1) {
        float* tileF = (float*)smem;
#pragma unroll
        for (int mt = 0; mt < 4; mt++) {
            const int rl = wm * 64 + mt * 16 + g;
#pragma unroll
            for (int nt = 0; nt < 4; nt++) {
                const int cl = wn * 32 + nt * 8 + tg * 2;
                float2 bv = *(const float2*)(bias + bx * BN + cl);
                tileF[rl * TSTR + cl]           = fmaxf(acc[mt][nt][0] + bv.x, 0.f);
                tileF[rl * TSTR + cl + 1]       = fmaxf(acc[mt][nt][1] + bv.y, 0.f);
                tileF[(rl + 8) * TSTR + cl]     = fmaxf(acc[mt][nt][2] + bv.x, 0.f);
                tileF[(rl + 8) * TSTR + cl + 1] = fmaxf(acc[mt][nt][3] + bv.y, 0.f);
            }
        }
        float* sWlF = tileF + SWL_OFF;
        float* sblF = tileF + SBL_OFF;
#pragma unroll
        for (int i = 0; i < 4; i++) sWlF[i * 256 + tid] = mcW[(size_t)(bx * 4) * 256 + i * 256 + tid];
        if (tid < 64) sblF[tid] = mcB[bx * 64 + tid];
        __syncthreads();

#pragma unroll
        for (int it = 0; it < 2; it++) {
            int w = it * 256 + tid;
            int j = w & 3, row = w >> 2;
            const float* tr = tileF + row * TSTR + j * 32;
            float inh[16];
#pragma unroll
            for (int h = 0; h < 16; h++) inh[h] = tr[16 + h];
            float o[16];
#pragma unroll
            for (int k = 0; k < 16; k++) {
                float lat = sblF[j * 16 + k];
#pragma unroll
                for (int h = 0; h < 16; h++) lat += inh[h] * sWlF[j * 256 + h * 16 + k];
                o[k] = fmaxf(tr[k] - lat, 0.f);
            }
            uint32_t hu[8], lu[8];
#pragma unroll
            for (int p = 0; p < 8; p++) split2(o[2 * p], o[2 * p + 1], hu[p], lu[p]);
            size_t oo = (size_t)(by * 128 + row) * DIM + (bx * 4 + j) * 16;
            *(uint4*)(oHi + oo)     = make_uint4(hu[0], hu[1], hu[2], hu[3]);
            *(uint4*)(oHi + oo + 8) = make_uint4(hu[4], hu[5], hu[6], hu[7]);
            *(uint4*)(oLo + oo)     = make_uint4(lu[0], lu[1], lu[2], lu[3]);
            *(uint4*)(oLo + oo + 8) = make_uint4(lu[4], lu[5], lu[6], lu[7]);
        }
    } else {
        const bool do_split = (EPI != 3) || (oHi != nullptr);
#pragma unroll
        for (int mt = 0; mt < 4; mt++) {
            const int r0 = by * BM + wm * 64 + mt * 16 + g;
#pragma unroll
            for (int nt = 0; nt < 4; nt++) {
                const int col = bx * BN + wn * 32 + nt * 8 + tg * 2;
                float2 bv = bias ? *(const float2*)(bias + col) : make_float2(0.f, 0.f);
                float2 v0, v1;
                v0.x = acc[mt][nt][0] + bv.x;  v0.y = acc[mt][nt][1] + bv.y;
                v1.x = acc[mt][nt][2] + bv.x;  v1.y = acc[mt][nt][3] + bv.y;
                if (EPI >= 2) {
                    float* p0 = oF + (size_t)r0 * N + col;
                    float* p1 = oF + (size_t)(r0 + 8) * N + col;
                    if (EPI == 3) {
                        float2 o0 = *(const float2*)p0;
                        float2 o1 = *(const float2*)p1;
                        v0.x += o0.x; v0.y += o0.y; v1.x += o1.x; v1.y += o1.y;
                    }
                    *(float2*)p0 = v0;
                    *(float2*)p1 = v1;
                }
                if (do_split) {
                    uint32_t h0, l0, h1, l1;
                    split2(v0.x, v0.y, h0, l0);
                    split2(v1.x, v1.y, h1, l1);
                    *(uint32_t*)(oHi + (size_t)r0 * N + col)       = h0;
                    *(uint32_t*)(oLo + (size_t)r0 * N + col)       = l0;
                    *(uint32_t*)(oHi + (size_t)(r0 + 8) * N + col) = h1;
                    *(uint32_t*)(oLo + (size_t)(r0 + 8) * N + col) = l1;
                }
            }
        }
    }

    if (sigSlot >= 0) {
        __threadfence();
        __syncthreads();
        if (tid == 0) atomicAdd(&g_ctr[sigSlot][by], 1u);
    }
}

// ---------------- standalone GEMM wrappers ----------------
template <int EPI, bool BATCH6>
__global__ __launch_bounds__(256, 2)
void bgemm(const __nv_bfloat16* __restrict__ Ah, const __nv_bfloat16* __restrict__ Al,
           const __nv_bfloat16* __restrict__ Wh, const __nv_bfloat16* __restrict__ Wl,
           const float* __restrict__ bias,
           __nv_bfloat16* __restrict__ oHi, __nv_bfloat16* __restrict__ oLo,
           float* __restrict__ oF, int N,
           const float* __restrict__ mcW, const float* __restrict__ mcB) {
    if (BATCH6) {
        size_t ws = (size_t)(blockIdx.y >> 3) * SQ;
        Wh += ws; Wl += ws;
    }
    gemm_core<EPI>(Ah, Al, Wh, Wl, bias, oHi, oLo, oF, N, mcW, mcB,
                   blockIdx.x, blockIdx.y, -1, 0, -1);
}

// ---------------- mega kernel: W3(0..5) + wide(1..5) + fb(0..4), 21504 CTAs ----------------
__global__ __launch_bounds__(256, 2)
void mega_kernel(__nv_bfloat16* __restrict__ w_h, __nv_bfloat16* __restrict__ w_l,
                 __nv_bfloat16* __restrict__ actA_h, __nv_bfloat16* __restrict__ actA_l,
                 __nv_bfloat16* __restrict__ actB_h, __nv_bfloat16* __restrict__ actB_l,
                 __nv_bfloat16* __restrict__ mc_h, __nv_bfloat16* __restrict__ mc_l,
                 const float* __restrict__ b3, const float* __restrict__ bei,
                 const float* __restrict__ fbb, float* __restrict__ out,
                 const float* __restrict__ Wl_mc, const float* __restrict__ bl_mc) {
    const size_t BD = (size_t)BATCH * DIM;
    int bid = blockIdx.x;

    if (bid < 1024) {
        int bx = bid & 7, by = bid >> 3;
        gemm_core<2>(mc_h, mc_l, w_h + OFF_W3, w_l + OFF_W3, b3,
                     actA_h, actA_l, out, 1024, nullptr, nullptr,
                     bx, by, -1, 0, 0);
        return;
    }
    bid -= 1024;
    if (bid < 5 * 3072) {
        const int l = bid / 3072 + 1;
        int t = bid % 3072;
        if (t < 2048) {
            int bx = t & 15, by = t >> 4;
            gemm_core<1>(actA_h, actA_l,
                         w_h + OFF_WEI + (size_t)l * 2048 * 1024,
                         w_l + OFF_WEI + (size_t)l * 2048 * 1024,
                         bei + l * 2048, mc_h, mc_l, nullptr, 2048,
                         Wl_mc + (size_t)l * NMC * HW * HW, bl_mc + (size_t)l * NMC * HW,
                         bx, by, l - 1, 8, 5 + l);
        } else {
            t -= 2048;
            int bx = t & 7, by = t >> 3;
            gemm_core<2>(mc_h, mc_l,
                         w_h + OFF_W3 + (size_t)l * SQ, w_l + OFF_W3 + (size_t)l * SQ,
                         b3 + l * DIM, actA_h, actA_l, out + (size_t)l * BD, 1024,
                         nullptr, nullptr, bx, by, 5 + l, 16, l);
        }
        return;
    }
    bid -= 5 * 3072;
    {
        const int i = bid >> 10;
        const int t = bid & 1023;
        const int bx = t & 7, by = t >> 3;
        const int idx = 4 - i;
        const bool last = (i == 4);
        __nv_bfloat16 *fin_h, *fin_l, *fout_h, *fout_l;
        if ((i & 1) == 0) { fin_h = actA_h; fin_l = actA_l; fout_h = actB_h; fout_l = actB_l; }
        else              { fin_h = actB_h; fin_l = actB_l; fout_h = actA_h; fout_l = actA_l; }
        gemm_core<3>(fin_h, fin_l,
                     w_h + OFF_FB + (size_t)i * SQ, w_l + OFF_FB + (size_t)i * SQ,
                     fbb + i * DIM,
                     last ? nullptr : fout_h, last ? nullptr : fout_l,
                     out + (size_t)idx * BD, 1024, nullptr, nullptr,
                     bx, by, (i == 0) ? 5 : (11 + i - 1), 8, last ? -1 : (11 + i));
    }
}

// ---------------- driver ----------------
extern "C" void kernel_launch(void* const* d_in, const int* in_sizes, int n_in,
                              void* d_out, int out_size) {
    const float* x    = (const float*)d_in[0];
    const float* We   = (const float*)d_in[1];
    const float* be   = (const float*)d_in[2];
    const float* Wi   = (const float*)d_in[3];
    const float* bi   = (const float*)d_in[4];
    const float* Wl   = (const float*)d_in[5];
    const float* bl   = (const float*)d_in[6];
    const float* Wlat = (const float*)d_in[7];
    const float* blat = (const float*)d_in[8];
    const float* Wv   = (const float*)d_in[9];
    const float* bv   = (const float*)d_in[10];
    const float* Wo   = (const float*)d_in[11];
    const float* bo   = (const float*)d_in[12];
    const float* fbW  = (const float*)d_in[13];
    const float* fbb  = (const float*)d_in[14];
    float* out = (float*)d_out;

    const size_t BD = (size_t)BATCH * DIM;

    __nv_bfloat16 *w_h, *w_l, *actA_h, *actA_l, *actB_h, *actB_l, *mc_h, *mc_l;
    float *bei_p, *b3_p, *wvo_f;
    cudaGetSymbolAddress((void**)&w_h, g_w_h);
    cudaGetSymbolAddress((void**)&w_l, g_w_l);
    cudaGetSymbolAddress((void**)&actA_h, g_actA_h);
    cudaGetSymbolAddress((void**)&actA_l, g_actA_l);
    cudaGetSymbolAddress((void**)&actB_h, g_actB_h);
    cudaGetSymbolAddress((void**)&actB_l, g_actB_l);
    cudaGetSymbolAddress((void**)&mc_h, g_mc_h);
    cudaGetSymbolAddress((void**)&mc_l, g_mc_l);
    cudaGetSymbolAddress((void**)&bei_p, g_bei);
    cudaGetSymbolAddress((void**)&b3_p, g_b3);
    cudaGetSymbolAddress((void**)&wvo_f, g_wvo_f);

    cudaFuncSetAttribute((const void*)bgemm<0, true>,  cudaFuncAttributeMaxDynamicSharedMemorySize, SMEM_BYTES);
    cudaFuncSetAttribute((const void*)bgemm<2, true>,  cudaFuncAttributeMaxDynamicSharedMemorySize, SMEM_BYTES);
    cudaFuncSetAttribute((const void*)bgemm<1, false>, cudaFuncAttributeMaxDynamicSharedMemorySize, SMEM_BYTES);
    cudaFuncSetAttribute((const void*)mega_kernel,     cudaFuncAttributeMaxDynamicSharedMemorySize, SMEM_BYTES);

    cudaStream_t s2;
    cudaStreamCreateWithFlags(&s2, cudaStreamNonBlocking);
    cudaEvent_t evFork, evJoin;
    cudaEventCreateWithFlags(&evFork, cudaEventDisableTiming);
    cudaEventCreateWithFlags(&evJoin, cudaEventDisableTiming);

    // ---- minimal main-stream prefix: only what wide(0) needs ----
    const size_t tw1 = (size_t)DIM * 2 * DIM;
    pack_wei<<<(unsigned)((tw1 + 255) / 256), 256>>>(We, Wi, 0, 1);
    pack_split<<<(unsigned)(BD / 4 / 256), 256>>>(x, actA_h, actA_l, BD);
    pack_bias_kernel<<<(NLAY * 2 * DIM + 255) / 256, 256>>>(be, bi);  // also zeroes counters

    // ---- fork: everything else on s2, overlapped with wide(0) ----
    cudaEventRecord(evFork, 0);
    cudaStreamWaitEvent(s2, evFork, 0);
    {
        pack_wei<<<(unsigned)((5 * tw1 + 255) / 256), 256, 0, s2>>>(We, Wi, 1, 5);
        pack_split<<<(unsigned)(6 * SQ / 4 / 256), 256, 0, s2>>>(Wlat, w_h + OFF_LAT, w_l + OFF_LAT, 6 * SQ);
        pack_split<<<(unsigned)(6 * SQ / 4 / 256), 256, 0, s2>>>(Wv,   w_h + OFF_V,   w_l + OFF_V,   6 * SQ);
        pack_split<<<(unsigned)(6 * SQ / 4 / 256), 256, 0, s2>>>(Wo,   w_h + OFF_O,   w_l + OFF_O,   6 * SQ);
        pack_split<<<(unsigned)(5 * SQ / 4 / 256), 256, 0, s2>>>(fbW,  w_h + OFF_FB,  w_l + OFF_FB,  5 * SQ);
        bvo_kernel<<<dim3(4, NLAY), 256, 0, s2>>>(bv, Wo, bo);
        bgemm<2, true><<<dim3(8, 48), 256, SMEM_BYTES, s2>>>(
            w_h + OFF_V, w_l + OFF_V, w_h + OFF_O, w_l + OFF_O, nullptr,
            w_h + OFF_VO, w_l + OFF_VO, wvo_f, 1024, nullptr, nullptr);
        bgemm<0, true><<<dim3(8, 48), 256, SMEM_BYTES, s2>>>(
            w_h + OFF_LAT, w_l + OFF_LAT, w_h + OFF_VO, w_l + OFF_VO, nullptr,
            w_h + OFF_W3, w_l + OFF_W3, nullptr, 1024, nullptr, nullptr);
        b3_kernel<<<dim3(4, NLAY), 256, 0, s2>>>(blat);
    }
    cudaEventRecord(evJoin, s2);

    dim3 blk(256);
    dim3 grid_wide(2 * DIM / BN, BATCH / BM);

    // wide(0): standalone launch (overlaps s2 precompute)
    bgemm<1, false><<<grid_wide, blk, SMEM_BYTES>>>(
        actA_h, actA_l, w_h + OFF_WEI, w_l + OFF_WEI, bei_p,
        mc_h, mc_l, nullptr, 2048, Wl, bl);

    // join, then the entire rest of the network in one flagged mega-launch
    cudaStreamWaitEvent(0, evJoin, 0);
    mega_kernel<<<21504, blk, SMEM_BYTES>>>(
        w_h, w_l, actA_h, actA_l, actB_h, actB_l, mc_h, mc_l,
        b3_p, bei_p, fbb, out, Wl, bl);
}